// round 5
// baseline (speedup 1.0000x reference)
#include <cuda_runtime.h>
#include <cuda_bf16.h>
#include <math.h>
#include <stdint.h>

// ---------------- problem constants ----------------
#define Bdim 8
#define Kst 4
#define Lseq 1024
#define Ddim 512
#define Hn 8
#define HDdim 64
#define BLn 8192
#define Tn 32768
#define D3 1536

#define OUT_FUSED 0
#define OUT_AP    4194304
#define OUT_WM    8388608
#define OUT_MF    12582912
#define OUT_AM    16777216
#define OUT_NSW   16809984

// ---------------- device scratch ----------------
__device__ __nv_bfloat16 g_Xs[(size_t)Tn * 1536];
__device__ float         g_QKV[(size_t)Tn * 1536];
__device__ __nv_bfloat16 g_AOs[(size_t)BLn * 1536];
__device__ __nv_bfloat16 g_Gs[(size_t)BLn * 4608];
__device__ __nv_bfloat16 g_H1s[(size_t)BLn * 1536];
__device__ float         g_GATE[(size_t)BLn * Ddim];
__device__ __nv_bfloat16 g_Ws1[1536 * 1536];
__device__ __nv_bfloat16 g_Wso[512 * 1536];
__device__ __nv_bfloat16 g_Wsg1[512 * 4608];
__device__ __nv_bfloat16 g_Wsg2[512 * 1536];
__device__ float g_swr[BLn * Kst];
__device__ float g_nsw[Bdim * Kst];
__device__ float g_lognsw[Bdim * Kst];
__device__ int   g_mask_u8;
__device__ int   g_cnt;
__device__ int   g_rowmap[Tn];

// ---------------- helpers ----------------
__device__ __forceinline__ uint32_t smem_u32(const void* p) {
    uint32_t a;
    asm("{ .reg .u64 t; cvta.to.shared.u64 t, %1; cvt.u32.u64 %0, t; }" : "=r"(a) : "l"(p));
    return a;
}
__device__ __forceinline__ void split2(float v, __nv_bfloat16& hi, __nv_bfloat16& lo) {
    hi = __float2bfloat16(v);
    lo = __float2bfloat16(v - __bfloat162float(hi));
}
__device__ __forceinline__ void ldsm_x4(uint32_t& r0, uint32_t& r1, uint32_t& r2,
                                        uint32_t& r3, uint32_t addr) {
    asm volatile("ldmatrix.sync.aligned.m8n8.x4.shared.b16 {%0,%1,%2,%3}, [%4];"
                 : "=r"(r0), "=r"(r1), "=r"(r2), "=r"(r3) : "r"(addr));
}
__device__ __forceinline__ void mma16816(float* c, const uint32_t* a, const uint32_t* b) {
    asm volatile(
        "mma.sync.aligned.m16n8k16.row.col.f32.bf16.bf16.f32 "
        "{%0,%1,%2,%3}, {%4,%5,%6,%7}, {%8,%9}, {%0,%1,%2,%3};"
        : "+f"(c[0]), "+f"(c[1]), "+f"(c[2]), "+f"(c[3])
        : "r"(a[0]), "r"(a[1]), "r"(a[2]), "r"(a[3]), "r"(b[0]), "r"(b[1]));
}
__device__ __forceinline__ uint32_t swz(uint32_t off) {
    return off ^ ((off >> 3) & 0x70);
}
__device__ __forceinline__ void cp_async16(uint32_t dst, const void* src) {
    asm volatile("cp.async.cg.shared.global [%0], [%1], 16;" :: "r"(dst), "l"(src));
}

// ---------------- mask dtype detection (+ counter reset) ----------------
__global__ void detect_mask_kernel(const void* rm) {
    const int* p = (const int*)rm;
    int bad = 0;
    for (int i = threadIdx.x; i < 8192; i += 256) {
        int v = p[i];
        if (v != 0 && v != 1) bad = 1;
    }
    bad = __syncthreads_or(bad);
    if (threadIdx.x == 0) {
        g_mask_u8 = bad;
        g_cnt = 0;
    }
}
__device__ __forceinline__ bool mask_at(const void* p, int idx, int u8) {
    return u8 ? (((const unsigned char*)p)[idx] != 0) : (((const int*)p)[idx] != 0);
}

// ---------------- nsw ----------------
__global__ void nsw_kernel(const float* __restrict__ sw, const void* __restrict__ pm,
                           float* __restrict__ out_nsw) {
    int b = threadIdx.x;
    if (b >= Bdim) return;
    int u8 = g_mask_u8;
    float w[Kst], pres[Kst];
    float denom = 0.f, psum = 0.f;
#pragma unroll
    for (int k = 0; k < Kst; k++) {
        pres[k] = mask_at(pm, b * Kst + k, u8) ? 1.f : 0.f;
        w[k] = sw[b * Kst + k] * pres[k];
        denom += w[k];
        psum += pres[k];
    }
#pragma unroll
    for (int k = 0; k < Kst; k++) {
        float nswk = (denom > 1e-8f) ? (w[k] / fmaxf(denom, 1e-8f))
                                     : (pres[k] / fmaxf(psum, 1.f));
        g_nsw[b * Kst + k] = nswk;
        g_lognsw[b * Kst + k] = logf(fmaxf(nswk, 1e-8f));
        out_nsw[b * Kst + k] = nswk;
    }
}

// ---------------- build split-x (compacted), weighted_mean, max_feat, swr ----------------
__global__ void __launch_bounds__(512) build_x_kernel(
    const float* __restrict__ sr, const void* __restrict__ rm,
    const void* __restrict__ pm, const int* __restrict__ roles,
    const float* __restrict__ remb, float* __restrict__ dout) {
    int bl = blockIdx.x;
    int b = bl >> 10;
    int l = bl & 1023;
    int d = threadIdx.x;
    int u8 = g_mask_u8;
    __shared__ int slots[Kst];

    bool vd[Kst];
    float swr[Kst];
    float ssum = 0.f;
#pragma unroll
    for (int k = 0; k < Kst; k++) {
        bool v = mask_at(rm, (b * Kst + k) * Lseq + l, u8) && mask_at(pm, b * Kst + k, u8);
        vd[k] = v;
        swr[k] = v ? g_nsw[b * Kst + k] : 0.f;
        ssum += swr[k];
    }
    if (d == 0) {
        int nv = 0;
#pragma unroll
        for (int k = 0; k < Kst; k++) nv += vd[k] ? 1 : 0;
        int base = nv ? atomicAdd(&g_cnt, nv) : 0;
#pragma unroll
        for (int k = 0; k < Kst; k++) {
            if (vd[k]) {
                slots[k] = base;
                g_rowmap[base] = bl * Kst + k;
                base++;
            } else slots[k] = -1;
        }
    }
    __syncthreads();
    float inv = 1.f / fmaxf(ssum, 1e-8f);

    float wm = 0.f, mx = -1e9f;
    bool any = false;
#pragma unroll
    for (int k = 0; k < Kst; k++) {
        swr[k] *= inv;
        float xv = 0.f;
        if (vd[k]) {
            int role = max(roles[b * Kst + k], 0);
            xv = sr[(((size_t)(b * Kst + k)) * Lseq + l) * Ddim + d] + remb[role * Ddim + d];
            any = true;
            mx = fmaxf(mx, xv);
            __nv_bfloat16 hi, lo;
            split2(xv, hi, lo);
            size_t row = (size_t)slots[k] * 1536;
            g_Xs[row + d] = hi;
            g_Xs[row + 512 + d] = lo;
            g_Xs[row + 1024 + d] = hi;
        }
        wm += swr[k] * xv;
    }
    dout[OUT_WM + (size_t)bl * Ddim + d] = wm;
    dout[OUT_MF + (size_t)bl * Ddim + d] = any ? mx : 0.f;
    if (d < Kst) g_swr[bl * Kst + d] = swr[d];
}

// ---------------- pad compacted rows to multiple of 128 with zeros ----------------
__global__ void pad_x_kernel() {
    int Mv = g_cnt;
    int padded = (Mv + 127) & ~127;
    int r = Mv + blockIdx.x;
    if (r >= padded) return;
    uint32_t* row = (uint32_t*)(g_Xs + (size_t)r * 1536);
    for (int i = threadIdx.x; i < 768; i += 256) row[i] = 0;
}

// ---------------- weight splitter: out[N x 3K] = [hi | hi | lo] ----------------
__global__ void split_w_kernel(const float* __restrict__ W, __nv_bfloat16* __restrict__ out,
                               int Nn, int Kk) {
    int idx = blockIdx.x * 256 + threadIdx.x;
    if (idx >= Nn * Kk) return;
    int n = idx / Kk, k = idx - n * Kk;
    float v = W[idx];
    __nv_bfloat16 hi, lo;
    split2(v, hi, lo);
    __nv_bfloat16* row = out + (size_t)n * 3 * Kk;
    row[k] = hi;
    row[Kk + k] = hi;
    row[2 * Kk + k] = lo;
}

// ---------------- HMMA bf16 GEMM, cp.async 3-stage pipeline ----------------
// C[M,N] = A[M,K'] @ B[N,K']^T. CTA tile 128 x (4*WN); 8 warps 2x4; warp 64 x WN.
// WN = 32 or 64. smem stage = 16KB (A) + 4*WN*128B (B).
#define STAGES 3

template <int EPI, bool COMPACT, int WN>
__global__ void __launch_bounds__(256) gemm_mma(
    const __nv_bfloat16* __restrict__ A, const __nv_bfloat16* __restrict__ B,
    const float* __restrict__ bias, float* __restrict__ Cf,
    __nv_bfloat16* __restrict__ Cb, int K, int ldc) {
    constexpr int NT = 4 * WN;             // CTA N tile
    constexpr int NTW = WN / 8;            // n-frags per warp
    constexpr int BSTG = NT * 128;         // B bytes per stage
    constexpr int STG = 16384 + BSTG;      // stage bytes
    int Mv = 0;
    if (COMPACT) {
        Mv = g_cnt;
        int padded = (Mv + 127) & ~127;
        if ((int)(blockIdx.y * 128) >= padded) return;
    }
    extern __shared__ __align__(1024) char smem[];
    uint32_t sA0 = smem_u32(smem);
    int tid = threadIdx.x;
    int wid = tid >> 5, lane = tid & 31;
    const int wm = wid >> 2, wn = wid & 3;

    const size_t bm = (size_t)blockIdx.y * 128;
    const int bn = blockIdx.x * NT;
    const int seg = tid & 7;
    const int r0 = tid >> 3;

    const __nv_bfloat16* Ab = A + (bm + r0) * (size_t)K + seg * 8;
    const __nv_bfloat16* Bb = B + (size_t)(bn + r0) * K + seg * 8;
    const uint32_t swbase = swz(r0 * 128 + seg * 16);

    auto copy_stage = [&](int c, int buf) {
        int kc = c << 6;
        uint32_t pa = sA0 + buf * STG + swbase;
#pragma unroll
        for (int i = 0; i < 4; i++)
            cp_async16(pa + i * 32 * 128, Ab + (size_t)(i * 32) * K + kc);
#pragma unroll
        for (int i = 0; i < NT / 32; i++)
            cp_async16(pa + 16384 + i * 32 * 128, Bb + (size_t)(i * 32) * K + kc);
        asm volatile("cp.async.commit_group;" ::: "memory");
    };

    float acc[4][NTW][4];
#pragma unroll
    for (int i = 0; i < 4; i++)
#pragma unroll
        for (int j = 0; j < NTW; j++)
#pragma unroll
            for (int q = 0; q < 4; q++) acc[i][j][q] = 0.f;

    const uint32_t aRow = wm * 64 + (lane & 15);
    const uint32_t aColB = (lane >> 4) << 4;
    const uint32_t bRow = wn * WN + (lane & 7) + ((lane >> 4) << 3);
    const uint32_t bColB = ((lane >> 3) & 1) << 4;

    const int NC = K >> 6;
#pragma unroll
    for (int s = 0; s < STAGES - 1; s++)
        if (s < NC) copy_stage(s, s);

    for (int c = 0; c < NC; c++) {
        asm volatile("cp.async.wait_group %0;" :: "n"(STAGES - 2));
        __syncthreads();
        if (c + STAGES - 1 < NC) copy_stage(c + STAGES - 1, (c + STAGES - 1) % STAGES);

        uint32_t Abuf = sA0 + (c % STAGES) * STG;
        uint32_t Bbuf = Abuf + 16384;
#pragma unroll
        for (int ks = 0; ks < 4; ks++) {
            uint32_t a[4][4], b[NTW][2];
#pragma unroll
            for (int mt = 0; mt < 4; mt++) {
                uint32_t off = (aRow + mt * 16) * 128 + ks * 32 + aColB;
                ldsm_x4(a[mt][0], a[mt][1], a[mt][2], a[mt][3], Abuf + swz(off));
            }
#pragma unroll
            for (int p = 0; p < NTW / 2; p++) {
                uint32_t off = (bRow + p * 16) * 128 + ks * 32 + bColB;
                ldsm_x4(b[2 * p][0], b[2 * p][1], b[2 * p + 1][0], b[2 * p + 1][1],
                        Bbuf + swz(off));
            }
#pragma unroll
            for (int mt = 0; mt < 4; mt++)
#pragma unroll
                for (int nt = 0; nt < NTW; nt++)
                    mma16816(acc[mt][nt], a[mt], b[nt]);
        }
    }

    // epilogue
    const int g = lane >> 2, t = lane & 3;
#pragma unroll
    for (int mt = 0; mt < 4; mt++) {
#pragma unroll
        for (int half = 0; half < 2; half++) {
            size_t grow = bm + wm * 64 + mt * 16 + g + half * 8;
            size_t orow = grow;
            if (COMPACT) {
                if ((int)grow >= Mv) continue;
                orow = (size_t)g_rowmap[grow];
            }
#pragma unroll
            for (int nt = 0; nt < NTW; nt++) {
                int col = bn + wn * WN + nt * 8 + t * 2;
                float v0 = acc[mt][nt][half * 2 + 0];
                float v1 = acc[mt][nt][half * 2 + 1];
                if (EPI == 0) {
                    float2 o = make_float2(v0, v1);
                    *(float2*)(Cf + orow * (size_t)ldc + col) = o;
                } else if (EPI == 1) {
                    v0 += bias[col];
                    v1 += bias[col + 1];
                    v0 = 0.5f * v0 * (1.f + erff(v0 * 0.70710678118654752f));
                    v1 = 0.5f * v1 * (1.f + erff(v1 * 0.70710678118654752f));
                    __nv_bfloat16 h0, l0, h1, l1;
                    split2(v0, h0, l0);
                    split2(v1, h1, l1);
                    size_t o = orow * 1536 + col;
                    *(__nv_bfloat162*)(Cb + o)        = __nv_bfloat162(h0, h1);
                    *(__nv_bfloat162*)(Cb + o + 512)  = __nv_bfloat162(l0, l1);
                    *(__nv_bfloat162*)(Cb + o + 1024) = __nv_bfloat162(h0, h1);
                } else {
                    v0 += bias[col];
                    v1 += bias[col + 1];
                    float2 o;
                    o.x = 1.f / (1.f + expf(-v0));
                    o.y = 1.f / (1.f + expf(-v1));
                    *(float2*)(Cf + orow * 512 + col) = o;
                }
            }
        }
    }
}

// ---------------- attention: 4x4 per (b,l,h); pooled split output + attn_mean ----------------
__global__ void __launch_bounds__(256) attn_kernel(
    const void* __restrict__ rm, const void* __restrict__ pm,
    float* __restrict__ dout) {
    int bl = blockIdx.x;
    int b = bl >> 10;
    int l = bl & 1023;
    int warp = threadIdx.x >> 5;
    int lane = threadIdx.x & 31;
    __shared__ float am[Kst];
    if (threadIdx.x < Kst) am[threadIdx.x] = 0.f;
    __syncthreads();
    int u8 = g_mask_u8;

    float2 q[Kst], kk[Kst], vv[Kst];
    float ln_w[Kst], swr[Kst];
    bool vd[Kst];
    int col = warp * HDdim + lane * 2;
#pragma unroll
    for (int s = 0; s < Kst; s++) {
        vd[s] = mask_at(rm, (b * Kst + s) * Lseq + l, u8) && mask_at(pm, b * Kst + s, u8);
        if (vd[s]) {
            size_t rbase = (size_t)(bl * Kst + s) * 1536 + col;
            q[s]  = *(const float2*)(g_QKV + rbase);
            kk[s] = *(const float2*)(g_QKV + rbase + 512);
            vv[s] = *(const float2*)(g_QKV + rbase + 1024);
        } else {
            q[s] = kk[s] = vv[s] = make_float2(0.f, 0.f);
        }
        ln_w[s] = g_lognsw[b * Kst + s];
        swr[s]  = g_swr[bl * Kst + s];
    }

    float dot[Kst][Kst];
#pragma unroll
    for (int i = 0; i < Kst; i++) {
#pragma unroll
        for (int j = 0; j < Kst; j++) {
            float p = q[i].x * kk[j].x + q[i].y * kk[j].y;
#pragma unroll
            for (int o = 16; o; o >>= 1) p += __shfl_xor_sync(0xffffffffu, p, o);
            dot[i][j] = p;
        }
    }

    float a[Kst][Kst];
#pragma unroll
    for (int i = 0; i < Kst; i++) {
        float lm[Kst] = {0.f, 0.f, 0.f, 0.f};
        float m = -3.4e38f;
#pragma unroll
        for (int j = 0; j < Kst; j++) {
            if (vd[j]) {
                lm[j] = dot[i][j] * 0.125f + ln_w[j];
                m = fmaxf(m, lm[j]);
            }
        }
        float ssum = 0.f;
#pragma unroll
        for (int j = 0; j < Kst; j++) {
            float e = vd[j] ? expf(lm[j] - m) : 0.f;
            a[i][j] = e;
            ssum += e;
        }
        float invs = (ssum > 0.f) ? (1.f / ssum) : 0.f;
#pragma unroll
        for (int j = 0; j < Kst; j++) a[i][j] *= invs;
    }

    float px = 0.f, py = 0.f;
#pragma unroll
    for (int i = 0; i < Kst; i++) {
        float ox = 0.f, oy = 0.f;
#pragma unroll
        for (int j = 0; j < Kst; j++) {
            ox += a[i][j] * vv[j].x;
            oy += a[i][j] * vv[j].y;
        }
        px += swr[i] * ox;
        py += swr[i] * oy;
    }
    __nv_bfloat16 hx, lx, hy, ly;
    split2(px, hx, lx);
    split2(py, hy, ly);
    size_t ob = (size_t)bl * 1536 + col;
    *(__nv_bfloat162*)(g_AOs + ob)        = __nv_bfloat162(hx, hy);
    *(__nv_bfloat162*)(g_AOs + ob + 512)  = __nv_bfloat162(lx, ly);
    *(__nv_bfloat162*)(g_AOs + ob + 1024) = __nv_bfloat162(hx, hy);

    if (lane == 0) {
#pragma unroll
        for (int j = 0; j < Kst; j++)
            atomicAdd(&am[j], a[0][j] + a[1][j] + a[2][j] + a[3][j]);
    }
    __syncthreads();
    if (threadIdx.x < Kst)
        dout[OUT_AM + (size_t)bl * Kst + threadIdx.x] = am[threadIdx.x] * (1.f / 32.f);
}

// ---------------- block reduction ----------------
__device__ __forceinline__ float block_sum(float v, float* red) {
    int lane = threadIdx.x & 31, w = threadIdx.x >> 5;
#pragma unroll
    for (int o = 16; o; o >>= 1) v += __shfl_xor_sync(0xffffffffu, v, o);
    __syncthreads();
    if (lane == 0) red[w] = v;
    __syncthreads();
    if (threadIdx.x == 0) {
        float t = 0.f;
        int nw = (blockDim.x + 31) >> 5;
        for (int i = 0; i < nw; i++) t += red[i];
        red[8] = t;
    }
    __syncthreads();
    return red[8];
}

// ---------------- layernorm of gate_in (1536) -> split bf16 ----------------
__global__ void __launch_bounds__(256) ln_gatein_kernel(
    const float* __restrict__ dro, const float* __restrict__ g,
    const float* __restrict__ bb) {
    int bl = blockIdx.x;
    __shared__ float buf[D3];
    __shared__ float red[9];
    float s = 0.f;
    for (int c = threadIdx.x; c < D3; c += 256) {
        float v;
        if (c < Ddim)          v = dro[OUT_AP + (size_t)bl * Ddim + c];
        else if (c < 2 * Ddim) v = dro[OUT_WM + (size_t)bl * Ddim + (c - Ddim)];
        else                   v = dro[OUT_MF + (size_t)bl * Ddim + (c - 2 * Ddim)];
        buf[c] = v;
        s += v;
    }
    s = block_sum(s, red);
    float mu = s * (1.f / D3);
    float sq = 0.f;
    for (int c = threadIdx.x; c < D3; c += 256) {
        float d = buf[c] - mu;
        sq += d * d;
    }
    sq = block_sum(sq, red);
    float rs = rsqrtf(sq * (1.f / D3) + 1e-5f);
    for (int c = threadIdx.x; c < D3; c += 256) {
        float y = (buf[c] - mu) * rs * g[c] + bb[c];
        __nv_bfloat16 hi, lo;
        split2(y, hi, lo);
        size_t row = (size_t)bl * 4608;
        g_Gs[row + c] = hi;
        g_Gs[row + 1536 + c] = lo;
        g_Gs[row + 3072 + c] = hi;
    }
}

// ---------------- final fuse + layernorm(512) ----------------
__global__ void __launch_bounds__(256) ln_final_kernel(
    float* __restrict__ dout, const float* __restrict__ ng,
    const float* __restrict__ nb) {
    int bl = blockIdx.x;
    __shared__ float buf[Ddim];
    __shared__ float red[9];
    float s = 0.f;
    for (int d = threadIdx.x; d < Ddim; d += 256) {
        float gate = g_GATE[(size_t)bl * Ddim + d];
        float ap = dout[OUT_AP + (size_t)bl * Ddim + d];
        float wm = dout[OUT_WM + (size_t)bl * Ddim + d];
        float mf = dout[OUT_MF + (size_t)bl * Ddim + d];
        float y = gate * 0.5f * (ap + wm) + (1.f - gate) * mf + wm;
        buf[d] = y;
        s += y;
    }
    s = block_sum(s, red);
    float mu = s * (1.f / Ddim);
    float sq = 0.f;
    for (int d = threadIdx.x; d < Ddim; d += 256) {
        float dd = buf[d] - mu;
        sq += dd * dd;
    }
    sq = block_sum(sq, red);
    float rs = rsqrtf(sq * (1.f / Ddim) + 1e-5f);
    for (int d = threadIdx.x; d < Ddim; d += 256)
        dout[OUT_FUSED + (size_t)bl * Ddim + d] = (buf[d] - mu) * rs * ng[d] + nb[d];
}

// ---------------- launch ----------------
extern "C" void kernel_launch(void* const* d_in, const int* in_sizes, int n_in,
                              void* d_out, int out_size) {
    const float* sr    = (const float*)d_in[0];
    const void*  rmask = d_in[1];
    const float* sw    = (const float*)d_in[2];
    const int*   roles = (const int*)d_in[3];
    const void*  pmask = d_in[4];
    const float* remb  = (const float*)d_in[5];
    const float* Wq    = (const float*)d_in[6];
    const float* Wk    = (const float*)d_in[7];
    const float* Wv    = (const float*)d_in[8];
    const float* Wo    = (const float*)d_in[9];
    const float* ln1g  = (const float*)d_in[10];
    const float* ln1b  = (const float*)d_in[11];
    const float* Wg1   = (const float*)d_in[12];
    const float* bg1   = (const float*)d_in[13];
    const float* Wg2   = (const float*)d_in[14];
    const float* bg2   = (const float*)d_in[15];
    const float* ng    = (const float*)d_in[16];
    const float* nb    = (const float*)d_in[17];
    float* dout = (float*)d_out;

    __nv_bfloat16 *pXs, *pAOs, *pGs, *pH1s, *pWs1, *pWso, *pWsg1, *pWsg2;
    float *pQKV, *pGATE;
    cudaGetSymbolAddress((void**)&pXs, g_Xs);
    cudaGetSymbolAddress((void**)&pQKV, g_QKV);
    cudaGetSymbolAddress((void**)&pAOs, g_AOs);
    cudaGetSymbolAddress((void**)&pGs, g_Gs);
    cudaGetSymbolAddress((void**)&pH1s, g_H1s);
    cudaGetSymbolAddress((void**)&pGATE, g_GATE);
    cudaGetSymbolAddress((void**)&pWs1, g_Ws1);
    cudaGetSymbolAddress((void**)&pWso, g_Wso);
    cudaGetSymbolAddress((void**)&pWsg1, g_Wsg1);
    cudaGetSymbolAddress((void**)&pWsg2, g_Wsg2);

    const int SM32 = STAGES * (16384 + 128 * 128);   // 98304
    const int SM64 = STAGES * (16384 + 256 * 128);   // 147456
    cudaFuncSetAttribute(gemm_mma<0, true, 64>,  cudaFuncAttributeMaxDynamicSharedMemorySize, SM64);
    cudaFuncSetAttribute(gemm_mma<0, false, 32>, cudaFuncAttributeMaxDynamicSharedMemorySize, SM32);
    cudaFuncSetAttribute(gemm_mma<1, false, 64>, cudaFuncAttributeMaxDynamicSharedMemorySize, SM64);
    cudaFuncSetAttribute(gemm_mma<2, false, 32>, cudaFuncAttributeMaxDynamicSharedMemorySize, SM32);

    detect_mask_kernel<<<1, 256>>>(rmask);
    nsw_kernel<<<1, 32>>>(sw, pmask, dout + OUT_NSW);
    build_x_kernel<<<BLn, 512>>>(sr, rmask, pmask, roles, remb, dout);
    pad_x_kernel<<<128, 256>>>();

    split_w_kernel<<<(512 * 512 + 255) / 256, 256>>>(Wq, pWs1, 512, 512);
    split_w_kernel<<<(512 * 512 + 255) / 256, 256>>>(Wk, pWs1 + (size_t)512 * 1536, 512, 512);
    split_w_kernel<<<(512 * 512 + 255) / 256, 256>>>(Wv, pWs1 + (size_t)1024 * 1536, 512, 512);
    split_w_kernel<<<(512 * 512 + 255) / 256, 256>>>(Wo, pWso, 512, 512);
    split_w_kernel<<<(512 * 1536 + 255) / 256, 256>>>(Wg1, pWsg1, 512, 1536);
    split_w_kernel<<<(512 * 512 + 255) / 256, 256>>>(Wg2, pWsg2, 512, 512);

    // fused QKV on compacted rows: [Mv x 1536] = Xs @ Ws1^T, scatter rows (WN=64 tile)
    {
        dim3 grid(1536 / 256, Tn / 128);
        gemm_mma<0, true, 64><<<grid, 256, SM64>>>(pXs, pWs1, nullptr, pQKV, nullptr, 1536, 1536);
    }

    attn_kernel<<<BLn, 256>>>(rmask, pmask, dout);

    // attn_pooled = AOs @ Wso^T  [8192 x 512]
    {
        dim3 grid(512 / 128, BLn / 128);
        gemm_mma<0, false, 32><<<grid, 256, SM32>>>(pAOs, pWso, nullptr, dout + OUT_AP, nullptr, 1536, 512);
    }

    ln_gatein_kernel<<<BLn, 256>>>(dout, ln1g, ln1b);

    // h = gelu(Gs @ Wsg1^T + bg1) -> split bf16 (WN=64 tile)
    {
        dim3 grid(512 / 256, BLn / 128);
        gemm_mma<1, false, 64><<<grid, 256, SM64>>>(pGs, pWsg1, bg1, nullptr, pH1s, 4608, 0);
    }
    // gate = sigmoid(H1s @ Wsg2^T + bg2)
    {
        dim3 grid(512 / 128, BLn / 128);
        gemm_mma<2, false, 32><<<grid, 256, SM32>>>(pH1s, pWsg2, bg2, pGATE, nullptr, 1536, 0);
    }

    ln_final_kernel<<<BLn, 256>>>(dout, ng, nb);
}

// round 6
// speedup vs baseline: 1.0582x; 1.0582x over previous
#include <cuda_runtime.h>
#include <cuda_bf16.h>
#include <math.h>
#include <stdint.h>

// ---------------- problem constants ----------------
#define Bdim 8
#define Kst 4
#define Lseq 1024
#define Ddim 512
#define Hn 8
#define HDdim 64
#define BLn 8192
#define Tn 32768
#define D3 1536

#define OUT_FUSED 0
#define OUT_AP    4194304
#define OUT_WM    8388608
#define OUT_MF    12582912
#define OUT_AM    16777216
#define OUT_NSW   16809984

// ---------------- device scratch ----------------
// A-side physical layout: [hi(0:S) | lo(S:2S)]; logical K'=3S (third segment re-reads hi).
// B-side physical layout: [hi | hi | lo] (3S).
__device__ __nv_bfloat16 g_Xs[(size_t)Tn * 1024];
__device__ float         g_QKV[(size_t)Tn * 1536];
__device__ __nv_bfloat16 g_AOs[(size_t)BLn * 1024];
__device__ __nv_bfloat16 g_Gs[(size_t)BLn * 3072];
__device__ __nv_bfloat16 g_H1s[(size_t)BLn * 1024];
__device__ float         g_GATE[(size_t)BLn * Ddim];
__device__ __nv_bfloat16 g_Ws1[1536 * 1536];
__device__ __nv_bfloat16 g_Wso[512 * 1536];
__device__ __nv_bfloat16 g_Wsg1[512 * 4608];
__device__ __nv_bfloat16 g_Wsg2[512 * 1536];
__device__ float g_swr[BLn * Kst];
__device__ float g_nsw[Bdim * Kst];
__device__ float g_lognsw[Bdim * Kst];
__device__ int   g_mask_u8;
__device__ int   g_cnt;
__device__ int   g_rowmap[Tn];

// ---------------- helpers ----------------
__device__ __forceinline__ uint32_t smem_u32(const void* p) {
    uint32_t a;
    asm("{ .reg .u64 t; cvta.to.shared.u64 t, %1; cvt.u32.u64 %0, t; }" : "=r"(a) : "l"(p));
    return a;
}
__device__ __forceinline__ void split2(float v, __nv_bfloat16& hi, __nv_bfloat16& lo) {
    hi = __float2bfloat16(v);
    lo = __float2bfloat16(v - __bfloat162float(hi));
}
__device__ __forceinline__ void ldsm_x4(uint32_t& r0, uint32_t& r1, uint32_t& r2,
                                        uint32_t& r3, uint32_t addr) {
    asm volatile("ldmatrix.sync.aligned.m8n8.x4.shared.b16 {%0,%1,%2,%3}, [%4];"
                 : "=r"(r0), "=r"(r1), "=r"(r2), "=r"(r3) : "r"(addr));
}
__device__ __forceinline__ void mma16816(float* c, const uint32_t* a, const uint32_t* b) {
    asm volatile(
        "mma.sync.aligned.m16n8k16.row.col.f32.bf16.bf16.f32 "
        "{%0,%1,%2,%3}, {%4,%5,%6,%7}, {%8,%9}, {%0,%1,%2,%3};"
        : "+f"(c[0]), "+f"(c[1]), "+f"(c[2]), "+f"(c[3])
        : "r"(a[0]), "r"(a[1]), "r"(a[2]), "r"(a[3]), "r"(b[0]), "r"(b[1]));
}
__device__ __forceinline__ uint32_t swz(uint32_t off) {
    return off ^ ((off >> 3) & 0x70);
}
__device__ __forceinline__ void cp_async16(uint32_t dst, const void* src) {
    asm volatile("cp.async.cg.shared.global [%0], [%1], 16;" :: "r"(dst), "l"(src));
}

// ---------------- mask dtype detection (+ counter reset) ----------------
__global__ void detect_mask_kernel(const void* rm) {
    const int* p = (const int*)rm;
    int bad = 0;
    for (int i = threadIdx.x; i < 8192; i += 256) {
        int v = p[i];
        if (v != 0 && v != 1) bad = 1;
    }
    bad = __syncthreads_or(bad);
    if (threadIdx.x == 0) {
        g_mask_u8 = bad;
        g_cnt = 0;
    }
}
__device__ __forceinline__ bool mask_at(const void* p, int idx, int u8) {
    return u8 ? (((const unsigned char*)p)[idx] != 0) : (((const int*)p)[idx] != 0);
}

// ---------------- nsw ----------------
__global__ void nsw_kernel(const float* __restrict__ sw, const void* __restrict__ pm,
                           float* __restrict__ out_nsw) {
    int b = threadIdx.x;
    if (b >= Bdim) return;
    int u8 = g_mask_u8;
    float w[Kst], pres[Kst];
    float denom = 0.f, psum = 0.f;
#pragma unroll
    for (int k = 0; k < Kst; k++) {
        pres[k] = mask_at(pm, b * Kst + k, u8) ? 1.f : 0.f;
        w[k] = sw[b * Kst + k] * pres[k];
        denom += w[k];
        psum += pres[k];
    }
#pragma unroll
    for (int k = 0; k < Kst; k++) {
        float nswk = (denom > 1e-8f) ? (w[k] / fmaxf(denom, 1e-8f))
                                     : (pres[k] / fmaxf(psum, 1.f));
        g_nsw[b * Kst + k] = nswk;
        g_lognsw[b * Kst + k] = logf(fmaxf(nswk, 1e-8f));
        out_nsw[b * Kst + k] = nswk;
    }
}

// ---------------- build split-x (compacted, [hi|lo]), weighted_mean, max_feat, swr ----------------
__global__ void __launch_bounds__(512) build_x_kernel(
    const float* __restrict__ sr, const void* __restrict__ rm,
    const void* __restrict__ pm, const int* __restrict__ roles,
    const float* __restrict__ remb, float* __restrict__ dout) {
    int bl = blockIdx.x;
    int b = bl >> 10;
    int l = bl & 1023;
    int d = threadIdx.x;
    int u8 = g_mask_u8;
    __shared__ int slots[Kst];

    bool vd[Kst];
    float swr[Kst];
    float ssum = 0.f;
#pragma unroll
    for (int k = 0; k < Kst; k++) {
        bool v = mask_at(rm, (b * Kst + k) * Lseq + l, u8) && mask_at(pm, b * Kst + k, u8);
        vd[k] = v;
        swr[k] = v ? g_nsw[b * Kst + k] : 0.f;
        ssum += swr[k];
    }
    if (d == 0) {
        int nv = 0;
#pragma unroll
        for (int k = 0; k < Kst; k++) nv += vd[k] ? 1 : 0;
        int base = nv ? atomicAdd(&g_cnt, nv) : 0;
#pragma unroll
        for (int k = 0; k < Kst; k++) {
            if (vd[k]) {
                slots[k] = base;
                g_rowmap[base] = bl * Kst + k;
                base++;
            } else slots[k] = -1;
        }
    }
    __syncthreads();
    float inv = 1.f / fmaxf(ssum, 1e-8f);

    float wm = 0.f, mx = -1e9f;
    bool any = false;
#pragma unroll
    for (int k = 0; k < Kst; k++) {
        swr[k] *= inv;
        float xv = 0.f;
        if (vd[k]) {
            int role = max(roles[b * Kst + k], 0);
            xv = sr[(((size_t)(b * Kst + k)) * Lseq + l) * Ddim + d] + remb[role * Ddim + d];
            any = true;
            mx = fmaxf(mx, xv);
            __nv_bfloat16 hi, lo;
            split2(xv, hi, lo);
            size_t row = (size_t)slots[k] * 1024;
            g_Xs[row + d] = hi;
            g_Xs[row + 512 + d] = lo;
        }
        wm += swr[k] * xv;
    }
    dout[OUT_WM + (size_t)bl * Ddim + d] = wm;
    dout[OUT_MF + (size_t)bl * Ddim + d] = any ? mx : 0.f;
    if (d < Kst) g_swr[bl * Kst + d] = swr[d];
}

// ---------------- pad compacted rows to multiple of 128 with zeros ----------------
__global__ void pad_x_kernel() {
    int Mv = g_cnt;
    int padded = (Mv + 127) & ~127;
    int r = Mv + blockIdx.x;
    if (r >= padded) return;
    uint32_t* row = (uint32_t*)(g_Xs + (size_t)r * 1024);
    for (int i = threadIdx.x; i < 512; i += 256) row[i] = 0;
}

// ---------------- fused weight splitter: B-side [hi | hi | lo] ----------------
// regions (256-thread blocks over elements): Wq,Wk,Wv,Wo,Wg2 (512x512 each), Wg1 (512x1536)
__global__ void split_w_all(const float* __restrict__ Wq, const float* __restrict__ Wk,
                            const float* __restrict__ Wv, const float* __restrict__ Wo,
                            const float* __restrict__ Wg2, const float* __restrict__ Wg1,
                            __nv_bfloat16* __restrict__ oWs1, __nv_bfloat16* __restrict__ oWso,
                            __nv_bfloat16* __restrict__ oWsg2, __nv_bfloat16* __restrict__ oWsg1) {
    int idx = blockIdx.x * 256 + threadIdx.x;
    const float* W;
    __nv_bfloat16* out;
    int Kk, e;
    if (idx < 262144)        { W = Wq;  out = oWs1;                         Kk = 512;  e = idx; }
    else if (idx < 524288)   { W = Wk;  out = oWs1 + (size_t)512 * 1536;    Kk = 512;  e = idx - 262144; }
    else if (idx < 786432)   { W = Wv;  out = oWs1 + (size_t)1024 * 1536;   Kk = 512;  e = idx - 524288; }
    else if (idx < 1048576)  { W = Wo;  out = oWso;                         Kk = 512;  e = idx - 786432; }
    else if (idx < 1310720)  { W = Wg2; out = oWsg2;                        Kk = 512;  e = idx - 1048576; }
    else                     { W = Wg1; out = oWsg1;                        Kk = 1536; e = idx - 1310720; }
    int n = e / Kk, k = e - n * Kk;
    float v = W[e];
    __nv_bfloat16 hi, lo;
    split2(v, hi, lo);
    __nv_bfloat16* row = out + (size_t)n * 3 * Kk;
    row[k] = hi;
    row[Kk + k] = hi;
    row[2 * Kk + k] = lo;
}

// ---------------- HMMA bf16 GEMM, cp.async 4-stage pipeline ----------------
// C[M,N] = A[M,K'] @ B[N,K']^T. CTA tile 128x128; 8 warps 2x4; warp 64x32.
// A physical lda = 2K'/3 ([hi|lo]); logical chunk kc>=lda reads phys kc-lda (hi again).
// B physical rows = K' ([hi|hi|lo]).
#define STAGES 4
#define GSM_BYTES (STAGES * 32768)

template <int EPI, bool COMPACT>
__global__ void __launch_bounds__(256) gemm_mma(
    const __nv_bfloat16* __restrict__ A, const __nv_bfloat16* __restrict__ B,
    const float* __restrict__ bias, float* __restrict__ Cf,
    __nv_bfloat16* __restrict__ Cb, int K, int lda, int ldc) {
    int Mv = 0;
    if (COMPACT) {
        Mv = g_cnt;
        int padded = (Mv + 127) & ~127;
        if ((int)(blockIdx.y * 128) >= padded) return;
    }
    extern __shared__ __align__(1024) char smem[];
    uint32_t sA0 = smem_u32(smem);
    int tid = threadIdx.x;
    int wid = tid >> 5, lane = tid & 31;
    const int wm = wid >> 2, wn = wid & 3;

    const size_t bm = (size_t)blockIdx.y * 128;
    const int bn = blockIdx.x * 128;
    const int seg = tid & 7;
    const int r0 = tid >> 3;

    const __nv_bfloat16* Ab = A + (bm + r0) * (size_t)lda + seg * 8;
    const __nv_bfloat16* Bb = B + (size_t)(bn + r0) * K + seg * 8;
    const uint32_t swbase = swz(r0 * 128 + seg * 16);

    auto copy_stage = [&](int c, int buf) {
        int kc = c << 6;
        int akc = (kc >= lda) ? kc - lda : kc;   // third logical segment re-reads hi
        uint32_t pa = sA0 + buf * 32768 + swbase;
#pragma unroll
        for (int i = 0; i < 4; i++) {
            cp_async16(pa + i * 32 * 128, Ab + (size_t)(i * 32) * lda + akc);
            cp_async16(pa + 16384 + i * 32 * 128, Bb + (size_t)(i * 32) * K + kc);
        }
        asm volatile("cp.async.commit_group;" ::: "memory");
    };

    float acc[4][4][4];
#pragma unroll
    for (int i = 0; i < 4; i++)
#pragma unroll
        for (int j = 0; j < 4; j++)
#pragma unroll
            for (int q = 0; q < 4; q++) acc[i][j][q] = 0.f;

    const uint32_t aRow = wm * 64 + (lane & 15);
    const uint32_t aColB = (lane >> 4) << 4;
    const uint32_t bRow = wn * 32 + (lane & 7) + ((lane >> 4) << 3);
    const uint32_t bColB = ((lane >> 3) & 1) << 4;

    const int NC = K >> 6;
#pragma unroll
    for (int s = 0; s < STAGES - 1; s++)
        if (s < NC) copy_stage(s, s);

    for (int c = 0; c < NC; c++) {
        asm volatile("cp.async.wait_group %0;" :: "n"(STAGES - 2));
        __syncthreads();
        if (c + STAGES - 1 < NC) copy_stage(c + STAGES - 1, (c + STAGES - 1) % STAGES);

        uint32_t Abuf = sA0 + (c % STAGES) * 32768;
        uint32_t Bbuf = Abuf + 16384;
#pragma unroll
        for (int ks = 0; ks < 4; ks++) {
            uint32_t a[4][4], b[4][2];
#pragma unroll
            for (int mt = 0; mt < 4; mt++) {
                uint32_t off = (aRow + mt * 16) * 128 + ks * 32 + aColB;
                ldsm_x4(a[mt][0], a[mt][1], a[mt][2], a[mt][3], Abuf + swz(off));
            }
#pragma unroll
            for (int p = 0; p < 2; p++) {
                uint32_t off = (bRow + p * 16) * 128 + ks * 32 + bColB;
                ldsm_x4(b[2 * p][0], b[2 * p][1], b[2 * p + 1][0], b[2 * p + 1][1],
                        Bbuf + swz(off));
            }
#pragma unroll
            for (int mt = 0; mt < 4; mt++)
#pragma unroll
                for (int nt = 0; nt < 4; nt++)
                    mma16816(acc[mt][nt], a[mt], b[nt]);
        }
    }

    // epilogue
    const int g = lane >> 2, t = lane & 3;
#pragma unroll
    for (int mt = 0; mt < 4; mt++) {
#pragma unroll
        for (int half = 0; half < 2; half++) {
            size_t grow = bm + wm * 64 + mt * 16 + g + half * 8;
            size_t orow = grow;
            if (COMPACT) {
                if ((int)grow >= Mv) continue;
                orow = (size_t)g_rowmap[grow];
            }
#pragma unroll
            for (int nt = 0; nt < 4; nt++) {
                int col = bn + wn * 32 + nt * 8 + t * 2;
                float v0 = acc[mt][nt][half * 2 + 0];
                float v1 = acc[mt][nt][half * 2 + 1];
                if (EPI == 0) {
                    float2 o = make_float2(v0, v1);
                    *(float2*)(Cf + orow * (size_t)ldc + col) = o;
                } else if (EPI == 1) {
                    v0 += bias[col];
                    v1 += bias[col + 1];
                    v0 = 0.5f * v0 * (1.f + erff(v0 * 0.70710678118654752f));
                    v1 = 0.5f * v1 * (1.f + erff(v1 * 0.70710678118654752f));
                    __nv_bfloat16 h0, l0, h1, l1;
                    split2(v0, h0, l0);
                    split2(v1, h1, l1);
                    size_t o = orow * 1024 + col;
                    *(__nv_bfloat162*)(Cb + o)       = __nv_bfloat162(h0, h1);
                    *(__nv_bfloat162*)(Cb + o + 512) = __nv_bfloat162(l0, l1);
                } else {
                    v0 += bias[col];
                    v1 += bias[col + 1];
                    float2 o;
                    o.x = 1.f / (1.f + expf(-v0));
                    o.y = 1.f / (1.f + expf(-v1));
                    *(float2*)(Cf + orow * 512 + col) = o;
                }
            }
        }
    }
}

// ---------------- attention: 4x4 per (b,l,h); pooled split output + attn_mean ----------------
__global__ void __launch_bounds__(256) attn_kernel(
    const void* __restrict__ rm, const void* __restrict__ pm,
    float* __restrict__ dout) {
    int bl = blockIdx.x;
    int b = bl >> 10;
    int l = bl & 1023;
    int warp = threadIdx.x >> 5;
    int lane = threadIdx.x & 31;
    __shared__ float am[Kst];
    if (threadIdx.x < Kst) am[threadIdx.x] = 0.f;
    __syncthreads();
    int u8 = g_mask_u8;

    float2 q[Kst], kk[Kst], vv[Kst];
    float ln_w[Kst], swr[Kst];
    bool vd[Kst];
    int col = warp * HDdim + lane * 2;
#pragma unroll
    for (int s = 0; s < Kst; s++) {
        vd[s] = mask_at(rm, (b * Kst + s) * Lseq + l, u8) && mask_at(pm, b * Kst + s, u8);
        if (vd[s]) {
            size_t rbase = (size_t)(bl * Kst + s) * 1536 + col;
            q[s]  = *(const float2*)(g_QKV + rbase);
            kk[s] = *(const float2*)(g_QKV + rbase + 512);
            vv[s] = *(const float2*)(g_QKV + rbase + 1024);
        } else {
            q[s] = kk[s] = vv[s] = make_float2(0.f, 0.f);
        }
        ln_w[s] = g_lognsw[b * Kst + s];
        swr[s]  = g_swr[bl * Kst + s];
    }

    float dot[Kst][Kst];
#pragma unroll
    for (int i = 0; i < Kst; i++) {
#pragma unroll
        for (int j = 0; j < Kst; j++) {
            float p = q[i].x * kk[j].x + q[i].y * kk[j].y;
#pragma unroll
            for (int o = 16; o; o >>= 1) p += __shfl_xor_sync(0xffffffffu, p, o);
            dot[i][j] = p;
        }
    }

    float a[Kst][Kst];
#pragma unroll
    for (int i = 0; i < Kst; i++) {
        float lm[Kst] = {0.f, 0.f, 0.f, 0.f};
        float m = -3.4e38f;
#pragma unroll
        for (int j = 0; j < Kst; j++) {
            if (vd[j]) {
                lm[j] = dot[i][j] * 0.125f + ln_w[j];
                m = fmaxf(m, lm[j]);
            }
        }
        float ssum = 0.f;
#pragma unroll
        for (int j = 0; j < Kst; j++) {
            float e = vd[j] ? expf(lm[j] - m) : 0.f;
            a[i][j] = e;
            ssum += e;
        }
        float invs = (ssum > 0.f) ? (1.f / ssum) : 0.f;
#pragma unroll
        for (int j = 0; j < Kst; j++) a[i][j] *= invs;
    }

    float px = 0.f, py = 0.f;
#pragma unroll
    for (int i = 0; i < Kst; i++) {
        float ox = 0.f, oy = 0.f;
#pragma unroll
        for (int j = 0; j < Kst; j++) {
            ox += a[i][j] * vv[j].x;
            oy += a[i][j] * vv[j].y;
        }
        px += swr[i] * ox;
        py += swr[i] * oy;
    }
    __nv_bfloat16 hx, lx, hy, ly;
    split2(px, hx, lx);
    split2(py, hy, ly);
    size_t ob = (size_t)bl * 1024 + col;
    *(__nv_bfloat162*)(g_AOs + ob)       = __nv_bfloat162(hx, hy);
    *(__nv_bfloat162*)(g_AOs + ob + 512) = __nv_bfloat162(lx, ly);

    if (lane == 0) {
#pragma unroll
        for (int j = 0; j < Kst; j++)
            atomicAdd(&am[j], a[0][j] + a[1][j] + a[2][j] + a[3][j]);
    }
    __syncthreads();
    if (threadIdx.x < Kst)
        dout[OUT_AM + (size_t)bl * Kst + threadIdx.x] = am[threadIdx.x] * (1.f / 32.f);
}

// ---------------- block reduction ----------------
__device__ __forceinline__ float block_sum(float v, float* red) {
    int lane = threadIdx.x & 31, w = threadIdx.x >> 5;
#pragma unroll
    for (int o = 16; o; o >>= 1) v += __shfl_xor_sync(0xffffffffu, v, o);
    __syncthreads();
    if (lane == 0) red[w] = v;
    __syncthreads();
    if (threadIdx.x == 0) {
        float t = 0.f;
        int nw = (blockDim.x + 31) >> 5;
        for (int i = 0; i < nw; i++) t += red[i];
        red[8] = t;
    }
    __syncthreads();
    return red[8];
}

// ---------------- layernorm of gate_in (1536) -> split bf16 [hi|lo] ----------------
__global__ void __launch_bounds__(256) ln_gatein_kernel(
    const float* __restrict__ dro, const float* __restrict__ g,
    const float* __restrict__ bb) {
    int bl = blockIdx.x;
    __shared__ float buf[D3];
    __shared__ float red[9];
    float s = 0.f;
    for (int c = threadIdx.x; c < D3; c += 256) {
        float v;
        if (c < Ddim)          v = dro[OUT_AP + (size_t)bl * Ddim + c];
        else if (c < 2 * Ddim) v = dro[OUT_WM + (size_t)bl * Ddim + (c - Ddim)];
        else                   v = dro[OUT_MF + (size_t)bl * Ddim + (c - 2 * Ddim)];
        buf[c] = v;
        s += v;
    }
    s = block_sum(s, red);
    float mu = s * (1.f / D3);
    float sq = 0.f;
    for (int c = threadIdx.x; c < D3; c += 256) {
        float d = buf[c] - mu;
        sq += d * d;
    }
    sq = block_sum(sq, red);
    float rs = rsqrtf(sq * (1.f / D3) + 1e-5f);
    for (int c = threadIdx.x; c < D3; c += 256) {
        float y = (buf[c] - mu) * rs * g[c] + bb[c];
        __nv_bfloat16 hi, lo;
        split2(y, hi, lo);
        size_t row = (size_t)bl * 3072;
        g_Gs[row + c] = hi;
        g_Gs[row + 1536 + c] = lo;
    }
}

// ---------------- final fuse + layernorm(512) ----------------
__global__ void __launch_bounds__(256) ln_final_kernel(
    float* __restrict__ dout, const float* __restrict__ ng,
    const float* __restrict__ nb) {
    int bl = blockIdx.x;
    __shared__ float buf[Ddim];
    __shared__ float red[9];
    float s = 0.f;
    for (int d = threadIdx.x; d < Ddim; d += 256) {
        float gate = g_GATE[(size_t)bl * Ddim + d];
        float ap = dout[OUT_AP + (size_t)bl * Ddim + d];
        float wm = dout[OUT_WM + (size_t)bl * Ddim + d];
        float mf = dout[OUT_MF + (size_t)bl * Ddim + d];
        float y = gate * 0.5f * (ap + wm) + (1.f - gate) * mf + wm;
        buf[d] = y;
        s += y;
    }
    s = block_sum(s, red);
    float mu = s * (1.f / Ddim);
    float sq = 0.f;
    for (int d = threadIdx.x; d < Ddim; d += 256) {
        float dd = buf[d] - mu;
        sq += dd * dd;
    }
    sq = block_sum(sq, red);
    float rs = rsqrtf(sq * (1.f / Ddim) + 1e-5f);
    for (int d = threadIdx.x; d < Ddim; d += 256)
        dout[OUT_FUSED + (size_t)bl * Ddim + d] = (buf[d] - mu) * rs * ng[d] + nb[d];
}

// ---------------- launch ----------------
extern "C" void kernel_launch(void* const* d_in, const int* in_sizes, int n_in,
                              void* d_out, int out_size) {
    const float* sr    = (const float*)d_in[0];
    const void*  rmask = d_in[1];
    const float* sw    = (const float*)d_in[2];
    const int*   roles = (const int*)d_in[3];
    const void*  pmask = d_in[4];
    const float* remb  = (const float*)d_in[5];
    const float* Wq    = (const float*)d_in[6];
    const float* Wk    = (const float*)d_in[7];
    const float* Wv    = (const float*)d_in[8];
    const float* Wo    = (const float*)d_in[9];
    const float* ln1g  = (const float*)d_in[10];
    const float* ln1b  = (const float*)d_in[11];
    const float* Wg1   = (const float*)d_in[12];
    const float* bg1   = (const float*)d_in[13];
    const float* Wg2   = (const float*)d_in[14];
    const float* bg2   = (const float*)d_in[15];
    const float* ng    = (const float*)d_in[16];
    const float* nb    = (const float*)d_in[17];
    float* dout = (float*)d_out;

    __nv_bfloat16 *pXs, *pAOs, *pGs, *pH1s, *pWs1, *pWso, *pWsg1, *pWsg2;
    float *pQKV, *pGATE;
    cudaGetSymbolAddress((void**)&pXs, g_Xs);
    cudaGetSymbolAddress((void**)&pQKV, g_QKV);
    cudaGetSymbolAddress((void**)&pAOs, g_AOs);
    cudaGetSymbolAddress((void**)&pGs, g_Gs);
    cudaGetSymbolAddress((void**)&pH1s, g_H1s);
    cudaGetSymbolAddress((void**)&pGATE, g_GATE);
    cudaGetSymbolAddress((void**)&pWs1, g_Ws1);
    cudaGetSymbolAddress((void**)&pWso, g_Wso);
    cudaGetSymbolAddress((void**)&pWsg1, g_Wsg1);
    cudaGetSymbolAddress((void**)&pWsg2, g_Wsg2);

    cudaFuncSetAttribute(gemm_mma<0, true>,  cudaFuncAttributeMaxDynamicSharedMemorySize, GSM_BYTES);
    cudaFuncSetAttribute(gemm_mma<0, false>, cudaFuncAttributeMaxDynamicSharedMemorySize, GSM_BYTES);
    cudaFuncSetAttribute(gemm_mma<1, false>, cudaFuncAttributeMaxDynamicSharedMemorySize, GSM_BYTES);
    cudaFuncSetAttribute(gemm_mma<2, false>, cudaFuncAttributeMaxDynamicSharedMemorySize, GSM_BYTES);

    detect_mask_kernel<<<1, 256>>>(rmask);
    nsw_kernel<<<1, 32>>>(sw, pmask, dout + OUT_NSW);
    build_x_kernel<<<BLn, 512>>>(sr, rmask, pmask, roles, remb, dout);
    pad_x_kernel<<<128, 256>>>();

    split_w_all<<<8192, 256>>>(Wq, Wk, Wv, Wo, Wg2, Wg1, pWs1, pWso, pWsg2, pWsg1);

    // fused QKV on compacted rows: [Mv x 1536] = Xs([hi|lo], lda=1024) @ Ws1^T
    {
        dim3 grid(1536 / 128, Tn / 128);
        gemm_mma<0, true><<<grid, 256, GSM_BYTES>>>(pXs, pWs1, nullptr, pQKV, nullptr, 1536, 1024, 1536);
    }

    attn_kernel<<<BLn, 256>>>(rmask, pmask, dout);

    // attn_pooled = AOs @ Wso^T  [8192 x 512]
    {
        dim3 grid(512 / 128, BLn / 128);
        gemm_mma<0, false><<<grid, 256, GSM_BYTES>>>(pAOs, pWso, nullptr, dout + OUT_AP, nullptr, 1536, 1024, 512);
    }

    ln_gatein_kernel<<<BLn, 256>>>(dout, ln1g, ln1b);

    // h = gelu(Gs @ Wsg1^T + bg1) -> split bf16 [hi|lo]
    {
        dim3 grid(512 / 128, BLn / 128);
        gemm_mma<1, false><<<grid, 256, GSM_BYTES>>>(pGs, pWsg1, bg1, nullptr, pH1s, 4608, 3072, 0);
    }
    // gate = sigmoid(H1s @ Wsg2^T + bg2)
    {
        dim3 grid(512 / 128, BLn / 128);
        gemm_mma<2, false><<<grid, 256, GSM_BYTES>>>(pH1s, pWsg2, bg2, pGATE, nullptr, 1536, 1024, 0);
    }

    ln_final_kernel<<<BLn, 256>>>(dout, ng, nb);
}

// round 7
// speedup vs baseline: 1.1213x; 1.0597x over previous
#include <cuda_runtime.h>
#include <cuda_bf16.h>
#include <math.h>
#include <stdint.h>

// ---------------- problem constants ----------------
#define Bdim 8
#define Kst 4
#define Lseq 1024
#define Ddim 512
#define Hn 8
#define HDdim 64
#define BLn 8192
#define Tn 32768
#define D3 1536

#define OUT_FUSED 0
#define OUT_AP    4194304
#define OUT_WM    8388608
#define OUT_MF    12582912
#define OUT_AM    16777216
#define OUT_NSW   16809984

// ---------------- device scratch ----------------
// A-side physical layout: [hi(0:S) | lo(S:2S)]; logical K'=3S (third segment re-reads hi).
// B-side physical layout: [hi | hi | lo] (3S).
__device__ __nv_bfloat16 g_Xs[(size_t)Tn * 1024];
__device__ float         g_QKV[(size_t)Tn * 1536];
__device__ __nv_bfloat16 g_AOs[(size_t)BLn * 1024];
__device__ __nv_bfloat16 g_Gs[(size_t)BLn * 3072];
__device__ __nv_bfloat16 g_H1s[(size_t)BLn * 1024];
__device__ float         g_GATE[(size_t)BLn * Ddim];
__device__ __nv_bfloat16 g_Ws1[1536 * 1536];
__device__ __nv_bfloat16 g_Wso[512 * 1536];
__device__ __nv_bfloat16 g_Wsg1[512 * 4608];
__device__ __nv_bfloat16 g_Wsg2[512 * 1536];
__device__ float g_swr[BLn * Kst];
__device__ float g_nsw[Bdim * Kst];
__device__ float g_lognsw[Bdim * Kst];
__device__ int   g_mask_u8;
__device__ int   g_cnt;
__device__ int   g_rowmap[Tn];

// ---------------- helpers ----------------
__device__ __forceinline__ uint32_t smem_u32(const void* p) {
    uint32_t a;
    asm("{ .reg .u64 t; cvta.to.shared.u64 t, %1; cvt.u32.u64 %0, t; }" : "=r"(a) : "l"(p));
    return a;
}
__device__ __forceinline__ void split2(float v, __nv_bfloat16& hi, __nv_bfloat16& lo) {
    hi = __float2bfloat16(v);
    lo = __float2bfloat16(v - __bfloat162float(hi));
}
__device__ __forceinline__ void ldsm_x4(uint32_t& r0, uint32_t& r1, uint32_t& r2,
                                        uint32_t& r3, uint32_t addr) {
    asm volatile("ldmatrix.sync.aligned.m8n8.x4.shared.b16 {%0,%1,%2,%3}, [%4];"
                 : "=r"(r0), "=r"(r1), "=r"(r2), "=r"(r3) : "r"(addr));
}
__device__ __forceinline__ void mma16816(float* c, const uint32_t* a, const uint32_t* b) {
    asm volatile(
        "mma.sync.aligned.m16n8k16.row.col.f32.bf16.bf16.f32 "
        "{%0,%1,%2,%3}, {%4,%5,%6,%7}, {%8,%9}, {%0,%1,%2,%3};"
        : "+f"(c[0]), "+f"(c[1]), "+f"(c[2]), "+f"(c[3])
        : "r"(a[0]), "r"(a[1]), "r"(a[2]), "r"(a[3]), "r"(b[0]), "r"(b[1]));
}
__device__ __forceinline__ uint32_t swz(uint32_t off) {
    return off ^ ((off >> 3) & 0x70);
}
__device__ __forceinline__ void cp_async16(uint32_t dst, const void* src) {
    asm volatile("cp.async.cg.shared.global [%0], [%1], 16;" :: "r"(dst), "l"(src));
}

// ---------------- mask dtype detection (+ counter reset) ----------------
__global__ void detect_mask_kernel(const void* rm) {
    const int* p = (const int*)rm;
    int bad = 0;
    for (int i = threadIdx.x; i < 8192; i += 256) {
        int v = p[i];
        if (v != 0 && v != 1) bad = 1;
    }
    bad = __syncthreads_or(bad);
    if (threadIdx.x == 0) {
        g_mask_u8 = bad;
        g_cnt = 0;
    }
}
__device__ __forceinline__ bool mask_at(const void* p, int idx, int u8) {
    return u8 ? (((const unsigned char*)p)[idx] != 0) : (((const int*)p)[idx] != 0);
}

// ---------------- nsw ----------------
__global__ void nsw_kernel(const float* __restrict__ sw, const void* __restrict__ pm,
                           float* __restrict__ out_nsw) {
    int b = threadIdx.x;
    if (b >= Bdim) return;
    int u8 = g_mask_u8;
    float w[Kst], pres[Kst];
    float denom = 0.f, psum = 0.f;
#pragma unroll
    for (int k = 0; k < Kst; k++) {
        pres[k] = mask_at(pm, b * Kst + k, u8) ? 1.f : 0.f;
        w[k] = sw[b * Kst + k] * pres[k];
        denom += w[k];
        psum += pres[k];
    }
#pragma unroll
    for (int k = 0; k < Kst; k++) {
        float nswk = (denom > 1e-8f) ? (w[k] / fmaxf(denom, 1e-8f))
                                     : (pres[k] / fmaxf(psum, 1.f));
        g_nsw[b * Kst + k] = nswk;
        g_lognsw[b * Kst + k] = logf(fmaxf(nswk, 1e-8f));
        out_nsw[b * Kst + k] = nswk;
    }
}

// ---------------- build split-x (compacted, [hi|lo]), weighted_mean, max_feat, swr ----------------
__global__ void __launch_bounds__(512) build_x_kernel(
    const float* __restrict__ sr, const void* __restrict__ rm,
    const void* __restrict__ pm, const int* __restrict__ roles,
    const float* __restrict__ remb, float* __restrict__ dout) {
    int bl = blockIdx.x;
    int b = bl >> 10;
    int l = bl & 1023;
    int d = threadIdx.x;
    int u8 = g_mask_u8;
    __shared__ int slots[Kst];

    bool vd[Kst];
    float swr[Kst];
    float ssum = 0.f;
#pragma unroll
    for (int k = 0; k < Kst; k++) {
        bool v = mask_at(rm, (b * Kst + k) * Lseq + l, u8) && mask_at(pm, b * Kst + k, u8);
        vd[k] = v;
        swr[k] = v ? g_nsw[b * Kst + k] : 0.f;
        ssum += swr[k];
    }
    if (d == 0) {
        int nv = 0;
#pragma unroll
        for (int k = 0; k < Kst; k++) nv += vd[k] ? 1 : 0;
        int base = nv ? atomicAdd(&g_cnt, nv) : 0;
#pragma unroll
        for (int k = 0; k < Kst; k++) {
            if (vd[k]) {
                slots[k] = base;
                g_rowmap[base] = bl * Kst + k;
                base++;
            } else slots[k] = -1;
        }
    }
    __syncthreads();
    float inv = 1.f / fmaxf(ssum, 1e-8f);

    float wm = 0.f, mx = -1e9f;
    bool any = false;
#pragma unroll
    for (int k = 0; k < Kst; k++) {
        swr[k] *= inv;
        float xv = 0.f;
        if (vd[k]) {
            int role = max(roles[b * Kst + k], 0);
            xv = sr[(((size_t)(b * Kst + k)) * Lseq + l) * Ddim + d] + remb[role * Ddim + d];
            any = true;
            mx = fmaxf(mx, xv);
            __nv_bfloat16 hi, lo;
            split2(xv, hi, lo);
            size_t row = (size_t)slots[k] * 1024;
            g_Xs[row + d] = hi;
            g_Xs[row + 512 + d] = lo;
        }
        wm += swr[k] * xv;
    }
    dout[OUT_WM + (size_t)bl * Ddim + d] = wm;
    dout[OUT_MF + (size_t)bl * Ddim + d] = any ? mx : 0.f;
    if (d < Kst) g_swr[bl * Kst + d] = swr[d];
}

// ---------------- pad compacted rows to multiple of 128 with zeros ----------------
__global__ void pad_x_kernel() {
    int Mv = g_cnt;
    int padded = (Mv + 127) & ~127;
    int r = Mv + blockIdx.x;
    if (r >= padded) return;
    uint32_t* row = (uint32_t*)(g_Xs + (size_t)r * 1024);
    for (int i = threadIdx.x; i < 512; i += 256) row[i] = 0;
}

// ---------------- fused weight splitter: B-side [hi | hi | lo] ----------------
__global__ void split_w_all(const float* __restrict__ Wq, const float* __restrict__ Wk,
                            const float* __restrict__ Wv, const float* __restrict__ Wo,
                            const float* __restrict__ Wg2, const float* __restrict__ Wg1,
                            __nv_bfloat16* __restrict__ oWs1, __nv_bfloat16* __restrict__ oWso,
                            __nv_bfloat16* __restrict__ oWsg2, __nv_bfloat16* __restrict__ oWsg1) {
    int idx = blockIdx.x * 256 + threadIdx.x;
    const float* W;
    __nv_bfloat16* out;
    int Kk, e;
    if (idx < 262144)        { W = Wq;  out = oWs1;                         Kk = 512;  e = idx; }
    else if (idx < 524288)   { W = Wk;  out = oWs1 + (size_t)512 * 1536;    Kk = 512;  e = idx - 262144; }
    else if (idx < 786432)   { W = Wv;  out = oWs1 + (size_t)1024 * 1536;   Kk = 512;  e = idx - 524288; }
    else if (idx < 1048576)  { W = Wo;  out = oWso;                         Kk = 512;  e = idx - 786432; }
    else if (idx < 1310720)  { W = Wg2; out = oWsg2;                        Kk = 512;  e = idx - 1048576; }
    else                     { W = Wg1; out = oWsg1;                        Kk = 1536; e = idx - 1310720; }
    int n = e / Kk, k = e - n * Kk;
    float v = W[e];
    __nv_bfloat16 hi, lo;
    split2(v, hi, lo);
    __nv_bfloat16* row = out + (size_t)n * 3 * Kk;
    row[k] = hi;
    row[Kk + k] = hi;
    row[2 * Kk + k] = lo;
}

// ---------------- HMMA bf16 GEMM, cp.async 3-stage pipeline, 2 CTAs/SM ----------------
// C[M,N] = A[M,K'] @ B[N,K']^T. CTA tile 128x128; 8 warps 2x4; warp 64x32.
// A physical lda = 2K'/3 ([hi|lo]); logical chunk kc>=lda reads phys kc-lda.
#define STAGES 3
#define GSM_BYTES (STAGES * 32768)

template <int EPI, bool COMPACT>
__global__ void __launch_bounds__(256, 2) gemm_mma(
    const __nv_bfloat16* __restrict__ A, const __nv_bfloat16* __restrict__ B,
    const float* __restrict__ bias, float* __restrict__ Cf,
    __nv_bfloat16* __restrict__ Cb, int K, int lda, int ldc) {
    int Mv = 0;
    if (COMPACT) {
        Mv = g_cnt;
        int padded = (Mv + 127) & ~127;
        if ((int)(blockIdx.y * 128) >= padded) return;
    }
    extern __shared__ __align__(1024) char smem[];
    uint32_t sA0 = smem_u32(smem);
    int tid = threadIdx.x;
    int wid = tid >> 5, lane = tid & 31;
    const int wm = wid >> 2, wn = wid & 3;

    const size_t bm = (size_t)blockIdx.y * 128;
    const int bn = blockIdx.x * 128;
    const int seg = tid & 7;
    const int r0 = tid >> 3;

    const __nv_bfloat16* Ab = A + (bm + r0) * (size_t)lda + seg * 8;
    const __nv_bfloat16* Bb = B + (size_t)(bn + r0) * K + seg * 8;
    const uint32_t swbase = swz(r0 * 128 + seg * 16);

    auto copy_stage = [&](int c, int buf) {
        int kc = c << 6;
        int akc = (kc >= lda) ? kc - lda : kc;
        uint32_t pa = sA0 + buf * 32768 + swbase;
#pragma unroll
        for (int i = 0; i < 4; i++) {
            cp_async16(pa + i * 32 * 128, Ab + (size_t)(i * 32) * lda + akc);
            cp_async16(pa + 16384 + i * 32 * 128, Bb + (size_t)(i * 32) * K + kc);
        }
        asm volatile("cp.async.commit_group;" ::: "memory");
    };

    float acc[4][4][4];
#pragma unroll
    for (int i = 0; i < 4; i++)
#pragma unroll
        for (int j = 0; j < 4; j++)
#pragma unroll
            for (int q = 0; q < 4; q++) acc[i][j][q] = 0.f;

    const uint32_t aRow = wm * 64 + (lane & 15);
    const uint32_t aColB = (lane >> 4) << 4;
    const uint32_t bRow = wn * 32 + (lane & 7) + ((lane >> 4) << 3);
    const uint32_t bColB = ((lane >> 3) & 1) << 4;

    const int NC = K >> 6;
#pragma unroll
    for (int s = 0; s < STAGES - 1; s++)
        if (s < NC) copy_stage(s, s);

    for (int c = 0; c < NC; c++) {
        asm volatile("cp.async.wait_group %0;" :: "n"(STAGES - 2));
        __syncthreads();
        if (c + STAGES - 1 < NC) copy_stage(c + STAGES - 1, (c + STAGES - 1) % STAGES);

        uint32_t Abuf = sA0 + (c % STAGES) * 32768;
        uint32_t Bbuf = Abuf + 16384;
#pragma unroll
        for (int ks = 0; ks < 4; ks++) {
            uint32_t a[4][4], b[4][2];
#pragma unroll
            for (int mt = 0; mt < 4; mt++) {
                uint32_t off = (aRow + mt * 16) * 128 + ks * 32 + aColB;
                ldsm_x4(a[mt][0], a[mt][1], a[mt][2], a[mt][3], Abuf + swz(off));
            }
#pragma unroll
            for (int p = 0; p < 2; p++) {
                uint32_t off = (bRow + p * 16) * 128 + ks * 32 + bColB;
                ldsm_x4(b[2 * p][0], b[2 * p][1], b[2 * p + 1][0], b[2 * p + 1][1],
                        Bbuf + swz(off));
            }
#pragma unroll
            for (int mt = 0; mt < 4; mt++)
#pragma unroll
                for (int nt = 0; nt < 4; nt++)
                    mma16816(acc[mt][nt], a[mt], b[nt]);
        }
    }

    // epilogue
    const int g = lane >> 2, t = lane & 3;
#pragma unroll
    for (int mt = 0; mt < 4; mt++) {
#pragma unroll
        for (int half = 0; half < 2; half++) {
            size_t grow = bm + wm * 64 + mt * 16 + g + half * 8;
            size_t orow = grow;
            if (COMPACT) {
                if ((int)grow >= Mv) continue;
                orow = (size_t)g_rowmap[grow];
            }
#pragma unroll
            for (int nt = 0; nt < 4; nt++) {
                int col = bn + wn * 32 + nt * 8 + t * 2;
                float v0 = acc[mt][nt][half * 2 + 0];
                float v1 = acc[mt][nt][half * 2 + 1];
                if (EPI == 0) {
                    float2 o = make_float2(v0, v1);
                    *(float2*)(Cf + orow * (size_t)ldc + col) = o;
                } else if (EPI == 1) {
                    v0 += bias[col];
                    v1 += bias[col + 1];
                    v0 = 0.5f * v0 * (1.f + erff(v0 * 0.70710678118654752f));
                    v1 = 0.5f * v1 * (1.f + erff(v1 * 0.70710678118654752f));
                    __nv_bfloat16 h0, l0, h1, l1;
                    split2(v0, h0, l0);
                    split2(v1, h1, l1);
                    size_t o = orow * 1024 + col;
                    *(__nv_bfloat162*)(Cb + o)       = __nv_bfloat162(h0, h1);
                    *(__nv_bfloat162*)(Cb + o + 512) = __nv_bfloat162(l0, l1);
                } else {
                    v0 += bias[col];
                    v1 += bias[col + 1];
                    float2 o;
                    o.x = 1.f / (1.f + expf(-v0));
                    o.y = 1.f / (1.f + expf(-v1));
                    *(float2*)(Cf + orow * 512 + col) = o;
                }
            }
        }
    }
}

// ---------------- attention: 4x4 per (b,l,h); pooled split output + attn_mean ----------------
__global__ void __launch_bounds__(256) attn_kernel(
    const void* __restrict__ rm, const void* __restrict__ pm,
    float* __restrict__ dout) {
    int bl = blockIdx.x;
    int b = bl >> 10;
    int l = bl & 1023;
    int warp = threadIdx.x >> 5;
    int lane = threadIdx.x & 31;
    __shared__ float am[Kst];
    if (threadIdx.x < Kst) am[threadIdx.x] = 0.f;
    __syncthreads();
    int u8 = g_mask_u8;

    float2 q[Kst], kk[Kst], vv[Kst];
    float ln_w[Kst], swr[Kst];
    bool vd[Kst];
    int col = warp * HDdim + lane * 2;
#pragma unroll
    for (int s = 0; s < Kst; s++) {
        vd[s] = mask_at(rm, (b * Kst + s) * Lseq + l, u8) && mask_at(pm, b * Kst + s, u8);
        if (vd[s]) {
            size_t rbase = (size_t)(bl * Kst + s) * 1536 + col;
            q[s]  = *(const float2*)(g_QKV + rbase);
            kk[s] = *(const float2*)(g_QKV + rbase + 512);
            vv[s] = *(const float2*)(g_QKV + rbase + 1024);
        } else {
            q[s] = kk[s] = vv[s] = make_float2(0.f, 0.f);
        }
        ln_w[s] = g_lognsw[b * Kst + s];
        swr[s]  = g_swr[bl * Kst + s];
    }

    float dot[Kst][Kst];
#pragma unroll
    for (int i = 0; i < Kst; i++) {
#pragma unroll
        for (int j = 0; j < Kst; j++) {
            float p = q[i].x * kk[j].x + q[i].y * kk[j].y;
#pragma unroll
            for (int o = 16; o; o >>= 1) p += __shfl_xor_sync(0xffffffffu, p, o);
            dot[i][j] = p;
        }
    }

    float a[Kst][Kst];
#pragma unroll
    for (int i = 0; i < Kst; i++) {
        float lm[Kst] = {0.f, 0.f, 0.f, 0.f};
        float m = -3.4e38f;
#pragma unroll
        for (int j = 0; j < Kst; j++) {
            if (vd[j]) {
                lm[j] = dot[i][j] * 0.125f + ln_w[j];
                m = fmaxf(m, lm[j]);
            }
        }
        float ssum = 0.f;
#pragma unroll
        for (int j = 0; j < Kst; j++) {
            float e = vd[j] ? expf(lm[j] - m) : 0.f;
            a[i][j] = e;
            ssum += e;
        }
        float invs = (ssum > 0.f) ? (1.f / ssum) : 0.f;
#pragma unroll
        for (int j = 0; j < Kst; j++) a[i][j] *= invs;
    }

    float px = 0.f, py = 0.f;
#pragma unroll
    for (int i = 0; i < Kst; i++) {
        float ox = 0.f, oy = 0.f;
#pragma unroll
        for (int j = 0; j < Kst; j++) {
            ox += a[i][j] * vv[j].x;
            oy += a[i][j] * vv[j].y;
        }
        px += swr[i] * ox;
        py += swr[i] * oy;
    }
    __nv_bfloat16 hx, lx, hy, ly;
    split2(px, hx, lx);
    split2(py, hy, ly);
    size_t ob = (size_t)bl * 1024 + col;
    *(__nv_bfloat162*)(g_AOs + ob)       = __nv_bfloat162(hx, hy);
    *(__nv_bfloat162*)(g_AOs + ob + 512) = __nv_bfloat162(lx, ly);

    if (lane == 0) {
#pragma unroll
        for (int j = 0; j < Kst; j++)
            atomicAdd(&am[j], a[0][j] + a[1][j] + a[2][j] + a[3][j]);
    }
    __syncthreads();
    if (threadIdx.x < Kst)
        dout[OUT_AM + (size_t)bl * Kst + threadIdx.x] = am[threadIdx.x] * (1.f / 32.f);
}

// ---------------- block reduction ----------------
__device__ __forceinline__ float block_sum(float v, float* red) {
    int lane = threadIdx.x & 31, w = threadIdx.x >> 5;
#pragma unroll
    for (int o = 16; o; o >>= 1) v += __shfl_xor_sync(0xffffffffu, v, o);
    __syncthreads();
    if (lane == 0) red[w] = v;
    __syncthreads();
    if (threadIdx.x == 0) {
        float t = 0.f;
        int nw = (blockDim.x + 31) >> 5;
        for (int i = 0; i < nw; i++) t += red[i];
        red[8] = t;
    }
    __syncthreads();
    return red[8];
}

// ---------------- layernorm of gate_in (1536) -> split bf16 [hi|lo] ----------------
__global__ void __launch_bounds__(256) ln_gatein_kernel(
    const float* __restrict__ dro, const float* __restrict__ g,
    const float* __restrict__ bb) {
    int bl = blockIdx.x;
    __shared__ float buf[D3];
    __shared__ float red[9];
    float s = 0.f;
    for (int c = threadIdx.x; c < D3; c += 256) {
        float v;
        if (c < Ddim)          v = dro[OUT_AP + (size_t)bl * Ddim + c];
        else if (c < 2 * Ddim) v = dro[OUT_WM + (size_t)bl * Ddim + (c - Ddim)];
        else                   v = dro[OUT_MF + (size_t)bl * Ddim + (c - 2 * Ddim)];
        buf[c] = v;
        s += v;
    }
    s = block_sum(s, red);
    float mu = s * (1.f / D3);
    float sq = 0.f;
    for (int c = threadIdx.x; c < D3; c += 256) {
        float d = buf[c] - mu;
        sq += d * d;
    }
    sq = block_sum(sq, red);
    float rs = rsqrtf(sq * (1.f / D3) + 1e-5f);
    for (int c = threadIdx.x; c < D3; c += 256) {
        float y = (buf[c] - mu) * rs * g[c] + bb[c];
        __nv_bfloat16 hi, lo;
        split2(y, hi, lo);
        size_t row = (size_t)bl * 3072;
        g_Gs[row + c] = hi;
        g_Gs[row + 1536 + c] = lo;
    }
}

// ---------------- final fuse + layernorm(512) ----------------
__global__ void __launch_bounds__(256) ln_final_kernel(
    float* __restrict__ dout, const float* __restrict__ ng,
    const float* __restrict__ nb) {
    int bl = blockIdx.x;
    __shared__ float buf[Ddim];
    __shared__ float red[9];
    float s = 0.f;
    for (int d = threadIdx.x; d < Ddim; d += 256) {
        float gate = g_GATE[(size_t)bl * Ddim + d];
        float ap = dout[OUT_AP + (size_t)bl * Ddim + d];
        float wm = dout[OUT_WM + (size_t)bl * Ddim + d];
        float mf = dout[OUT_MF + (size_t)bl * Ddim + d];
        float y = gate * 0.5f * (ap + wm) + (1.f - gate) * mf + wm;
        buf[d] = y;
        s += y;
    }
    s = block_sum(s, red);
    float mu = s * (1.f / Ddim);
    float sq = 0.f;
    for (int d = threadIdx.x; d < Ddim; d += 256) {
        float dd = buf[d] - mu;
        sq += dd * dd;
    }
    sq = block_sum(sq, red);
    float rs = rsqrtf(sq * (1.f / Ddim) + 1e-5f);
    for (int d = threadIdx.x; d < Ddim; d += 256)
        dout[OUT_FUSED + (size_t)bl * Ddim + d] = (buf[d] - mu) * rs * ng[d] + nb[d];
}

// ---------------- launch ----------------
extern "C" void kernel_launch(void* const* d_in, const int* in_sizes, int n_in,
                              void* d_out, int out_size) {
    const float* sr    = (const float*)d_in[0];
    const void*  rmask = d_in[1];
    const float* sw    = (const float*)d_in[2];
    const int*   roles = (const int*)d_in[3];
    const void*  pmask = d_in[4];
    const float* remb  = (const float*)d_in[5];
    const float* Wq    = (const float*)d_in[6];
    const float* Wk    = (const float*)d_in[7];
    const float* Wv    = (const float*)d_in[8];
    const float* Wo    = (const float*)d_in[9];
    const float* ln1g  = (const float*)d_in[10];
    const float* ln1b  = (const float*)d_in[11];
    const float* Wg1   = (const float*)d_in[12];
    const float* bg1   = (const float*)d_in[13];
    const float* Wg2   = (const float*)d_in[14];
    const float* bg2   = (const float*)d_in[15];
    const float* ng    = (const float*)d_in[16];
    const float* nb    = (const float*)d_in[17];
    float* dout = (float*)d_out;

    __nv_bfloat16 *pXs, *pAOs, *pGs, *pH1s, *pWs1, *pWso, *pWsg1, *pWsg2;
    float *pQKV, *pGATE;
    cudaGetSymbolAddress((void**)&pXs, g_Xs);
    cudaGetSymbolAddress((void**)&pQKV, g_QKV);
    cudaGetSymbolAddress((void**)&pAOs, g_AOs);
    cudaGetSymbolAddress((void**)&pGs, g_Gs);
    cudaGetSymbolAddress((void**)&pH1s, g_H1s);
    cudaGetSymbolAddress((void**)&pGATE, g_GATE);
    cudaGetSymbolAddress((void**)&pWs1, g_Ws1);
    cudaGetSymbolAddress((void**)&pWso, g_Wso);
    cudaGetSymbolAddress((void**)&pWsg1, g_Wsg1);
    cudaGetSymbolAddress((void**)&pWsg2, g_Wsg2);

    cudaFuncSetAttribute(gemm_mma<0, true>,  cudaFuncAttributeMaxDynamicSharedMemorySize, GSM_BYTES);
    cudaFuncSetAttribute(gemm_mma<0, false>, cudaFuncAttributeMaxDynamicSharedMemorySize, GSM_BYTES);
    cudaFuncSetAttribute(gemm_mma<1, false>, cudaFuncAttributeMaxDynamicSharedMemorySize, GSM_BYTES);
    cudaFuncSetAttribute(gemm_mma<2, false>, cudaFuncAttributeMaxDynamicSharedMemorySize, GSM_BYTES);

    detect_mask_kernel<<<1, 256>>>(rmask);
    nsw_kernel<<<1, 32>>>(sw, pmask, dout + OUT_NSW);
    build_x_kernel<<<BLn, 512>>>(sr, rmask, pmask, roles, remb, dout);
    pad_x_kernel<<<128, 256>>>();

    split_w_all<<<8192, 256>>>(Wq, Wk, Wv, Wo, Wg2, Wg1, pWs1, pWso, pWsg2, pWsg1);

    // fused QKV on compacted rows: [Mv x 1536] = Xs([hi|lo], lda=1024) @ Ws1^T
    {
        dim3 grid(1536 / 128, Tn / 128);
        gemm_mma<0, true><<<grid, 256, GSM_BYTES>>>(pXs, pWs1, nullptr, pQKV, nullptr, 1536, 1024, 1536);
    }

    attn_kernel<<<BLn, 256>>>(rmask, pmask, dout);

    // attn_pooled = AOs @ Wso^T  [8192 x 512]
    {
        dim3 grid(512 / 128, BLn / 128);
        gemm_mma<0, false><<<grid, 256, GSM_BYTES>>>(pAOs, pWso, nullptr, dout + OUT_AP, nullptr, 1536, 1024, 512);
    }

    ln_gatein_kernel<<<BLn, 256>>>(dout, ln1g, ln1b);

    // h = gelu(Gs @ Wsg1^T + bg1) -> split bf16 [hi|lo]
    {
        dim3 grid(512 / 128, BLn / 128);
        gemm_mma<1, false><<<grid, 256, GSM_BYTES>>>(pGs, pWsg1, bg1, nullptr, pH1s, 4608, 3072, 0);
    }
    // gate = sigmoid(H1s @ Wsg2^T + bg2)
    {
        dim3 grid(512 / 128, BLn / 128);
        gemm_mma<2, false><<<grid, 256, GSM_BYTES>>>(pH1s, pWsg2, bg2, pGATE, nullptr, 1536, 1024, 0);
    }

    ln_final_kernel<<<BLn, 256>>>(dout, ng, nb);
}

// round 9
// speedup vs baseline: 1.1346x; 1.0118x over previous
#include <cuda_runtime.h>
#include <cuda_bf16.h>
#include <math.h>
#include <stdint.h>

// ---------------- problem constants ----------------
#define Bdim 8
#define Kst 4
#define Lseq 1024
#define Ddim 512
#define Hn 8
#define HDdim 64
#define BLn 8192
#define Tn 32768
#define D3 1536

#define OUT_FUSED 0
#define OUT_AP    4194304
#define OUT_WM    8388608
#define OUT_MF    12582912
#define OUT_AM    16777216
#define OUT_NSW   16809984

// ---------------- device scratch ----------------
// A-side physical layout: [hi(0:S) | lo(S:2S)]; logical K'=3S (third segment re-reads hi).
// B-side physical layout: [hi | hi | lo] (3S).
__device__ __nv_bfloat16 g_Xs[(size_t)Tn * 1024];
__device__ float         g_QKV[(size_t)Tn * 1536];
__device__ __nv_bfloat16 g_AOs[(size_t)BLn * 1024];
__device__ __nv_bfloat16 g_Gs[(size_t)BLn * 3072];
__device__ __nv_bfloat16 g_H1s[(size_t)BLn * 1024];
__device__ float         g_GATE[(size_t)BLn * Ddim];
__device__ __nv_bfloat16 g_Ws1[1536 * 1536];
__device__ __nv_bfloat16 g_Wso[512 * 1536];
__device__ __nv_bfloat16 g_Wsg1[512 * 4608];
__device__ __nv_bfloat16 g_Wsg2[512 * 1536];
__device__ float g_swr[BLn * Kst];
__device__ float g_nsw[Bdim * Kst];
__device__ float g_lognsw[Bdim * Kst];
__device__ int   g_mask_u8;
__device__ int   g_cnt;
__device__ int   g_rowmap[Tn];

// ---------------- helpers ----------------
__device__ __forceinline__ uint32_t smem_u32(const void* p) {
    uint32_t a;
    asm("{ .reg .u64 t; cvta.to.shared.u64 t, %1; cvt.u32.u64 %0, t; }" : "=r"(a) : "l"(p));
    return a;
}
__device__ __forceinline__ void split2(float v, __nv_bfloat16& hi, __nv_bfloat16& lo) {
    hi = __float2bfloat16(v);
    lo = __float2bfloat16(v - __bfloat162float(hi));
}
__device__ __forceinline__ void ldsm_x4(uint32_t& r0, uint32_t& r1, uint32_t& r2,
                                        uint32_t& r3, uint32_t addr) {
    asm volatile("ldmatrix.sync.aligned.m8n8.x4.shared.b16 {%0,%1,%2,%3}, [%4];"
                 : "=r"(r0), "=r"(r1), "=r"(r2), "=r"(r3) : "r"(addr));
}
__device__ __forceinline__ void mma16816(float* c, const uint32_t* a, const uint32_t* b) {
    asm volatile(
        "mma.sync.aligned.m16n8k16.row.col.f32.bf16.bf16.f32 "
        "{%0,%1,%2,%3}, {%4,%5,%6,%7}, {%8,%9}, {%0,%1,%2,%3};"
        : "+f"(c[0]), "+f"(c[1]), "+f"(c[2]), "+f"(c[3])
        : "r"(a[0]), "r"(a[1]), "r"(a[2]), "r"(a[3]), "r"(b[0]), "r"(b[1]));
}
__device__ __forceinline__ uint32_t swz(uint32_t off) {
    return off ^ ((off >> 3) & 0x70);
}
__device__ __forceinline__ void cp_async16(uint32_t dst, const void* src) {
    asm volatile("cp.async.cg.shared.global [%0], [%1], 16;" :: "r"(dst), "l"(src));
}
__device__ __forceinline__ bool mask_at(const void* p, int idx, int u8) {
    return u8 ? (((const unsigned char*)p)[idx] != 0) : (((const int*)p)[idx] != 0);
}

// ---------------- fused mask-detect + nsw ----------------
__global__ void detnsw_kernel(const void* __restrict__ rm, const float* __restrict__ sw,
                              const void* __restrict__ pm, float* __restrict__ out_nsw) {
    __shared__ int s_u8;
    const int* p = (const int*)rm;
    int bad = 0;
    for (int i = threadIdx.x; i < 8192; i += 256) {
        int v = p[i];
        if (v != 0 && v != 1) bad = 1;
    }
    bad = __syncthreads_or(bad);
    if (threadIdx.x == 0) {
        g_mask_u8 = bad;
        g_cnt = 0;
        s_u8 = bad;
    }
    __syncthreads();
    int b = threadIdx.x;
    if (b >= Bdim) return;
    int u8 = s_u8;
    float w[Kst], pres[Kst];
    float denom = 0.f, psum = 0.f;
#pragma unroll
    for (int k = 0; k < Kst; k++) {
        pres[k] = mask_at(pm, b * Kst + k, u8) ? 1.f : 0.f;
        w[k] = sw[b * Kst + k] * pres[k];
        denom += w[k];
        psum += pres[k];
    }
#pragma unroll
    for (int k = 0; k < Kst; k++) {
        float nswk = (denom > 1e-8f) ? (w[k] / fmaxf(denom, 1e-8f))
                                     : (pres[k] / fmaxf(psum, 1.f));
        g_nsw[b * Kst + k] = nswk;
        g_lognsw[b * Kst + k] = logf(fmaxf(nswk, 1e-8f));
        out_nsw[b * Kst + k] = nswk;
    }
}

// ---------------- fused build-x + weight split ----------------
// blocks [0, 8192): build split-x (compacted [hi|lo]), weighted_mean, max_feat, swr.
// blocks [8192, 8192+4096): weight split, linear idx over 2,097,152 elements.
#define WSPLIT_BLOCKS 4096

__global__ void __launch_bounds__(512) build_split_kernel(
    const float* __restrict__ sr, const void* __restrict__ rm,
    const void* __restrict__ pm, const int* __restrict__ roles,
    const float* __restrict__ remb, float* __restrict__ dout,
    const float* __restrict__ Wq, const float* __restrict__ Wk,
    const float* __restrict__ Wv, const float* __restrict__ Wo,
    const float* __restrict__ Wg2, const float* __restrict__ Wg1,
    __nv_bfloat16* __restrict__ oWs1, __nv_bfloat16* __restrict__ oWso,
    __nv_bfloat16* __restrict__ oWsg2, __nv_bfloat16* __restrict__ oWsg1) {
    if (blockIdx.x >= BLn) {
        // ---- weight split path: total 5*262144 + 786432 = 2,097,152 elements ----
        int idx = (blockIdx.x - BLn) * 512 + threadIdx.x;
        const float* W;
        __nv_bfloat16* out;
        int Kk, e;
        if (idx < 262144)        { W = Wq;  out = oWs1;                       Kk = 512;  e = idx; }
        else if (idx < 524288)   { W = Wk;  out = oWs1 + (size_t)512 * 1536;  Kk = 512;  e = idx - 262144; }
        else if (idx < 786432)   { W = Wv;  out = oWs1 + (size_t)1024 * 1536; Kk = 512;  e = idx - 524288; }
        else if (idx < 1048576)  { W = Wo;  out = oWso;                       Kk = 512;  e = idx - 786432; }
        else if (idx < 1310720)  { W = Wg2; out = oWsg2;                      Kk = 512;  e = idx - 1048576; }
        else                     { W = Wg1; out = oWsg1;                      Kk = 1536; e = idx - 1310720; }
        int n = e / Kk, k = e - n * Kk;
        float v = W[e];
        __nv_bfloat16 hi, lo;
        split2(v, hi, lo);
        __nv_bfloat16* row = out + (size_t)n * 3 * Kk;
        row[k] = hi;
        row[Kk + k] = hi;
        row[2 * Kk + k] = lo;
        return;
    }
    // ---- build-x path ----
    int bl = blockIdx.x;
    int b = bl >> 10;
    int l = bl & 1023;
    int d = threadIdx.x;
    int u8 = g_mask_u8;
    __shared__ int slots[Kst];

    bool vd[Kst];
    float swr[Kst];
    float ssum = 0.f;
#pragma unroll
    for (int k = 0; k < Kst; k++) {
        bool v = mask_at(rm, (b * Kst + k) * Lseq + l, u8) && mask_at(pm, b * Kst + k, u8);
        vd[k] = v;
        swr[k] = v ? g_nsw[b * Kst + k] : 0.f;
        ssum += swr[k];
    }
    if (d == 0) {
        int nv = 0;
#pragma unroll
        for (int k = 0; k < Kst; k++) nv += vd[k] ? 1 : 0;
        int base = nv ? atomicAdd(&g_cnt, nv) : 0;
#pragma unroll
        for (int k = 0; k < Kst; k++) {
            if (vd[k]) {
                slots[k] = base;
                g_rowmap[base] = bl * Kst + k;
                base++;
            } else slots[k] = -1;
        }
    }
    __syncthreads();
    float inv = 1.f / fmaxf(ssum, 1e-8f);

    float wm = 0.f, mx = -1e9f;
    bool any = false;
#pragma unroll
    for (int k = 0; k < Kst; k++) {
        swr[k] *= inv;
        float xv = 0.f;
        if (vd[k]) {
            int role = max(roles[b * Kst + k], 0);
            xv = sr[(((size_t)(b * Kst + k)) * Lseq + l) * Ddim + d] + remb[role * Ddim + d];
            any = true;
            mx = fmaxf(mx, xv);
            __nv_bfloat16 hi, lo;
            split2(xv, hi, lo);
            size_t row = (size_t)slots[k] * 1024;
            g_Xs[row + d] = hi;
            g_Xs[row + 512 + d] = lo;
        }
        wm += swr[k] * xv;
    }
    dout[OUT_WM + (size_t)bl * Ddim + d] = wm;
    dout[OUT_MF + (size_t)bl * Ddim + d] = any ? mx : 0.f;
    if (d < Kst) g_swr[bl * Kst + d] = swr[d];
}

// ---------------- HMMA bf16 GEMM, cp.async 3-stage pipeline, 2 CTAs/SM ----------------
// C[M,N] = A[M,K'] @ B[N,K']^T. CTA tile 128x128; 8 warps 2x4; warp 64x32.
// A physical lda = 2K'/3 ([hi|lo]); logical chunk kc>=lda reads phys kc-lda.
// COMPACT rows in [Mv, padded) are zeros (never written); results never stored.
#define STAGES 3
#define GSM_BYTES (STAGES * 32768)

template <int EPI, bool COMPACT>
__global__ void __launch_bounds__(256, 2) gemm_mma(
    const __nv_bfloat16* __restrict__ A, const __nv_bfloat16* __restrict__ B,
    const float* __restrict__ bias, float* __restrict__ Cf,
    __nv_bfloat16* __restrict__ Cb, int K, int lda, int ldc) {
    int Mv = 0;
    if (COMPACT) {
        Mv = g_cnt;
        int padded = (Mv + 127) & ~127;
        if ((int)(blockIdx.y * 128) >= padded) return;
    }
    extern __shared__ __align__(1024) char smem[];
    uint32_t sA0 = smem_u32(smem);
    int tid = threadIdx.x;
    int wid = tid >> 5, lane = tid & 31;
    const int wm = wid >> 2, wn = wid & 3;

    const size_t bm = (size_t)blockIdx.y * 128;
    const int bn = blockIdx.x * 128;
    const int seg = tid & 7;
    const int r0 = tid >> 3;

    const __nv_bfloat16* Ab = A + (bm + r0) * (size_t)lda + seg * 8;
    const __nv_bfloat16* Bb = B + (size_t)(bn + r0) * K + seg * 8;
    const uint32_t swbase = swz(r0 * 128 + seg * 16);

    auto copy_stage = [&](int c, int buf) {
        int kc = c << 6;
        int akc = (kc >= lda) ? kc - lda : kc;
        uint32_t pa = sA0 + buf * 32768 + swbase;
#pragma unroll
        for (int i = 0; i < 4; i++) {
            cp_async16(pa + i * 32 * 128, Ab + (size_t)(i * 32) * lda + akc);
            cp_async16(pa + 16384 + i * 32 * 128, Bb + (size_t)(i * 32) * K + kc);
        }
        asm volatile("cp.async.commit_group;" ::: "memory");
    };

    float acc[4][4][4];
#pragma unroll
    for (int i = 0; i < 4; i++)
#pragma unroll
        for (int j = 0; j < 4; j++)
#pragma unroll
            for (int q = 0; q < 4; q++) acc[i][j][q] = 0.f;

    const uint32_t aRow = wm * 64 + (lane & 15);
    const uint32_t aColB = (lane >> 4) << 4;
    const uint32_t bRow = wn * 32 + (lane & 7) + ((lane >> 4) << 3);
    const uint32_t bColB = ((lane >> 3) & 1) << 4;

    const int NC = K >> 6;
#pragma unroll
    for (int s = 0; s < STAGES - 1; s++)
        if (s < NC) copy_stage(s, s);

    for (int c = 0; c < NC; c++) {
        asm volatile("cp.async.wait_group %0;" :: "n"(STAGES - 2));
        __syncthreads();
        if (c + STAGES - 1 < NC) copy_stage(c + STAGES - 1, (c + STAGES - 1) % STAGES);

        uint32_t Abuf = sA0 + (c % STAGES) * 32768;
        uint32_t Bbuf = Abuf + 16384;
#pragma unroll
        for (int ks = 0; ks < 4; ks++) {
            uint32_t a[4][4], b[4][2];
#pragma unroll
            for (int mt = 0; mt < 4; mt++) {
                uint32_t off = (aRow + mt * 16) * 128 + ks * 32 + aColB;
                ldsm_x4(a[mt][0], a[mt][1], a[mt][2], a[mt][3], Abuf + swz(off));
            }
#pragma unroll
            for (int p = 0; p < 2; p++) {
                uint32_t off = (bRow + p * 16) * 128 + ks * 32 + bColB;
                ldsm_x4(b[2 * p][0], b[2 * p][1], b[2 * p + 1][0], b[2 * p + 1][1],
                        Bbuf + swz(off));
            }
#pragma unroll
            for (int mt = 0; mt < 4; mt++)
#pragma unroll
                for (int nt = 0; nt < 4; nt++)
                    mma16816(acc[mt][nt], a[mt], b[nt]);
        }
    }

    // epilogue
    const int g = lane >> 2, t = lane & 3;
#pragma unroll
    for (int mt = 0; mt < 4; mt++) {
#pragma unroll
        for (int half = 0; half < 2; half++) {
            size_t grow = bm + wm * 64 + mt * 16 + g + half * 8;
            size_t orow = grow;
            if (COMPACT) {
                if ((int)grow >= Mv) continue;
                orow = (size_t)g_rowmap[grow];
            }
#pragma unroll
            for (int nt = 0; nt < 4; nt++) {
                int col = bn + wn * 32 + nt * 8 + t * 2;
                float v0 = acc[mt][nt][half * 2 + 0];
                float v1 = acc[mt][nt][half * 2 + 1];
                if (EPI == 0) {
                    float2 o = make_float2(v0, v1);
                    *(float2*)(Cf + orow * (size_t)ldc + col) = o;
                } else if (EPI == 1) {
                    v0 += bias[col];
                    v1 += bias[col + 1];
                    v0 = 0.5f * v0 * (1.f + erff(v0 * 0.70710678118654752f));
                    v1 = 0.5f * v1 * (1.f + erff(v1 * 0.70710678118654752f));
                    __nv_bfloat16 h0, l0, h1, l1;
                    split2(v0, h0, l0);
                    split2(v1, h1, l1);
                    size_t o = orow * 1024 + col;
                    *(__nv_bfloat162*)(Cb + o)       = __nv_bfloat162(h0, h1);
                    *(__nv_bfloat162*)(Cb + o + 512) = __nv_bfloat162(l0, l1);
                } else {
                    v0 += bias[col];
                    v1 += bias[col + 1];
                    float2 o;
                    o.x = 1.f / (1.f + __expf(-v0));
                    o.y = 1.f / (1.f + __expf(-v1));
                    *(float2*)(Cf + orow * 512 + col) = o;
                }
            }
        }
    }
}

// ---------------- attention: 4x4 per (b,l,h); pooled split output + attn_mean ----------------
__global__ void __launch_bounds__(256) attn_kernel(
    const void* __restrict__ rm, const void* __restrict__ pm,
    float* __restrict__ dout) {
    int bl = blockIdx.x;
    int b = bl >> 10;
    int l = bl & 1023;
    int warp = threadIdx.x >> 5;
    int lane = threadIdx.x & 31;
    __shared__ float am[Kst];
    if (threadIdx.x < Kst) am[threadIdx.x] = 0.f;
    __syncthreads();
    int u8 = g_mask_u8;

    float2 q[Kst], kk[Kst], vv[Kst];
    float ln_w[Kst], swr[Kst];
    bool vd[Kst];
    int col = warp * HDdim + lane * 2;
#pragma unroll
    for (int s = 0; s < Kst; s++) {
        vd[s] = mask_at(rm, (b * Kst + s) * Lseq + l, u8) && mask_at(pm, b * Kst + s, u8);
        if (vd[s]) {
            size_t rbase = (size_t)(bl * Kst + s) * 1536 + col;
            q[s]  = *(const float2*)(g_QKV + rbase);
            kk[s] = *(const float2*)(g_QKV + rbase + 512);
            vv[s] = *(const float2*)(g_QKV + rbase + 1024);
        } else {
            q[s] = kk[s] = vv[s] = make_float2(0.f, 0.f);
        }
        ln_w[s] = g_lognsw[b * Kst + s];
        swr[s]  = g_swr[bl * Kst + s];
    }

    float dot[Kst][Kst];
#pragma unroll
    for (int i = 0; i < Kst; i++) {
#pragma unroll
        for (int j = 0; j < Kst; j++) {
            float p = q[i].x * kk[j].x + q[i].y * kk[j].y;
#pragma unroll
            for (int o = 16; o; o >>= 1) p += __shfl_xor_sync(0xffffffffu, p, o);
            dot[i][j] = p;
        }
    }

    float a[Kst][Kst];
#pragma unroll
    for (int i = 0; i < Kst; i++) {
        float lm[Kst] = {0.f, 0.f, 0.f, 0.f};
        float m = -3.4e38f;
#pragma unroll
        for (int j = 0; j < Kst; j++) {
            if (vd[j]) {
                lm[j] = dot[i][j] * 0.125f + ln_w[j];
                m = fmaxf(m, lm[j]);
            }
        }
        float ssum = 0.f;
#pragma unroll
        for (int j = 0; j < Kst; j++) {
            float e = vd[j] ? __expf(lm[j] - m) : 0.f;
            a[i][j] = e;
            ssum += e;
        }
        float invs = (ssum > 0.f) ? (1.f / ssum) : 0.f;
#pragma unroll
        for (int j = 0; j < Kst; j++) a[i][j] *= invs;
    }

    float px = 0.f, py = 0.f;
#pragma unroll
    for (int i = 0; i < Kst; i++) {
        float ox = 0.f, oy = 0.f;
#pragma unroll
        for (int j = 0; j < Kst; j++) {
            ox += a[i][j] * vv[j].x;
            oy += a[i][j] * vv[j].y;
        }
        px += swr[i] * ox;
        py += swr[i] * oy;
    }
    __nv_bfloat16 hx, lx, hy, ly;
    split2(px, hx, lx);
    split2(py, hy, ly);
    size_t ob = (size_t)bl * 1024 + col;
    *(__nv_bfloat162*)(g_AOs + ob)       = __nv_bfloat162(hx, hy);
    *(__nv_bfloat162*)(g_AOs + ob + 512) = __nv_bfloat162(lx, ly);

    if (lane == 0) {
#pragma unroll
        for (int j = 0; j < Kst; j++)
            atomicAdd(&am[j], a[0][j] + a[1][j] + a[2][j] + a[3][j]);
    }
    __syncthreads();
    if (threadIdx.x < Kst)
        dout[OUT_AM + (size_t)bl * Kst + threadIdx.x] = am[threadIdx.x] * (1.f / 32.f);
}

// ---------------- block reduction ----------------
__device__ __forceinline__ float block_sum(float v, float* red) {
    int lane = threadIdx.x & 31, w = threadIdx.x >> 5;
#pragma unroll
    for (int o = 16; o; o >>= 1) v += __shfl_xor_sync(0xffffffffu, v, o);
    __syncthreads();
    if (lane == 0) red[w] = v;
    __syncthreads();
    if (threadIdx.x == 0) {
        float t = 0.f;
        int nw = (blockDim.x + 31) >> 5;
        for (int i = 0; i < nw; i++) t += red[i];
        red[8] = t;
    }
    __syncthreads();
    return red[8];
}

// ---------------- layernorm of gate_in (1536) -> split bf16 [hi|lo] ----------------
__global__ void __launch_bounds__(256) ln_gatein_kernel(
    const float* __restrict__ dro, const float* __restrict__ g,
    const float* __restrict__ bb) {
    int bl = blockIdx.x;
    __shared__ float buf[D3];
    __shared__ float red[9];
    float s = 0.f;
    for (int c = threadIdx.x; c < D3; c += 256) {
        float v;
        if (c < Ddim)          v = dro[OUT_AP + (size_t)bl * Ddim + c];
        else if (c < 2 * Ddim) v = dro[OUT_WM + (size_t)bl * Ddim + (c - Ddim)];
        else                   v = dro[OUT_MF + (size_t)bl * Ddim + (c - 2 * Ddim)];
        buf[c] = v;
        s += v;
    }
    s = block_sum(s, red);
    float mu = s * (1.f / D3);
    float sq = 0.f;
    for (int c = threadIdx.x; c < D3; c += 256) {
        float d = buf[c] - mu;
        sq += d * d;
    }
    sq = block_sum(sq, red);
    float rs = rsqrtf(sq * (1.f / D3) + 1e-5f);
    for (int c = threadIdx.x; c < D3; c += 256) {
        float y = (buf[c] - mu) * rs * g[c] + bb[c];
        __nv_bfloat16 hi, lo;
        split2(y, hi, lo);
        size_t row = (size_t)bl * 3072;
        g_Gs[row + c] = hi;
        g_Gs[row + 1536 + c] = lo;
    }
}

// ---------------- final fuse + layernorm(512) ----------------
__global__ void __launch_bounds__(256) ln_final_kernel(
    float* __restrict__ dout, const float* __restrict__ ng,
    const float* __restrict__ nb) {
    int bl = blockIdx.x;
    __shared__ float buf[Ddim];
    __shared__ float red[9];
    float s = 0.f;
    for (int d = threadIdx.x; d < Ddim; d += 256) {
        float gate = g_GATE[(size_t)bl * Ddim + d];
        float ap = dout[OUT_AP + (size_t)bl * Ddim + d];
        float wm = dout[OUT_WM + (size_t)bl * Ddim + d];
        float mf = dout[OUT_MF + (size_t)bl * Ddim + d];
        float y = gate * 0.5f * (ap + wm) + (1.f - gate) * mf + wm;
        buf[d] = y;
        s += y;
    }
    s = block_sum(s, red);
    float mu = s * (1.f / Ddim);
    float sq = 0.f;
    for (int d = threadIdx.x; d < Ddim; d += 256) {
        float dd = buf[d] - mu;
        sq += dd * dd;
    }
    sq = block_sum(sq, red);
    float rs = rsqrtf(sq * (1.f / Ddim) + 1e-5f);
    for (int d = threadIdx.x; d < Ddim; d += 256)
        dout[OUT_FUSED + (size_t)bl * Ddim + d] = (buf[d] - mu) * rs * ng[d] + nb[d];
}

// ---------------- launch ----------------
extern "C" void kernel_launch(void* const* d_in, const int* in_sizes, int n_in,
                              void* d_out, int out_size) {
    const float* sr    = (const float*)d_in[0];
    const void*  rmask = d_in[1];
    const float* sw    = (const float*)d_in[2];
    const int*   roles = (const int*)d_in[3];
    const void*  pmask = d_in[4];
    const float* remb  = (const float*)d_in[5];
    const float* Wq    = (const float*)d_in[6];
    const float* Wk    = (const float*)d_in[7];
    const float* Wv    = (const float*)d_in[8];
    const float* Wo    = (const float*)d_in[9];
    const float* ln1g  = (const float*)d_in[10];
    const float* ln1b  = (const float*)d_in[11];
    const float* Wg1   = (const float*)d_in[12];
    const float* bg1   = (const float*)d_in[13];
    const float* Wg2   = (const float*)d_in[14];
    const float* bg2   = (const float*)d_in[15];
    const float* ng    = (const float*)d_in[16];
    const float* nb    = (const float*)d_in[17];
    float* dout = (float*)d_out;

    __nv_bfloat16 *pXs, *pAOs, *pGs, *pH1s, *pWs1, *pWso, *pWsg1, *pWsg2;
    float *pQKV, *pGATE;
    cudaGetSymbolAddress((void**)&pXs, g_Xs);
    cudaGetSymbolAddress((void**)&pQKV, g_QKV);
    cudaGetSymbolAddress((void**)&pAOs, g_AOs);
    cudaGetSymbolAddress((void**)&pGs, g_Gs);
    cudaGetSymbolAddress((void**)&pH1s, g_H1s);
    cudaGetSymbolAddress((void**)&pGATE, g_GATE);
    cudaGetSymbolAddress((void**)&pWs1, g_Ws1);
    cudaGetSymbolAddress((void**)&pWso, g_Wso);
    cudaGetSymbolAddress((void**)&pWsg1, g_Wsg1);
    cudaGetSymbolAddress((void**)&pWsg2, g_Wsg2);

    cudaFuncSetAttribute(gemm_mma<0, true>,  cudaFuncAttributeMaxDynamicSharedMemorySize, GSM_BYTES);
    cudaFuncSetAttribute(gemm_mma<0, false>, cudaFuncAttributeMaxDynamicSharedMemorySize, GSM_BYTES);
    cudaFuncSetAttribute(gemm_mma<1, false>, cudaFuncAttributeMaxDynamicSharedMemorySize, GSM_BYTES);
    cudaFuncSetAttribute(gemm_mma<2, false>, cudaFuncAttributeMaxDynamicSharedMemorySize, GSM_BYTES);

    detnsw_kernel<<<1, 256>>>(rmask, sw, pmask, dout + OUT_NSW);
    build_split_kernel<<<BLn + WSPLIT_BLOCKS, 512>>>(sr, rmask, pmask, roles, remb, dout,
                                                     Wq, Wk, Wv, Wo, Wg2, Wg1,
                                                     pWs1, pWso, pWsg2, pWsg1);

    // fused QKV on compacted rows: [Mv x 1536] = Xs([hi|lo], lda=1024) @ Ws1^T
    {
        dim3 grid(1536 / 128, Tn / 128);
        gemm_mma<0, true><<<grid, 256, GSM_BYTES>>>(pXs, pWs1, nullptr, pQKV, nullptr, 1536, 1024, 1536);
    }

    attn_kernel<<<BLn, 256>>>(rmask, pmask, dout);

    // attn_pooled = AOs @ Wso^T  [8192 x 512]
    {
        dim3 grid(512 / 128, BLn / 128);
        gemm_mma<0, false><<<grid, 256, GSM_BYTES>>>(pAOs, pWso, nullptr, dout + OUT_AP, nullptr, 1536, 1024, 512);
    }

    ln_gatein_kernel<<<BLn, 256>>>(dout, ln1g, ln1b);

    // h = gelu(Gs @ Wsg1^T + bg1) -> split bf16 [hi|lo]
    {
        dim3 grid(512 / 128, BLn / 128);
        gemm_mma<1, false><<<grid, 256, GSM_BYTES>>>(pGs, pWsg1, bg1, nullptr, pH1s, 4608, 3072, 0);
    }
    // gate = sigmoid(H1s @ Wsg2^T + bg2)
    {
        dim3 grid(512 / 128, BLn / 128);
        gemm_mma<2, false><<<grid, 256, GSM_BYTES>>>(pH1s, pWsg2, bg2, pGATE, nullptr, 1536, 1024, 0);
    }

    ln_final_kernel<<<BLn, 256>>>(dout, ng, nb);
}

// round 10
// speedup vs baseline: 1.4744x; 1.2995x over previous
#include <cuda_runtime.h>
#include <cuda_fp16.h>
#include <math.h>
#include <stdint.h>

// ---------------- problem constants ----------------
#define Bdim 8
#define Kst 4
#define Lseq 1024
#define Ddim 512
#define Hn 8
#define HDdim 64
#define BLn 8192
#define Tn 32768
#define D3 1536

#define OUT_FUSED 0
#define OUT_AP    4194304
#define OUT_WM    8388608
#define OUT_MF    12582912
#define OUT_AM    16777216
#define OUT_NSW   16809984

// ---------------- device scratch ----------------
// fp16 2-term split: A-side [hi(0:S) | lo(S:2S)], logical K'=2S (direct).
// B-side stores only hi [N x S]; logical second half re-reads hi (index wrap).
// GEMM computes A_hi.B_hi + A_lo.B_hi; dropped A_hi.B_lo ~ 2^-11 rel.
__device__ __half g_Xs[(size_t)Tn * 1024];
__device__ float  g_QKV[(size_t)Tn * 1536];
__device__ __half g_AOs[(size_t)BLn * 1024];
__device__ __half g_Gs[(size_t)BLn * 3072];
__device__ __half g_H1s[(size_t)BLn * 1024];
__device__ float  g_GATE[(size_t)BLn * Ddim];
__device__ __half g_Ws1[1536 * 512];    // [Wq;Wk;Wv] hi
__device__ __half g_Wso[512 * 512];
__device__ __half g_Wsg1[512 * 1536];
__device__ __half g_Wsg2[512 * 512];
__device__ float g_swr[BLn * Kst];
__device__ float g_nsw[Bdim * Kst];
__device__ float g_lognsw[Bdim * Kst];
__device__ int   g_mask_u8;
__device__ int   g_cnt;
__device__ int   g_rowmap[Tn];

// ---------------- helpers ----------------
__device__ __forceinline__ uint32_t smem_u32(const void* p) {
    uint32_t a;
    asm("{ .reg .u64 t; cvta.to.shared.u64 t, %1; cvt.u32.u64 %0, t; }" : "=r"(a) : "l"(p));
    return a;
}
__device__ __forceinline__ void split2h(float v, __half& hi, __half& lo) {
    hi = __float2half_rn(v);
    lo = __float2half_rn(v - __half2float(hi));
}
__device__ __forceinline__ void ldsm_x4(uint32_t& r0, uint32_t& r1, uint32_t& r2,
                                        uint32_t& r3, uint32_t addr) {
    asm volatile("ldmatrix.sync.aligned.m8n8.x4.shared.b16 {%0,%1,%2,%3}, [%4];"
                 : "=r"(r0), "=r"(r1), "=r"(r2), "=r"(r3) : "r"(addr));
}
__device__ __forceinline__ void mma16816(float* c, const uint32_t* a, const uint32_t* b) {
    asm volatile(
        "mma.sync.aligned.m16n8k16.row.col.f32.f16.f16.f32 "
        "{%0,%1,%2,%3}, {%4,%5,%6,%7}, {%8,%9}, {%0,%1,%2,%3};"
        : "+f"(c[0]), "+f"(c[1]), "+f"(c[2]), "+f"(c[3])
        : "r"(a[0]), "r"(a[1]), "r"(a[2]), "r"(a[3]), "r"(b[0]), "r"(b[1]));
}
__device__ __forceinline__ uint32_t swz(uint32_t off) {
    return off ^ ((off >> 3) & 0x70);
}
__device__ __forceinline__ void cp_async16(uint32_t dst, const void* src) {
    asm volatile("cp.async.cg.shared.global [%0], [%1], 16;" :: "r"(dst), "l"(src));
}
__device__ __forceinline__ bool mask_at(const void* p, int idx, int u8) {
    return u8 ? (((const unsigned char*)p)[idx] != 0) : (((const int*)p)[idx] != 0);
}

// ---------------- fused mask-detect + nsw ----------------
__global__ void detnsw_kernel(const void* __restrict__ rm, const float* __restrict__ sw,
                              const void* __restrict__ pm, float* __restrict__ out_nsw) {
    __shared__ int s_u8;
    const int* p = (const int*)rm;
    int bad = 0;
    for (int i = threadIdx.x; i < 8192; i += 256) {
        int v = p[i];
        if (v != 0 && v != 1) bad = 1;
    }
    bad = __syncthreads_or(bad);
    if (threadIdx.x == 0) {
        g_mask_u8 = bad;
        g_cnt = 0;
        s_u8 = bad;
    }
    __syncthreads();
    int b = threadIdx.x;
    if (b >= Bdim) return;
    int u8 = s_u8;
    float w[Kst], pres[Kst];
    float denom = 0.f, psum = 0.f;
#pragma unroll
    for (int k = 0; k < Kst; k++) {
        pres[k] = mask_at(pm, b * Kst + k, u8) ? 1.f : 0.f;
        w[k] = sw[b * Kst + k] * pres[k];
        denom += w[k];
        psum += pres[k];
    }
#pragma unroll
    for (int k = 0; k < Kst; k++) {
        float nswk = (denom > 1e-8f) ? (w[k] / fmaxf(denom, 1e-8f))
                                     : (pres[k] / fmaxf(psum, 1.f));
        g_nsw[b * Kst + k] = nswk;
        g_lognsw[b * Kst + k] = logf(fmaxf(nswk, 1e-8f));
        out_nsw[b * Kst + k] = nswk;
    }
}

// ---------------- fused build-x + weight convert ----------------
// blocks [0, 8192): build split-x (compacted [hi|lo]), weighted_mean, max_feat, swr.
// blocks [8192, 8192+4096): weight fp32->fp16 hi convert, 2,097,152 elements.
#define WSPLIT_BLOCKS 4096

__global__ void __launch_bounds__(512) build_split_kernel(
    const float* __restrict__ sr, const void* __restrict__ rm,
    const void* __restrict__ pm, const int* __restrict__ roles,
    const float* __restrict__ remb, float* __restrict__ dout,
    const float* __restrict__ Wq, const float* __restrict__ Wk,
    const float* __restrict__ Wv, const float* __restrict__ Wo,
    const float* __restrict__ Wg2, const float* __restrict__ Wg1,
    __half* __restrict__ oWs1, __half* __restrict__ oWso,
    __half* __restrict__ oWsg2, __half* __restrict__ oWsg1) {
    if (blockIdx.x >= BLn) {
        int idx = (blockIdx.x - BLn) * 512 + threadIdx.x;
        const float* W;
        __half* out;
        int e;
        if (idx < 262144)        { W = Wq;  out = oWs1;                      e = idx; }
        else if (idx < 524288)   { W = Wk;  out = oWs1 + (size_t)512 * 512;  e = idx - 262144; }
        else if (idx < 786432)   { W = Wv;  out = oWs1 + (size_t)1024 * 512; e = idx - 524288; }
        else if (idx < 1048576)  { W = Wo;  out = oWso;                      e = idx - 786432; }
        else if (idx < 1310720)  { W = Wg2; out = oWsg2;                     e = idx - 1048576; }
        else                     { W = Wg1; out = oWsg1;                     e = idx - 1310720; }
        out[e] = __float2half_rn(W[e]);
        return;
    }
    // ---- build-x path ----
    int bl = blockIdx.x;
    int b = bl >> 10;
    int l = bl & 1023;
    int d = threadIdx.x;
    int u8 = g_mask_u8;
    __shared__ int slots[Kst];

    bool vd[Kst];
    float swr[Kst];
    float ssum = 0.f;
#pragma unroll
    for (int k = 0; k < Kst; k++) {
        bool v = mask_at(rm, (b * Kst + k) * Lseq + l, u8) && mask_at(pm, b * Kst + k, u8);
        vd[k] = v;
        swr[k] = v ? g_nsw[b * Kst + k] : 0.f;
        ssum += swr[k];
    }
    if (d == 0) {
        int nv = 0;
#pragma unroll
        for (int k = 0; k < Kst; k++) nv += vd[k] ? 1 : 0;
        int base = nv ? atomicAdd(&g_cnt, nv) : 0;
#pragma unroll
        for (int k = 0; k < Kst; k++) {
            if (vd[k]) {
                slots[k] = base;
                g_rowmap[base] = bl * Kst + k;
                base++;
            } else slots[k] = -1;
        }
    }
    __syncthreads();
    float inv = 1.f / fmaxf(ssum, 1e-8f);

    float wm = 0.f, mx = -1e9f;
    bool any = false;
#pragma unroll
    for (int k = 0; k < Kst; k++) {
        swr[k] *= inv;
        float xv = 0.f;
        if (vd[k]) {
            int role = max(roles[b * Kst + k], 0);
            xv = sr[(((size_t)(b * Kst + k)) * Lseq + l) * Ddim + d] + remb[role * Ddim + d];
            any = true;
            mx = fmaxf(mx, xv);
            __half hi, lo;
            split2h(xv, hi, lo);
            size_t row = (size_t)slots[k] * 1024;
            g_Xs[row + d] = hi;
            g_Xs[row + 512 + d] = lo;
        }
        wm += swr[k] * xv;
    }
    dout[OUT_WM + (size_t)bl * Ddim + d] = wm;
    dout[OUT_MF + (size_t)bl * Ddim + d] = any ? mx : 0.f;
    if (d < Kst) g_swr[bl * Kst + d] = swr[d];
}

// ---------------- HMMA fp16 GEMM, cp.async 3-stage pipeline, 2 CTAs/SM ----------------
// C[M,N] = A[M,K'] @ B[N,K']^T. CTA tile 128x128; 8 warps 2x4; warp 64x32.
// A physical = logical [hi|lo] (lda=K'). B physical only hi (ldb=K'/2), wrap kc>=ldb.
#define STAGES 3
#define GSM_BYTES (STAGES * 32768)

template <int EPI, bool COMPACT>
__global__ void __launch_bounds__(256, 2) gemm_mma(
    const __half* __restrict__ A, const __half* __restrict__ B,
    const float* __restrict__ bias, float* __restrict__ Cf,
    __half* __restrict__ Cb, int K, int ldb, int ldc) {
    int Mv = 0;
    if (COMPACT) {
        Mv = g_cnt;
        int padded = (Mv + 127) & ~127;
        if ((int)(blockIdx.y * 128) >= padded) return;
    }
    extern __shared__ __align__(1024) char smem[];
    uint32_t sA0 = smem_u32(smem);
    int tid = threadIdx.x;
    int wid = tid >> 5, lane = tid & 31;
    const int wm = wid >> 2, wn = wid & 3;

    const size_t bm = (size_t)blockIdx.y * 128;
    const int bn = blockIdx.x * 128;
    const int seg = tid & 7;
    const int r0 = tid >> 3;

    const __half* Ab = A + (bm + r0) * (size_t)K + seg * 8;
    const __half* Bb = B + (size_t)(bn + r0) * ldb + seg * 8;
    const uint32_t swbase = swz(r0 * 128 + seg * 16);

    auto copy_stage = [&](int c, int buf) {
        int kc = c << 6;
        int bkc = (kc >= ldb) ? kc - ldb : kc;   // B second logical half re-reads hi
        uint32_t pa = sA0 + buf * 32768 + swbase;
#pragma unroll
        for (int i = 0; i < 4; i++) {
            cp_async16(pa + i * 32 * 128, Ab + (size_t)(i * 32) * K + kc);
            cp_async16(pa + 16384 + i * 32 * 128, Bb + (size_t)(i * 32) * ldb + bkc);
        }
        asm volatile("cp.async.commit_group;" ::: "memory");
    };

    float acc[4][4][4];
#pragma unroll
    for (int i = 0; i < 4; i++)
#pragma unroll
        for (int j = 0; j < 4; j++)
#pragma unroll
            for (int q = 0; q < 4; q++) acc[i][j][q] = 0.f;

    const uint32_t aRow = wm * 64 + (lane & 15);
    const uint32_t aColB = (lane >> 4) << 4;
    const uint32_t bRow = wn * 32 + (lane & 7) + ((lane >> 4) << 3);
    const uint32_t bColB = ((lane >> 3) & 1) << 4;

    const int NC = K >> 6;
#pragma unroll
    for (int s = 0; s < STAGES - 1; s++)
        if (s < NC) copy_stage(s, s);

    for (int c = 0; c < NC; c++) {
        asm volatile("cp.async.wait_group %0;" :: "n"(STAGES - 2));
        __syncthreads();
        if (c + STAGES - 1 < NC) copy_stage(c + STAGES - 1, (c + STAGES - 1) % STAGES);

        uint32_t Abuf = sA0 + (c % STAGES) * 32768;
        uint32_t Bbuf = Abuf + 16384;
#pragma unroll
        for (int ks = 0; ks < 4; ks++) {
            uint32_t a[4][4], b[4][2];
#pragma unroll
            for (int mt = 0; mt < 4; mt++) {
                uint32_t off = (aRow + mt * 16) * 128 + ks * 32 + aColB;
                ldsm_x4(a[mt][0], a[mt][1], a[mt][2], a[mt][3], Abuf + swz(off));
            }
#pragma unroll
            for (int p = 0; p < 2; p++) {
                uint32_t off = (bRow + p * 16) * 128 + ks * 32 + bColB;
                ldsm_x4(b[2 * p][0], b[2 * p][1], b[2 * p + 1][0], b[2 * p + 1][1],
                        Bbuf + swz(off));
            }
#pragma unroll
            for (int mt = 0; mt < 4; mt++)
#pragma unroll
                for (int nt = 0; nt < 4; nt++)
                    mma16816(acc[mt][nt], a[mt], b[nt]);
        }
    }

    // epilogue
    const int g = lane >> 2, t = lane & 3;
#pragma unroll
    for (int mt = 0; mt < 4; mt++) {
#pragma unroll
        for (int half = 0; half < 2; half++) {
            size_t grow = bm + wm * 64 + mt * 16 + g + half * 8;
            size_t orow = grow;
            if (COMPACT) {
                if ((int)grow >= Mv) continue;
                orow = (size_t)g_rowmap[grow];
            }
#pragma unroll
            for (int nt = 0; nt < 4; nt++) {
                int col = bn + wn * 32 + nt * 8 + t * 2;
                float v0 = acc[mt][nt][half * 2 + 0];
                float v1 = acc[mt][nt][half * 2 + 1];
                if (EPI == 0) {
                    float2 o = make_float2(v0, v1);
                    *(float2*)(Cf + orow * (size_t)ldc + col) = o;
                } else if (EPI == 1) {
                    v0 += bias[col];
                    v1 += bias[col + 1];
                    v0 = 0.5f * v0 * (1.f + erff(v0 * 0.70710678118654752f));
                    v1 = 0.5f * v1 * (1.f + erff(v1 * 0.70710678118654752f));
                    __half h0, l0, h1, l1;
                    split2h(v0, h0, l0);
                    split2h(v1, h1, l1);
                    size_t o = orow * 1024 + col;
                    *(__half2*)(Cb + o)       = __halves2half2(h0, h1);
                    *(__half2*)(Cb + o + 512) = __halves2half2(l0, l1);
                } else {
                    v0 += bias[col];
                    v1 += bias[col + 1];
                    float2 o;
                    o.x = 1.f / (1.f + __expf(-v0));
                    o.y = 1.f / (1.f + __expf(-v1));
                    *(float2*)(Cf + orow * 512 + col) = o;
                }
            }
        }
    }
}

// ---------------- attention: 4x4 per (b,l,h); pooled split output + attn_mean ----------------
__global__ void __launch_bounds__(256) attn_kernel(
    const void* __restrict__ rm, const void* __restrict__ pm,
    float* __restrict__ dout) {
    int bl = blockIdx.x;
    int b = bl >> 10;
    int l = bl & 1023;
    int warp = threadIdx.x >> 5;
    int lane = threadIdx.x & 31;
    __shared__ float am[Kst];
    if (threadIdx.x < Kst) am[threadIdx.x] = 0.f;
    __syncthreads();
    int u8 = g_mask_u8;

    float2 q[Kst], kk[Kst], vv[Kst];
    float ln_w[Kst], swr[Kst];
    bool vd[Kst];
    int col = warp * HDdim + lane * 2;
#pragma unroll
    for (int s = 0; s < Kst; s++) {
        vd[s] = mask_at(rm, (b * Kst + s) * Lseq + l, u8) && mask_at(pm, b * Kst + s, u8);
        if (vd[s]) {
            size_t rbase = (size_t)(bl * Kst + s) * 1536 + col;
            q[s]  = *(const float2*)(g_QKV + rbase);
            kk[s] = *(const float2*)(g_QKV + rbase + 512);
            vv[s] = *(const float2*)(g_QKV + rbase + 1024);
        } else {
            q[s] = kk[s] = vv[s] = make_float2(0.f, 0.f);
        }
        ln_w[s] = g_lognsw[b * Kst + s];
        swr[s]  = g_swr[bl * Kst + s];
    }

    float dot[Kst][Kst];
#pragma unroll
    for (int i = 0; i < Kst; i++) {
#pragma unroll
        for (int j = 0; j < Kst; j++) {
            float p = q[i].x * kk[j].x + q[i].y * kk[j].y;
#pragma unroll
            for (int o = 16; o; o >>= 1) p += __shfl_xor_sync(0xffffffffu, p, o);
            dot[i][j] = p;
        }
    }

    float a[Kst][Kst];
#pragma unroll
    for (int i = 0; i < Kst; i++) {
        float lm[Kst] = {0.f, 0.f, 0.f, 0.f};
        float m = -3.4e38f;
#pragma unroll
        for (int j = 0; j < Kst; j++) {
            if (vd[j]) {
                lm[j] = dot[i][j] * 0.125f + ln_w[j];
                m = fmaxf(m, lm[j]);
            }
        }
        float ssum = 0.f;
#pragma unroll
        for (int j = 0; j < Kst; j++) {
            float e = vd[j] ? __expf(lm[j] - m) : 0.f;
            a[i][j] = e;
            ssum += e;
        }
        float invs = (ssum > 0.f) ? (1.f / ssum) : 0.f;
#pragma unroll
        for (int j = 0; j < Kst; j++) a[i][j] *= invs;
    }

    float px = 0.f, py = 0.f;
#pragma unroll
    for (int i = 0; i < Kst; i++) {
        float ox = 0.f, oy = 0.f;
#pragma unroll
        for (int j = 0; j < Kst; j++) {
            ox += a[i][j] * vv[j].x;
            oy += a[i][j] * vv[j].y;
        }
        px += swr[i] * ox;
        py += swr[i] * oy;
    }
    __half hx, lx, hy, ly;
    split2h(px, hx, lx);
    split2h(py, hy, ly);
    size_t ob = (size_t)bl * 1024 + col;
    *(__half2*)(g_AOs + ob)       = __halves2half2(hx, hy);
    *(__half2*)(g_AOs + ob + 512) = __halves2half2(lx, ly);

    if (lane == 0) {
#pragma unroll
        for (int j = 0; j < Kst; j++)
            atomicAdd(&am[j], a[0][j] + a[1][j] + a[2][j] + a[3][j]);
    }
    __syncthreads();
    if (threadIdx.x < Kst)
        dout[OUT_AM + (size_t)bl * Kst + threadIdx.x] = am[threadIdx.x] * (1.f / 32.f);
}

// ---------------- block reduction ----------------
__device__ __forceinline__ float block_sum(float v, float* red) {
    int lane = threadIdx.x & 31, w = threadIdx.x >> 5;
#pragma unroll
    for (int o = 16; o; o >>= 1) v += __shfl_xor_sync(0xffffffffu, v, o);
    __syncthreads();
    if (lane == 0) red[w] = v;
    __syncthreads();
    if (threadIdx.x == 0) {
        float t = 0.f;
        int nw = (blockDim.x + 31) >> 5;
        for (int i = 0; i < nw; i++) t += red[i];
        red[8] = t;
    }
    __syncthreads();
    return red[8];
}

// ---------------- layernorm of gate_in (1536) -> split fp16 [hi|lo] ----------------
__global__ void __launch_bounds__(256) ln_gatein_kernel(
    const float* __restrict__ dro, const float* __restrict__ g,
    const float* __restrict__ bb) {
    int bl = blockIdx.x;
    __shared__ float buf[D3];
    __shared__ float red[9];
    float s = 0.f;
    for (int c = threadIdx.x; c < D3; c += 256) {
        float v;
        if (c < Ddim)          v = dro[OUT_AP + (size_t)bl * Ddim + c];
        else if (c < 2 * Ddim) v = dro[OUT_WM + (size_t)bl * Ddim + (c - Ddim)];
        else                   v = dro[OUT_MF + (size_t)bl * Ddim + (c - 2 * Ddim)];
        buf[c] = v;
        s += v;
    }
    s = block_sum(s, red);
    float mu = s * (1.f / D3);
    float sq = 0.f;
    for (int c = threadIdx.x; c < D3; c += 256) {
        float d = buf[c] - mu;
        sq += d * d;
    }
    sq = block_sum(sq, red);
    float rs = rsqrtf(sq * (1.f / D3) + 1e-5f);
    for (int c = threadIdx.x; c < D3; c += 256) {
        float y = (buf[c] - mu) * rs * g[c] + bb[c];
        __half hi, lo;
        split2h(y, hi, lo);
        size_t row = (size_t)bl * 3072;
        g_Gs[row + c] = hi;
        g_Gs[row + 1536 + c] = lo;
    }
}

// ---------------- final fuse + layernorm(512) ----------------
__global__ void __launch_bounds__(256) ln_final_kernel(
    float* __restrict__ dout, const float* __restrict__ ng,
    const float* __restrict__ nb) {
    int bl = blockIdx.x;
    __shared__ float buf[Ddim];
    __shared__ float red[9];
    float s = 0.f;
    for (int d = threadIdx.x; d < Ddim; d += 256) {
        float gate = g_GATE[(size_t)bl * Ddim + d];
        float ap = dout[OUT_AP + (size_t)bl * Ddim + d];
        float wm = dout[OUT_WM + (size_t)bl * Ddim + d];
        float mf = dout[OUT_MF + (size_t)bl * Ddim + d];
        float y = gate * 0.5f * (ap + wm) + (1.f - gate) * mf + wm;
        buf[d] = y;
        s += y;
    }
    s = block_sum(s, red);
    float mu = s * (1.f / Ddim);
    float sq = 0.f;
    for (int d = threadIdx.x; d < Ddim; d += 256) {
        float dd = buf[d] - mu;
        sq += dd * dd;
    }
    sq = block_sum(sq, red);
    float rs = rsqrtf(sq * (1.f / Ddim) + 1e-5f);
    for (int d = threadIdx.x; d < Ddim; d += 256)
        dout[OUT_FUSED + (size_t)bl * Ddim + d] = (buf[d] - mu) * rs * ng[d] + nb[d];
}

// ---------------- launch ----------------
extern "C" void kernel_launch(void* const* d_in, const int* in_sizes, int n_in,
                              void* d_out, int out_size) {
    const float* sr    = (const float*)d_in[0];
    const void*  rmask = d_in[1];
    const float* sw    = (const float*)d_in[2];
    const int*   roles = (const int*)d_in[3];
    const void*  pmask = d_in[4];
    const float* remb  = (const float*)d_in[5];
    const float* Wq    = (const float*)d_in[6];
    const float* Wk    = (const float*)d_in[7];
    const float* Wv    = (const float*)d_in[8];
    const float* Wo    = (const float*)d_in[9];
    const float* ln1g  = (const float*)d_in[10];
    const float* ln1b  = (const float*)d_in[11];
    const float* Wg1   = (const float*)d_in[12];
    const float* bg1   = (const float*)d_in[13];
    const float* Wg2   = (const float*)d_in[14];
    const float* bg2   = (const float*)d_in[15];
    const float* ng    = (const float*)d_in[16];
    const float* nb    = (const float*)d_in[17];
    float* dout = (float*)d_out;

    __half *pXs, *pAOs, *pGs, *pH1s, *pWs1, *pWso, *pWsg1, *pWsg2;
    float *pQKV, *pGATE;
    cudaGetSymbolAddress((void**)&pXs, g_Xs);
    cudaGetSymbolAddress((void**)&pQKV, g_QKV);
    cudaGetSymbolAddress((void**)&pAOs, g_AOs);
    cudaGetSymbolAddress((void**)&pGs, g_Gs);
    cudaGetSymbolAddress((void**)&pH1s, g_H1s);
    cudaGetSymbolAddress((void**)&pGATE, g_GATE);
    cudaGetSymbolAddress((void**)&pWs1, g_Ws1);
    cudaGetSymbolAddress((void**)&pWso, g_Wso);
    cudaGetSymbolAddress((void**)&pWsg1, g_Wsg1);
    cudaGetSymbolAddress((void**)&pWsg2, g_Wsg2);

    cudaFuncSetAttribute(gemm_mma<0, true>,  cudaFuncAttributeMaxDynamicSharedMemorySize, GSM_BYTES);
    cudaFuncSetAttribute(gemm_mma<0, false>, cudaFuncAttributeMaxDynamicSharedMemorySize, GSM_BYTES);
    cudaFuncSetAttribute(gemm_mma<1, false>, cudaFuncAttributeMaxDynamicSharedMemorySize, GSM_BYTES);
    cudaFuncSetAttribute(gemm_mma<2, false>, cudaFuncAttributeMaxDynamicSharedMemorySize, GSM_BYTES);

    detnsw_kernel<<<1, 256>>>(rmask, sw, pmask, dout + OUT_NSW);
    build_split_kernel<<<BLn + WSPLIT_BLOCKS, 512>>>(sr, rmask, pmask, roles, remb, dout,
                                                     Wq, Wk, Wv, Wo, Wg2, Wg1,
                                                     pWs1, pWso, pWsg2, pWsg1);

    // fused QKV on compacted rows: [Mv x 1536] = Xs([hi|lo], K'=1024) @ Ws1(hi, ldb=512)^T
    {
        dim3 grid(1536 / 128, Tn / 128);
        gemm_mma<0, true><<<grid, 256, GSM_BYTES>>>(pXs, pWs1, nullptr, pQKV, nullptr, 1024, 512, 1536);
    }

    attn_kernel<<<BLn, 256>>>(rmask, pmask, dout);

    // attn_pooled = AOs @ Wso^T  [8192 x 512]
    {
        dim3 grid(512 / 128, BLn / 128);
        gemm_mma<0, false><<<grid, 256, GSM_BYTES>>>(pAOs, pWso, nullptr, dout + OUT_AP, nullptr, 1024, 512, 512);
    }

    ln_gatein_kernel<<<BLn, 256>>>(dout, ln1g, ln1b);

    // h = gelu(Gs @ Wsg1^T + bg1) -> split fp16 [hi|lo]
    {
        dim3 grid(512 / 128, BLn / 128);
        gemm_mma<1, false><<<grid, 256, GSM_BYTES>>>(pGs, pWsg1, bg1, nullptr, pH1s, 3072, 1536, 0);
    }
    // gate = sigmoid(H1s @ Wsg2^T + bg2)
    {
        dim3 grid(512 / 128, BLn / 128);
        gemm_mma<2, false><<<grid, 256, GSM_BYTES>>>(pH1s, pWsg2, bg2, pGATE, nullptr, 1024, 512, 0);
    }

    ln_final_kernel<<<BLn, 256>>>(dout, ng, nb);
}

// round 11
// speedup vs baseline: 1.5255x; 1.0347x over previous
#include <cuda_runtime.h>
#include <cuda_fp16.h>
#include <math.h>
#include <stdint.h>

// ---------------- problem constants ----------------
#define Bdim 8
#define Kst 4
#define Lseq 1024
#define Ddim 512
#define Hn 8
#define HDdim 64
#define BLn 8192
#define Tn 32768
#define D3 1536

#define OUT_FUSED 0
#define OUT_AP    4194304
#define OUT_WM    8388608
#define OUT_MF    12582912
#define OUT_AM    16777216
#define OUT_NSW   16809984

// ---------------- device scratch ----------------
// fp16 2-term split: A-side [hi(0:S) | lo(S:2S)], logical K'=2S.
// B-side stores only hi [N x S]; logical second half re-reads hi (index wrap).
__device__ __half g_Xs[(size_t)Tn * 1024];
__device__ float  g_QKV[(size_t)Tn * 1536];
__device__ __half g_AOs[(size_t)BLn * 1024];
__device__ __half g_Gs[(size_t)BLn * 3072];
__device__ __half g_H1s[(size_t)BLn * 1024];
__device__ float  g_GATE[(size_t)BLn * Ddim];
__device__ __half g_Ws1[1536 * 512];
__device__ __half g_Wso[512 * 512];
__device__ __half g_Wsg1[512 * 1536];
__device__ __half g_Wsg2[512 * 512];
__device__ float g_swr[BLn * Kst];
__device__ float g_nsw[Bdim * Kst];
__device__ float g_lognsw[Bdim * Kst];
__device__ int   g_mask_u8;
__device__ int   g_cnt;
__device__ int   g_rowmap[Tn];

// ---------------- helpers ----------------
__device__ __forceinline__ uint32_t smem_u32(const void* p) {
    uint32_t a;
    asm("{ .reg .u64 t; cvta.to.shared.u64 t, %1; cvt.u32.u64 %0, t; }" : "=r"(a) : "l"(p));
    return a;
}
__device__ __forceinline__ void split2h(float v, __half& hi, __half& lo) {
    hi = __float2half_rn(v);
    lo = __float2half_rn(v - __half2float(hi));
}
__device__ __forceinline__ void ldsm_x4(uint32_t& r0, uint32_t& r1, uint32_t& r2,
                                        uint32_t& r3, uint32_t addr) {
    asm volatile("ldmatrix.sync.aligned.m8n8.x4.shared.b16 {%0,%1,%2,%3}, [%4];"
                 : "=r"(r0), "=r"(r1), "=r"(r2), "=r"(r3) : "r"(addr));
}
__device__ __forceinline__ void mma16816(float* c, const uint32_t* a, const uint32_t* b) {
    asm volatile(
        "mma.sync.aligned.m16n8k16.row.col.f32.f16.f16.f32 "
        "{%0,%1,%2,%3}, {%4,%5,%6,%7}, {%8,%9}, {%0,%1,%2,%3};"
        : "+f"(c[0]), "+f"(c[1]), "+f"(c[2]), "+f"(c[3])
        : "r"(a[0]), "r"(a[1]), "r"(a[2]), "r"(a[3]), "r"(b[0]), "r"(b[1]));
}
__device__ __forceinline__ uint32_t swz(uint32_t off) {
    return off ^ ((off >> 3) & 0x70);
}
__device__ __forceinline__ void cp_async16(uint32_t dst, const void* src) {
    asm volatile("cp.async.cg.shared.global [%0], [%1], 16;" :: "r"(dst), "l"(src));
}
__device__ __forceinline__ bool mask_at(const void* p, int idx, int u8) {
    return u8 ? (((const unsigned char*)p)[idx] != 0) : (((const int*)p)[idx] != 0);
}
__device__ __forceinline__ float dot4(float4 a, float4 b) {
    return a.x * b.x + a.y * b.y + a.z * b.z + a.w * b.w;
}

// ---------------- fused mask-detect + nsw ----------------
__global__ void detnsw_kernel(const void* __restrict__ rm, const float* __restrict__ sw,
                              const void* __restrict__ pm, float* __restrict__ out_nsw) {
    __shared__ int s_u8;
    const int* p = (const int*)rm;
    int bad = 0;
    for (int i = threadIdx.x; i < 8192; i += 256) {
        int v = p[i];
        if (v != 0 && v != 1) bad = 1;
    }
    bad = __syncthreads_or(bad);
    if (threadIdx.x == 0) {
        g_mask_u8 = bad;
        g_cnt = 0;
        s_u8 = bad;
    }
    __syncthreads();
    int b = threadIdx.x;
    if (b >= Bdim) return;
    int u8 = s_u8;
    float w[Kst], pres[Kst];
    float denom = 0.f, psum = 0.f;
#pragma unroll
    for (int k = 0; k < Kst; k++) {
        pres[k] = mask_at(pm, b * Kst + k, u8) ? 1.f : 0.f;
        w[k] = sw[b * Kst + k] * pres[k];
        denom += w[k];
        psum += pres[k];
    }
#pragma unroll
    for (int k = 0; k < Kst; k++) {
        float nswk = (denom > 1e-8f) ? (w[k] / fmaxf(denom, 1e-8f))
                                     : (pres[k] / fmaxf(psum, 1.f));
        g_nsw[b * Kst + k] = nswk;
        g_lognsw[b * Kst + k] = logf(fmaxf(nswk, 1e-8f));
        out_nsw[b * Kst + k] = nswk;
    }
}

// ---------------- fused build-x + weight convert (blockDim 128) ----------------
// blocks [0, 8192): build split-x (float4 path, 4 dims/thread).
// blocks [8192, 8192+16384): weight fp32->fp16 convert, 2,097,152 elements.
#define WSPLIT_BLOCKS 16384

__global__ void __launch_bounds__(128) build_split_kernel(
    const float* __restrict__ sr, const void* __restrict__ rm,
    const void* __restrict__ pm, const int* __restrict__ roles,
    const float* __restrict__ remb, float* __restrict__ dout,
    const float* __restrict__ Wq, const float* __restrict__ Wk,
    const float* __restrict__ Wv, const float* __restrict__ Wo,
    const float* __restrict__ Wg2, const float* __restrict__ Wg1,
    __half* __restrict__ oWs1, __half* __restrict__ oWso,
    __half* __restrict__ oWsg2, __half* __restrict__ oWsg1) {
    if (blockIdx.x >= BLn) {
        int idx = (blockIdx.x - BLn) * 128 + threadIdx.x;
        const float* W;
        __half* out;
        int e;
        if (idx < 262144)        { W = Wq;  out = oWs1;                      e = idx; }
        else if (idx < 524288)   { W = Wk;  out = oWs1 + (size_t)512 * 512;  e = idx - 262144; }
        else if (idx < 786432)   { W = Wv;  out = oWs1 + (size_t)1024 * 512; e = idx - 524288; }
        else if (idx < 1048576)  { W = Wo;  out = oWso;                      e = idx - 786432; }
        else if (idx < 1310720)  { W = Wg2; out = oWsg2;                     e = idx - 1048576; }
        else                     { W = Wg1; out = oWsg1;                     e = idx - 1310720; }
        out[e] = __float2half_rn(W[e]);
        return;
    }
    // ---- build-x path: 128 threads x 4 dims ----
    int bl = blockIdx.x;
    int b = bl >> 10;
    int l = bl & 1023;
    int t = threadIdx.x;
    int d0 = t * 4;
    int u8 = g_mask_u8;
    __shared__ int slots[Kst];

    bool vd[Kst];
    float swr[Kst];
    float ssum = 0.f;
#pragma unroll
    for (int k = 0; k < Kst; k++) {
        bool v = mask_at(rm, (b * Kst + k) * Lseq + l, u8) && mask_at(pm, b * Kst + k, u8);
        vd[k] = v;
        swr[k] = v ? g_nsw[b * Kst + k] : 0.f;
        ssum += swr[k];
    }
    if (t == 0) {
        int nv = 0;
#pragma unroll
        for (int k = 0; k < Kst; k++) nv += vd[k] ? 1 : 0;
        int base = nv ? atomicAdd(&g_cnt, nv) : 0;
#pragma unroll
        for (int k = 0; k < Kst; k++) {
            if (vd[k]) {
                slots[k] = base;
                g_rowmap[base] = bl * Kst + k;
                base++;
            } else slots[k] = -1;
        }
    }
    __syncthreads();
    float inv = 1.f / fmaxf(ssum, 1e-8f);

    float4 wm = make_float4(0.f, 0.f, 0.f, 0.f);
    float4 mx = make_float4(-1e9f, -1e9f, -1e9f, -1e9f);
    bool any = false;
#pragma unroll
    for (int k = 0; k < Kst; k++) {
        swr[k] *= inv;
        if (vd[k]) {
            int role = max(roles[b * Kst + k], 0);
            float4 s4 = *(const float4*)(sr + (((size_t)(b * Kst + k)) * Lseq + l) * Ddim + d0);
            float4 r4 = *(const float4*)(remb + (size_t)role * Ddim + d0);
            float4 xv = make_float4(s4.x + r4.x, s4.y + r4.y, s4.z + r4.z, s4.w + r4.w);
            any = true;
            mx.x = fmaxf(mx.x, xv.x); mx.y = fmaxf(mx.y, xv.y);
            mx.z = fmaxf(mx.z, xv.z); mx.w = fmaxf(mx.w, xv.w);
            __half h0, l0, h1, l1, h2, l2, h3, l3;
            split2h(xv.x, h0, l0); split2h(xv.y, h1, l1);
            split2h(xv.z, h2, l2); split2h(xv.w, h3, l3);
            size_t row = (size_t)slots[k] * 1024;
            *(__half2*)(g_Xs + row + d0)           = __halves2half2(h0, h1);
            *(__half2*)(g_Xs + row + d0 + 2)       = __halves2half2(h2, h3);
            *(__half2*)(g_Xs + row + 512 + d0)     = __halves2half2(l0, l1);
            *(__half2*)(g_Xs + row + 512 + d0 + 2) = __halves2half2(l2, l3);
            wm.x += swr[k] * xv.x; wm.y += swr[k] * xv.y;
            wm.z += swr[k] * xv.z; wm.w += swr[k] * xv.w;
        }
    }
    *(float4*)(dout + OUT_WM + (size_t)bl * Ddim + d0) = wm;
    if (!any) mx = make_float4(0.f, 0.f, 0.f, 0.f);
    *(float4*)(dout + OUT_MF + (size_t)bl * Ddim + d0) = mx;
    if (t < Kst) g_swr[bl * Kst + t] = swr[t];
}

// ---------------- HMMA fp16 GEMM, cp.async 3-stage pipeline, 2 CTAs/SM ----------------
#define STAGES 3
#define GSM_BYTES (STAGES * 32768)

template <int EPI, bool COMPACT>
__global__ void __launch_bounds__(256, 2) gemm_mma(
    const __half* __restrict__ A, const __half* __restrict__ B,
    const float* __restrict__ bias, float* __restrict__ Cf,
    __half* __restrict__ Cb, int K, int ldb, int ldc) {
    int Mv = 0;
    if (COMPACT) {
        Mv = g_cnt;
        int padded = (Mv + 127) & ~127;
        if ((int)(blockIdx.y * 128) >= padded) return;
    }
    extern __shared__ __align__(1024) char smem[];
    uint32_t sA0 = smem_u32(smem);
    int tid = threadIdx.x;
    int wid = tid >> 5, lane = tid & 31;
    const int wm = wid >> 2, wn = wid & 3;

    const size_t bm = (size_t)blockIdx.y * 128;
    const int bn = blockIdx.x * 128;
    const int seg = tid & 7;
    const int r0 = tid >> 3;

    const __half* Ab = A + (bm + r0) * (size_t)K + seg * 8;
    const __half* Bb = B + (size_t)(bn + r0) * ldb + seg * 8;
    const uint32_t swbase = swz(r0 * 128 + seg * 16);

    auto copy_stage = [&](int c, int buf) {
        int kc = c << 6;
        int bkc = (kc >= ldb) ? kc - ldb : kc;
        uint32_t pa = sA0 + buf * 32768 + swbase;
#pragma unroll
        for (int i = 0; i < 4; i++) {
            cp_async16(pa + i * 32 * 128, Ab + (size_t)(i * 32) * K + kc);
            cp_async16(pa + 16384 + i * 32 * 128, Bb + (size_t)(i * 32) * ldb + bkc);
        }
        asm volatile("cp.async.commit_group;" ::: "memory");
    };

    float acc[4][4][4];
#pragma unroll
    for (int i = 0; i < 4; i++)
#pragma unroll
        for (int j = 0; j < 4; j++)
#pragma unroll
            for (int q = 0; q < 4; q++) acc[i][j][q] = 0.f;

    const uint32_t aRow = wm * 64 + (lane & 15);
    const uint32_t aColB = (lane >> 4) << 4;
    const uint32_t bRow = wn * 32 + (lane & 7) + ((lane >> 4) << 3);
    const uint32_t bColB = ((lane >> 3) & 1) << 4;

    const int NC = K >> 6;
#pragma unroll
    for (int s = 0; s < STAGES - 1; s++)
        if (s < NC) copy_stage(s, s);

    for (int c = 0; c < NC; c++) {
        asm volatile("cp.async.wait_group %0;" :: "n"(STAGES - 2));
        __syncthreads();
        if (c + STAGES - 1 < NC) copy_stage(c + STAGES - 1, (c + STAGES - 1) % STAGES);

        uint32_t Abuf = sA0 + (c % STAGES) * 32768;
        uint32_t Bbuf = Abuf + 16384;
#pragma unroll
        for (int ks = 0; ks < 4; ks++) {
            uint32_t a[4][4], b[4][2];
#pragma unroll
            for (int mt = 0; mt < 4; mt++) {
                uint32_t off = (aRow + mt * 16) * 128 + ks * 32 + aColB;
                ldsm_x4(a[mt][0], a[mt][1], a[mt][2], a[mt][3], Abuf + swz(off));
            }
#pragma unroll
            for (int p = 0; p < 2; p++) {
                uint32_t off = (bRow + p * 16) * 128 + ks * 32 + bColB;
                ldsm_x4(b[2 * p][0], b[2 * p][1], b[2 * p + 1][0], b[2 * p + 1][1],
                        Bbuf + swz(off));
            }
#pragma unroll
            for (int mt = 0; mt < 4; mt++)
#pragma unroll
                for (int nt = 0; nt < 4; nt++)
                    mma16816(acc[mt][nt], a[mt], b[nt]);
        }
    }

    // epilogue
    const int g = lane >> 2, t = lane & 3;
#pragma unroll
    for (int mt = 0; mt < 4; mt++) {
#pragma unroll
        for (int half = 0; half < 2; half++) {
            size_t grow = bm + wm * 64 + mt * 16 + g + half * 8;
            size_t orow = grow;
            if (COMPACT) {
                if ((int)grow >= Mv) continue;
                orow = (size_t)g_rowmap[grow];
            }
#pragma unroll
            for (int nt = 0; nt < 4; nt++) {
                int col = bn + wn * 32 + nt * 8 + t * 2;
                float v0 = acc[mt][nt][half * 2 + 0];
                float v1 = acc[mt][nt][half * 2 + 1];
                if (EPI == 0) {
                    float2 o = make_float2(v0, v1);
                    *(float2*)(Cf + orow * (size_t)ldc + col) = o;
                } else if (EPI == 1) {
                    v0 += bias[col];
                    v1 += bias[col + 1];
                    v0 = 0.5f * v0 * (1.f + erff(v0 * 0.70710678118654752f));
                    v1 = 0.5f * v1 * (1.f + erff(v1 * 0.70710678118654752f));
                    __half h0, l0, h1, l1;
                    split2h(v0, h0, l0);
                    split2h(v1, h1, l1);
                    size_t o = orow * 1024 + col;
                    *(__half2*)(Cb + o)       = __halves2half2(h0, h1);
                    *(__half2*)(Cb + o + 512) = __halves2half2(l0, l1);
                } else {
                    v0 += bias[col];
                    v1 += bias[col + 1];
                    float2 o;
                    o.x = 1.f / (1.f + __expf(-v0));
                    o.y = 1.f / (1.f + __expf(-v1));
                    *(float2*)(Cf + orow * 512 + col) = o;
                }
            }
        }
    }
}

// ---------------- attention: group-dot scheme ----------------
// warp = head. lane: g = lane>>3 (key j = g for partial dots), sl = lane&7 (8 dims).
// Slot order: slot s holds absolute j = g ^ s after the xor-gather.
__global__ void __launch_bounds__(256) attn_kernel(
    const void* __restrict__ rm, const void* __restrict__ pm,
    float* __restrict__ dout) {
    int bl = blockIdx.x;
    int b = bl >> 10;
    int l = bl & 1023;
    int h = threadIdx.x >> 5;
    int lane = threadIdx.x & 31;
    int g = lane >> 3, sl = lane & 7;
    __shared__ float am[Kst];
    if (threadIdx.x < Kst) am[threadIdx.x] = 0.f;
    __syncthreads();
    int u8 = g_mask_u8;

    // absolute valid bits + swr
    int mbits = 0;
    float swr[Kst];
#pragma unroll
    for (int s = 0; s < Kst; s++) {
        bool v = mask_at(rm, (b * Kst + s) * Lseq + l, u8) && mask_at(pm, b * Kst + s, u8);
        mbits |= (v ? 1 : 0) << s;
        swr[s] = g_swr[bl * Kst + s];
    }

    // ---- dots: q_i (all i) x k_g over dims [8sl, 8sl+8) ----
    int dimoff = h * HDdim + sl * 8;
    float4 z4 = make_float4(0.f, 0.f, 0.f, 0.f);
    float4 qa[Kst][2];
#pragma unroll
    for (int i = 0; i < Kst; i++) {
        if ((mbits >> i) & 1) {
            const float* qp = g_QKV + (size_t)(bl * Kst + i) * 1536 + dimoff;
            qa[i][0] = *(const float4*)(qp);
            qa[i][1] = *(const float4*)(qp + 4);
        } else { qa[i][0] = z4; qa[i][1] = z4; }
    }
    float4 ka0 = z4, ka1 = z4;
    if ((mbits >> g) & 1) {
        const float* kp = g_QKV + (size_t)(bl * Kst + g) * 1536 + 512 + dimoff;
        ka0 = *(const float4*)(kp);
        ka1 = *(const float4*)(kp + 4);
    }
    float d[Kst];
#pragma unroll
    for (int i = 0; i < Kst; i++)
        d[i] = dot4(qa[i][0], ka0) + dot4(qa[i][1], ka1);
    // intra-group reduce (8 lanes)
#pragma unroll
    for (int off = 4; off; off >>= 1)
#pragma unroll
        for (int i = 0; i < Kst; i++)
            d[i] += __shfl_xor_sync(0xffffffffu, d[i], off);
    // cross-group gather: ds[s][i] = dot[i][j = g^s]
    float ds[Kst][Kst];
#pragma unroll
    for (int i = 0; i < Kst; i++) {
        ds[0][i] = d[i];
        ds[1][i] = __shfl_xor_sync(0xffffffffu, d[i], 8);
        ds[2][i] = __shfl_xor_sync(0xffffffffu, ds[0][i], 16);
        ds[3][i] = __shfl_xor_sync(0xffffffffu, ds[1][i], 16);
    }

    // per-slot tables (j = g ^ s)
    float lnws[Kst];
    bool vds[Kst];
#pragma unroll
    for (int s = 0; s < Kst; s++) {
        int j = g ^ s;
        lnws[s] = g_lognsw[b * Kst + j];
        vds[s] = (mbits >> j) & 1;
    }

    // softmax per query i over slots
    float a[Kst][Kst];
#pragma unroll
    for (int i = 0; i < Kst; i++) {
        float lm[Kst] = {0.f, 0.f, 0.f, 0.f};
        float m = -3.4e38f;
#pragma unroll
        for (int s = 0; s < Kst; s++) {
            if (vds[s]) {
                lm[s] = ds[s][i] * 0.125f + lnws[s];
                m = fmaxf(m, lm[s]);
            }
        }
        float ssum = 0.f;
#pragma unroll
        for (int s = 0; s < Kst; s++) {
            float e = vds[s] ? __expf(lm[s] - m) : 0.f;
            a[i][s] = e;
            ssum += e;
        }
        float invs = (ssum > 0.f) ? (1.f / ssum) : 0.f;
#pragma unroll
        for (int s = 0; s < Kst; s++) a[i][s] *= invs;
    }

    // pooling: per-lane dims [2*lane, 2*lane+1] within head
    int col = h * HDdim + (lane << 1);
    float2 vv[Kst];
#pragma unroll
    for (int s = 0; s < Kst; s++) {
        int j = g ^ s;
        vv[s] = vds[s] ? *(const float2*)(g_QKV + (size_t)(bl * Kst + j) * 1536 + 1024 + col)
                       : make_float2(0.f, 0.f);
    }
    float px = 0.f, py = 0.f;
#pragma unroll
    for (int i = 0; i < Kst; i++) {
        float ox = 0.f, oy = 0.f;
#pragma unroll
        for (int s = 0; s < Kst; s++) {
            ox += a[i][s] * vv[s].x;
            oy += a[i][s] * vv[s].y;
        }
        px += swr[i] * ox;
        py += swr[i] * oy;
    }
    __half hx, lx, hy, ly;
    split2h(px, hx, lx);
    split2h(py, hy, ly);
    size_t ob = (size_t)bl * 1024 + col;
    *(__half2*)(g_AOs + ob)       = __halves2half2(hx, hy);
    *(__half2*)(g_AOs + ob + 512) = __halves2half2(lx, ly);

    // attn_mean: lane 0 has g=0 so slot s == absolute j
    if (lane == 0) {
#pragma unroll
        for (int s = 0; s < Kst; s++)
            atomicAdd(&am[s], a[0][s] + a[1][s] + a[2][s] + a[3][s]);
    }
    __syncthreads();
    if (threadIdx.x < Kst)
        dout[OUT_AM + (size_t)bl * Kst + threadIdx.x] = am[threadIdx.x] * (1.f / 32.f);
}

// ---------------- block reduction ----------------
__device__ __forceinline__ float block_sum(float v, float* red) {
    int lane = threadIdx.x & 31, w = threadIdx.x >> 5;
#pragma unroll
    for (int o = 16; o; o >>= 1) v += __shfl_xor_sync(0xffffffffu, v, o);
    __syncthreads();
    if (lane == 0) red[w] = v;
    __syncthreads();
    if (threadIdx.x == 0) {
        float t = 0.f;
        int nw = (blockDim.x + 31) >> 5;
        for (int i = 0; i < nw; i++) t += red[i];
        red[8] = t;
    }
    __syncthreads();
    return red[8];
}

// ---------------- layernorm of gate_in (1536) -> split fp16 [hi|lo] ----------------
__global__ void __launch_bounds__(256) ln_gatein_kernel(
    const float* __restrict__ dro, const float* __restrict__ g,
    const float* __restrict__ bb) {
    int bl = blockIdx.x;
    __shared__ float buf[D3];
    __shared__ float red[9];
    float s = 0.f;
    for (int c = threadIdx.x; c < D3; c += 256) {
        float v;
        if (c < Ddim)          v = dro[OUT_AP + (size_t)bl * Ddim + c];
        else if (c < 2 * Ddim) v = dro[OUT_WM + (size_t)bl * Ddim + (c - Ddim)];
        else                   v = dro[OUT_MF + (size_t)bl * Ddim + (c - 2 * Ddim)];
        buf[c] = v;
        s += v;
    }
    s = block_sum(s, red);
    float mu = s * (1.f / D3);
    float sq = 0.f;
    for (int c = threadIdx.x; c < D3; c += 256) {
        float d = buf[c] - mu;
        sq += d * d;
    }
    sq = block_sum(sq, red);
    float rs = rsqrtf(sq * (1.f / D3) + 1e-5f);
    for (int c = threadIdx.x; c < D3; c += 256) {
        float y = (buf[c] - mu) * rs * g[c] + bb[c];
        __half hi, lo;
        split2h(y, hi, lo);
        size_t row = (size_t)bl * 3072;
        g_Gs[row + c] = hi;
        g_Gs[row + 1536 + c] = lo;
    }
}

// ---------------- final fuse + layernorm(512) ----------------
__global__ void __launch_bounds__(256) ln_final_kernel(
    float* __restrict__ dout, const float* __restrict__ ng,
    const float* __restrict__ nb) {
    int bl = blockIdx.x;
    __shared__ float buf[Ddim];
    __shared__ float red[9];
    float s = 0.f;
    for (int d = threadIdx.x; d < Ddim; d += 256) {
        float gate = g_GATE[(size_t)bl * Ddim + d];
        float ap = dout[OUT_AP + (size_t)bl * Ddim + d];
        float wm = dout[OUT_WM + (size_t)bl * Ddim + d];
        float mf = dout[OUT_MF + (size_t)bl * Ddim + d];
        float y = gate * 0.5f * (ap + wm) + (1.f - gate) * mf + wm;
        buf[d] = y;
        s += y;
    }
    s = block_sum(s, red);
    float mu = s * (1.f / Ddim);
    float sq = 0.f;
    for (int d = threadIdx.x; d < Ddim; d += 256) {
        float dd = buf[d] - mu;
        sq += dd * dd;
    }
    sq = block_sum(sq, red);
    float rs = rsqrtf(sq * (1.f / Ddim) + 1e-5f);
    for (int d = threadIdx.x; d < Ddim; d += 256)
        dout[OUT_FUSED + (size_t)bl * Ddim + d] = (buf[d] - mu) * rs * ng[d] + nb[d];
}

// ---------------- launch ----------------
extern "C" void kernel_launch(void* const* d_in, const int* in_sizes, int n_in,
                              void* d_out, int out_size) {
    const float* sr    = (const float*)d_in[0];
    const void*  rmask = d_in[1];
    const float* sw    = (const float*)d_in[2];
    const int*   roles = (const int*)d_in[3];
    const void*  pmask = d_in[4];
    const float* remb  = (const float*)d_in[5];
    const float* Wq    = (const float*)d_in[6];
    const float* Wk    = (const float*)d_in[7];
    const float* Wv    = (const float*)d_in[8];
    const float* Wo    = (const float*)d_in[9];
    const float* ln1g  = (const float*)d_in[10];
    const float* ln1b  = (const float*)d_in[11];
    const float* Wg1   = (const float*)d_in[12];
    const float* bg1   = (const float*)d_in[13];
    const float* Wg2   = (const float*)d_in[14];
    const float* bg2   = (const float*)d_in[15];
    const float* ng    = (const float*)d_in[16];
    const float* nb    = (const float*)d_in[17];
    float* dout = (float*)d_out;

    __half *pXs, *pAOs, *pGs, *pH1s, *pWs1, *pWso, *pWsg1, *pWsg2;
    float *pQKV, *pGATE;
    cudaGetSymbolAddress((void**)&pXs, g_Xs);
    cudaGetSymbolAddress((void**)&pQKV, g_QKV);
    cudaGetSymbolAddress((void**)&pAOs, g_AOs);
    cudaGetSymbolAddress((void**)&pGs, g_Gs);
    cudaGetSymbolAddress((void**)&pH1s, g_H1s);
    cudaGetSymbolAddress((void**)&pGATE, g_GATE);
    cudaGetSymbolAddress((void**)&pWs1, g_Ws1);
    cudaGetSymbolAddress((void**)&pWso, g_Wso);
    cudaGetSymbolAddress((void**)&pWsg1, g_Wsg1);
    cudaGetSymbolAddress((void**)&pWsg2, g_Wsg2);

    cudaFuncSetAttribute(gemm_mma<0, true>,  cudaFuncAttributeMaxDynamicSharedMemorySize, GSM_BYTES);
    cudaFuncSetAttribute(gemm_mma<0, false>, cudaFuncAttributeMaxDynamicSharedMemorySize, GSM_BYTES);
    cudaFuncSetAttribute(gemm_mma<1, false>, cudaFuncAttributeMaxDynamicSharedMemorySize, GSM_BYTES);
    cudaFuncSetAttribute(gemm_mma<2, false>, cudaFuncAttributeMaxDynamicSharedMemorySize, GSM_BYTES);

    detnsw_kernel<<<1, 256>>>(rmask, sw, pmask, dout + OUT_NSW);
    build_split_kernel<<<BLn + WSPLIT_BLOCKS, 128>>>(sr, rmask, pmask, roles, remb, dout,
                                                     Wq, Wk, Wv, Wo, Wg2, Wg1,
                                                     pWs1, pWso, pWsg2, pWsg1);

    // fused QKV on compacted rows: [Mv x 1536] = Xs([hi|lo], K'=1024) @ Ws1(hi, ldb=512)^T
    {
        dim3 grid(1536 / 128, Tn / 128);
        gemm_mma<0, true><<<grid, 256, GSM_BYTES>>>(pXs, pWs1, nullptr, pQKV, nullptr, 1024, 512, 1536);
    }

    attn_kernel<<<BLn, 256>>>(rmask, pmask, dout);

    // attn_pooled = AOs @ Wso^T  [8192 x 512]
    {
        dim3 grid(512 / 128, BLn / 128);
        gemm_mma<0, false><<<grid, 256, GSM_BYTES>>>(pAOs, pWso, nullptr, dout + OUT_AP, nullptr, 1024, 512, 512);
    }

    ln_gatein_kernel<<<BLn, 256>>>(dout, ln1g, ln1b);

    // h = gelu(Gs @ Wsg1^T + bg1) -> split fp16 [hi|lo]
    {
        dim3 grid(512 / 128, BLn / 128);
        gemm_mma<1, false><<<grid, 256, GSM_BYTES>>>(pGs, pWsg1, bg1, nullptr, pH1s, 3072, 1536, 0);
    }
    // gate = sigmoid(H1s @ Wsg2^T + bg2)
    {
        dim3 grid(512 / 128, BLn / 128);
        gemm_mma<2, false><<<grid, 256, GSM_BYTES>>>(pH1s, pWsg2, bg2, pGATE, nullptr, 1024, 512, 0);
    }

    ln_final_kernel<<<BLn, 256>>>(dout, ng, nb);
}

// round 12
// speedup vs baseline: 1.5401x; 1.0096x over previous
#include <cuda_runtime.h>
#include <cuda_fp16.h>
#include <math.h>
#include <stdint.h>

// ---------------- problem constants ----------------
#define Bdim 8
#define Kst 4
#define Lseq 1024
#define Ddim 512
#define Hn 8
#define HDdim 64
#define BLn 8192
#define Tn 32768
#define D3 1536

#define OUT_FUSED 0
#define OUT_AP    4194304
#define OUT_WM    8388608
#define OUT_MF    12582912
#define OUT_AM    16777216
#define OUT_NSW   16809984

// ---------------- device scratch ----------------
// fp16 2-term split: A-side [hi(0:S) | lo(S:2S)], logical K'=2S.
// B-side stores only hi [N x S]; logical second half re-reads hi (index wrap).
__device__ __half g_Xs[(size_t)Tn * 1024];
__device__ float  g_QKV[(size_t)Tn * 1536];
__device__ __half g_AOs[(size_t)BLn * 1024];
__device__ __half g_Gs[(size_t)BLn * 3072];
__device__ __half g_H1s[(size_t)BLn * 1024];
__device__ float  g_GATE[(size_t)BLn * Ddim];
__device__ __half g_Ws1[1536 * 512];
__device__ __half g_Wso[512 * 512];
__device__ __half g_Wsg1[512 * 1536];
__device__ __half g_Wsg2[512 * 512];
__device__ float g_swr[BLn * Kst];
__device__ float g_nsw[Bdim * Kst];
__device__ float g_lognsw[Bdim * Kst];
__device__ int   g_mask_u8;
__device__ int   g_cnt;
__device__ int   g_rowmap[Tn];

// ---------------- helpers ----------------
__device__ __forceinline__ uint32_t smem_u32(const void* p) {
    uint32_t a;
    asm("{ .reg .u64 t; cvta.to.shared.u64 t, %1; cvt.u32.u64 %0, t; }" : "=r"(a) : "l"(p));
    return a;
}
__device__ __forceinline__ void split2h(float v, __half& hi, __half& lo) {
    hi = __float2half_rn(v);
    lo = __float2half_rn(v - __half2float(hi));
}
__device__ __forceinline__ void ldsm_x4(uint32_t& r0, uint32_t& r1, uint32_t& r2,
                                        uint32_t& r3, uint32_t addr) {
    asm volatile("ldmatrix.sync.aligned.m8n8.x4.shared.b16 {%0,%1,%2,%3}, [%4];"
                 : "=r"(r0), "=r"(r1), "=r"(r2), "=r"(r3) : "r"(addr));
}
__device__ __forceinline__ void mma16816(float* c, const uint32_t* a, const uint32_t* b) {
    asm volatile(
        "mma.sync.aligned.m16n8k16.row.col.f32.f16.f16.f32 "
        "{%0,%1,%2,%3}, {%4,%5,%6,%7}, {%8,%9}, {%0,%1,%2,%3};"
        : "+f"(c[0]), "+f"(c[1]), "+f"(c[2]), "+f"(c[3])
        : "r"(a[0]), "r"(a[1]), "r"(a[2]), "r"(a[3]), "r"(b[0]), "r"(b[1]));
}
__device__ __forceinline__ uint32_t swz(uint32_t off) {
    return off ^ ((off >> 3) & 0x70);
}
__device__ __forceinline__ void cp_async16(uint32_t dst, const void* src) {
    asm volatile("cp.async.cg.shared.global [%0], [%1], 16;" :: "r"(dst), "l"(src));
}
__device__ __forceinline__ bool mask_at(const void* p, int idx, int u8) {
    return u8 ? (((const unsigned char*)p)[idx] != 0) : (((const int*)p)[idx] != 0);
}

// ---------------- fused mask-detect + nsw ----------------
__global__ void detnsw_kernel(const void* __restrict__ rm, const float* __restrict__ sw,
                              const void* __restrict__ pm, float* __restrict__ out_nsw) {
    __shared__ int s_u8;
    const int* p = (const int*)rm;
    int bad = 0;
    for (int i = threadIdx.x; i < 8192; i += 256) {
        int v = p[i];
        if (v != 0 && v != 1) bad = 1;
    }
    bad = __syncthreads_or(bad);
    if (threadIdx.x == 0) {
        g_mask_u8 = bad;
        g_cnt = 0;
        s_u8 = bad;
    }
    __syncthreads();
    int b = threadIdx.x;
    if (b >= Bdim) return;
    int u8 = s_u8;
    float w[Kst], pres[Kst];
    float denom = 0.f, psum = 0.f;
#pragma unroll
    for (int k = 0; k < Kst; k++) {
        pres[k] = mask_at(pm, b * Kst + k, u8) ? 1.f : 0.f;
        w[k] = sw[b * Kst + k] * pres[k];
        denom += w[k];
        psum += pres[k];
    }
#pragma unroll
    for (int k = 0; k < Kst; k++) {
        float nswk = (denom > 1e-8f) ? (w[k] / fmaxf(denom, 1e-8f))
                                     : (pres[k] / fmaxf(psum, 1.f));
        g_nsw[b * Kst + k] = nswk;
        g_lognsw[b * Kst + k] = logf(fmaxf(nswk, 1e-8f));
        out_nsw[b * Kst + k] = nswk;
    }
}

// ---------------- fused build-x + weight convert (blockDim 128) ----------------
// blocks [0, 8192): build split-x (float4 path, 4 dims/thread).
// blocks [8192, 8192+16384): weight fp32->fp16 convert, 2,097,152 elements.
#define WSPLIT_BLOCKS 16384

__global__ void __launch_bounds__(128) build_split_kernel(
    const float* __restrict__ sr, const void* __restrict__ rm,
    const void* __restrict__ pm, const int* __restrict__ roles,
    const float* __restrict__ remb, float* __restrict__ dout,
    const float* __restrict__ Wq, const float* __restrict__ Wk,
    const float* __restrict__ Wv, const float* __restrict__ Wo,
    const float* __restrict__ Wg2, const float* __restrict__ Wg1,
    __half* __restrict__ oWs1, __half* __restrict__ oWso,
    __half* __restrict__ oWsg2, __half* __restrict__ oWsg1) {
    if (blockIdx.x >= BLn) {
        int idx = (blockIdx.x - BLn) * 128 + threadIdx.x;
        const float* W;
        __half* out;
        int e;
        if (idx < 262144)        { W = Wq;  out = oWs1;                      e = idx; }
        else if (idx < 524288)   { W = Wk;  out = oWs1 + (size_t)512 * 512;  e = idx - 262144; }
        else if (idx < 786432)   { W = Wv;  out = oWs1 + (size_t)1024 * 512; e = idx - 524288; }
        else if (idx < 1048576)  { W = Wo;  out = oWso;                      e = idx - 786432; }
        else if (idx < 1310720)  { W = Wg2; out = oWsg2;                     e = idx - 1048576; }
        else                     { W = Wg1; out = oWsg1;                     e = idx - 1310720; }
        out[e] = __float2half_rn(W[e]);
        return;
    }
    // ---- build-x path: 128 threads x 4 dims ----
    int bl = blockIdx.x;
    int b = bl >> 10;
    int l = bl & 1023;
    int t = threadIdx.x;
    int d0 = t * 4;
    int u8 = g_mask_u8;
    __shared__ int slots[Kst];

    bool vd[Kst];
    float swr[Kst];
    float ssum = 0.f;
#pragma unroll
    for (int k = 0; k < Kst; k++) {
        bool v = mask_at(rm, (b * Kst + k) * Lseq + l, u8) && mask_at(pm, b * Kst + k, u8);
        vd[k] = v;
        swr[k] = v ? g_nsw[b * Kst + k] : 0.f;
        ssum += swr[k];
    }
    if (t == 0) {
        int nv = 0;
#pragma unroll
        for (int k = 0; k < Kst; k++) nv += vd[k] ? 1 : 0;
        int base = nv ? atomicAdd(&g_cnt, nv) : 0;
#pragma unroll
        for (int k = 0; k < Kst; k++) {
            if (vd[k]) {
                slots[k] = base;
                g_rowmap[base] = bl * Kst + k;
                base++;
            } else slots[k] = -1;
        }
    }
    __syncthreads();
    float inv = 1.f / fmaxf(ssum, 1e-8f);

    float4 wm = make_float4(0.f, 0.f, 0.f, 0.f);
    float4 mx = make_float4(-1e9f, -1e9f, -1e9f, -1e9f);
    bool any = false;
#pragma unroll
    for (int k = 0; k < Kst; k++) {
        swr[k] *= inv;
        if (vd[k]) {
            int role = max(roles[b * Kst + k], 0);
            float4 s4 = *(const float4*)(sr + (((size_t)(b * Kst + k)) * Lseq + l) * Ddim + d0);
            float4 r4 = *(const float4*)(remb + (size_t)role * Ddim + d0);
            float4 xv = make_float4(s4.x + r4.x, s4.y + r4.y, s4.z + r4.z, s4.w + r4.w);
            any = true;
            mx.x = fmaxf(mx.x, xv.x); mx.y = fmaxf(mx.y, xv.y);
            mx.z = fmaxf(mx.z, xv.z); mx.w = fmaxf(mx.w, xv.w);
            __half h0, l0, h1, l1, h2, l2, h3, l3;
            split2h(xv.x, h0, l0); split2h(xv.y, h1, l1);
            split2h(xv.z, h2, l2); split2h(xv.w, h3, l3);
            size_t row = (size_t)slots[k] * 1024;
            *(__half2*)(g_Xs + row + d0)           = __halves2half2(h0, h1);
            *(__half2*)(g_Xs + row + d0 + 2)       = __halves2half2(h2, h3);
            *(__half2*)(g_Xs + row + 512 + d0)     = __halves2half2(l0, l1);
            *(__half2*)(g_Xs + row + 512 + d0 + 2) = __halves2half2(l2, l3);
            wm.x += swr[k] * xv.x; wm.y += swr[k] * xv.y;
            wm.z += swr[k] * xv.z; wm.w += swr[k] * xv.w;
        }
    }
    *(float4*)(dout + OUT_WM + (size_t)bl * Ddim + d0) = wm;
    if (!any) mx = make_float4(0.f, 0.f, 0.f, 0.f);
    *(float4*)(dout + OUT_MF + (size_t)bl * Ddim + d0) = mx;
    if (t < Kst) g_swr[bl * Kst + t] = swr[t];
}

// ---------------- HMMA fp16 GEMM, cp.async 3-stage pipeline, 2 CTAs/SM ----------------
#define STAGES 3
#define GSM_BYTES (STAGES * 32768)

template <int EPI, bool COMPACT>
__global__ void __launch_bounds__(256, 2) gemm_mma(
    const __half* __restrict__ A, const __half* __restrict__ B,
    const float* __restrict__ bias, float* __restrict__ Cf,
    __half* __restrict__ Cb, int K, int ldb, int ldc) {
    int Mv = 0;
    if (COMPACT) {
        Mv = g_cnt;
        int padded = (Mv + 127) & ~127;
        if ((int)(blockIdx.y * 128) >= padded) return;
    }
    extern __shared__ __align__(1024) char smem[];
    uint32_t sA0 = smem_u32(smem);
    int tid = threadIdx.x;
    int wid = tid >> 5, lane = tid & 31;
    const int wm = wid >> 2, wn = wid & 3;

    const size_t bm = (size_t)blockIdx.y * 128;
    const int bn = blockIdx.x * 128;
    const int seg = tid & 7;
    const int r0 = tid >> 3;

    const __half* Ab = A + (bm + r0) * (size_t)K + seg * 8;
    const __half* Bb = B + (size_t)(bn + r0) * ldb + seg * 8;
    const uint32_t swbase = swz(r0 * 128 + seg * 16);

    auto copy_stage = [&](int c, int buf) {
        int kc = c << 6;
        int bkc = (kc >= ldb) ? kc - ldb : kc;
        uint32_t pa = sA0 + buf * 32768 + swbase;
#pragma unroll
        for (int i = 0; i < 4; i++) {
            cp_async16(pa + i * 32 * 128, Ab + (size_t)(i * 32) * K + kc);
            cp_async16(pa + 16384 + i * 32 * 128, Bb + (size_t)(i * 32) * ldb + bkc);
        }
        asm volatile("cp.async.commit_group;" ::: "memory");
    };

    float acc[4][4][4];
#pragma unroll
    for (int i = 0; i < 4; i++)
#pragma unroll
        for (int j = 0; j < 4; j++)
#pragma unroll
            for (int q = 0; q < 4; q++) acc[i][j][q] = 0.f;

    const uint32_t aRow = wm * 64 + (lane & 15);
    const uint32_t aColB = (lane >> 4) << 4;
    const uint32_t bRow = wn * 32 + (lane & 7) + ((lane >> 4) << 3);
    const uint32_t bColB = ((lane >> 3) & 1) << 4;

    const int NC = K >> 6;
#pragma unroll
    for (int s = 0; s < STAGES - 1; s++)
        if (s < NC) copy_stage(s, s);

    for (int c = 0; c < NC; c++) {
        asm volatile("cp.async.wait_group %0;" :: "n"(STAGES - 2));
        __syncthreads();
        if (c + STAGES - 1 < NC) copy_stage(c + STAGES - 1, (c + STAGES - 1) % STAGES);

        uint32_t Abuf = sA0 + (c % STAGES) * 32768;
        uint32_t Bbuf = Abuf + 16384;
#pragma unroll
        for (int ks = 0; ks < 4; ks++) {
            uint32_t a[4][4], b[4][2];
#pragma unroll
            for (int mt = 0; mt < 4; mt++) {
                uint32_t off = (aRow + mt * 16) * 128 + ks * 32 + aColB;
                ldsm_x4(a[mt][0], a[mt][1], a[mt][2], a[mt][3], Abuf + swz(off));
            }
#pragma unroll
            for (int p = 0; p < 2; p++) {
                uint32_t off = (bRow + p * 16) * 128 + ks * 32 + bColB;
                ldsm_x4(b[2 * p][0], b[2 * p][1], b[2 * p + 1][0], b[2 * p + 1][1],
                        Bbuf + swz(off));
            }
#pragma unroll
            for (int mt = 0; mt < 4; mt++)
#pragma unroll
                for (int nt = 0; nt < 4; nt++)
                    mma16816(acc[mt][nt], a[mt], b[nt]);
        }
    }

    // epilogue
    const int g = lane >> 2, t = lane & 3;
#pragma unroll
    for (int mt = 0; mt < 4; mt++) {
#pragma unroll
        for (int half = 0; half < 2; half++) {
            size_t grow = bm + wm * 64 + mt * 16 + g + half * 8;
            size_t orow = grow;
            if (COMPACT) {
                if ((int)grow >= Mv) continue;
                orow = (size_t)g_rowmap[grow];
            }
#pragma unroll
            for (int nt = 0; nt < 4; nt++) {
                int col = bn + wn * 32 + nt * 8 + t * 2;
                float v0 = acc[mt][nt][half * 2 + 0];
                float v1 = acc[mt][nt][half * 2 + 1];
                if (EPI == 0) {
                    float2 o = make_float2(v0, v1);
                    *(float2*)(Cf + orow * (size_t)ldc + col) = o;
                } else if (EPI == 1) {
                    v0 += bias[col];
                    v1 += bias[col + 1];
                    v0 = 0.5f * v0 * (1.f + erff(v0 * 0.70710678118654752f));
                    v1 = 0.5f * v1 * (1.f + erff(v1 * 0.70710678118654752f));
                    __half h0, l0, h1, l1;
                    split2h(v0, h0, l0);
                    split2h(v1, h1, l1);
                    size_t o = orow * 1024 + col;
                    *(__half2*)(Cb + o)       = __halves2half2(h0, h1);
                    *(__half2*)(Cb + o + 512) = __halves2half2(l0, l1);
                } else {
                    v0 += bias[col];
                    v1 += bias[col + 1];
                    float2 o;
                    o.x = 1.f / (1.f + __expf(-v0));
                    o.y = 1.f / (1.f + __expf(-v1));
                    *(float2*)(Cf + orow * 512 + col) = o;
                }
            }
        }
    }
}

// ---------------- attention: 4x4 per (b,l,h); pooled split output + attn_mean ----------------
__global__ void __launch_bounds__(256) attn_kernel(
    const void* __restrict__ rm, const void* __restrict__ pm,
    float* __restrict__ dout) {
    int bl = blockIdx.x;
    int b = bl >> 10;
    int l = bl & 1023;
    int warp = threadIdx.x >> 5;
    int lane = threadIdx.x & 31;
    __shared__ float am[Kst];
    if (threadIdx.x < Kst) am[threadIdx.x] = 0.f;
    __syncthreads();
    int u8 = g_mask_u8;

    float2 q[Kst], kk[Kst], vv[Kst];
    float ln_w[Kst], swr[Kst];
    bool vd[Kst];
    int col = warp * HDdim + lane * 2;
#pragma unroll
    for (int s = 0; s < Kst; s++) {
        vd[s] = mask_at(rm, (b * Kst + s) * Lseq + l, u8) && mask_at(pm, b * Kst + s, u8);
        if (vd[s]) {
            size_t rbase = (size_t)(bl * Kst + s) * 1536 + col;
            q[s]  = *(const float2*)(g_QKV + rbase);
            kk[s] = *(const float2*)(g_QKV + rbase + 512);
            vv[s] = *(const float2*)(g_QKV + rbase + 1024);
        } else {
            q[s] = kk[s] = vv[s] = make_float2(0.f, 0.f);
        }
        ln_w[s] = g_lognsw[b * Kst + s];
        swr[s]  = g_swr[bl * Kst + s];
    }

    float dot[Kst][Kst];
#pragma unroll
    for (int i = 0; i < Kst; i++) {
#pragma unroll
        for (int j = 0; j < Kst; j++) {
            float p = q[i].x * kk[j].x + q[i].y * kk[j].y;
#pragma unroll
            for (int o = 16; o; o >>= 1) p += __shfl_xor_sync(0xffffffffu, p, o);
            dot[i][j] = p;
        }
    }

    float a[Kst][Kst];
#pragma unroll
    for (int i = 0; i < Kst; i++) {
        float lm[Kst] = {0.f, 0.f, 0.f, 0.f};
        float m = -3.4e38f;
#pragma unroll
        for (int j = 0; j < Kst; j++) {
            if (vd[j]) {
                lm[j] = dot[i][j] * 0.125f + ln_w[j];
                m = fmaxf(m, lm[j]);
            }
        }
        float ssum = 0.f;
#pragma unroll
        for (int j = 0; j < Kst; j++) {
            float e = vd[j] ? __expf(lm[j] - m) : 0.f;
            a[i][j] = e;
            ssum += e;
        }
        float invs = (ssum > 0.f) ? (1.f / ssum) : 0.f;
#pragma unroll
        for (int j = 0; j < Kst; j++) a[i][j] *= invs;
    }

    float px = 0.f, py = 0.f;
#pragma unroll
    for (int i = 0; i < Kst; i++) {
        float ox = 0.f, oy = 0.f;
#pragma unroll
        for (int j = 0; j < Kst; j++) {
            ox += a[i][j] * vv[j].x;
            oy += a[i][j] * vv[j].y;
        }
        px += swr[i] * ox;
        py += swr[i] * oy;
    }
    __half hx, lx, hy, ly;
    split2h(px, hx, lx);
    split2h(py, hy, ly);
    size_t ob = (size_t)bl * 1024 + col;
    *(__half2*)(g_AOs + ob)       = __halves2half2(hx, hy);
    *(__half2*)(g_AOs + ob + 512) = __halves2half2(lx, ly);

    if (lane == 0) {
#pragma unroll
        for (int j = 0; j < Kst; j++)
            atomicAdd(&am[j], a[0][j] + a[1][j] + a[2][j] + a[3][j]);
    }
    __syncthreads();
    if (threadIdx.x < Kst)
        dout[OUT_AM + (size_t)bl * Kst + threadIdx.x] = am[threadIdx.x] * (1.f / 32.f);
}

// ---------------- block reduction ----------------
__device__ __forceinline__ float block_sum(float v, float* red) {
    int lane = threadIdx.x & 31, w = threadIdx.x >> 5;
#pragma unroll
    for (int o = 16; o; o >>= 1) v += __shfl_xor_sync(0xffffffffu, v, o);
    __syncthreads();
    if (lane == 0) red[w] = v;
    __syncthreads();
    if (threadIdx.x == 0) {
        float t = 0.f;
        int nw = (blockDim.x + 31) >> 5;
        for (int i = 0; i < nw; i++) t += red[i];
        red[8] = t;
    }
    __syncthreads();
    return red[8];
}

// ---------------- layernorm of gate_in (1536) -> split fp16 [hi|lo] ----------------
__global__ void __launch_bounds__(256) ln_gatein_kernel(
    const float* __restrict__ dro, const float* __restrict__ g,
    const float* __restrict__ bb) {
    int bl = blockIdx.x;
    __shared__ float buf[D3];
    __shared__ float red[9];
    float s = 0.f;
    for (int c = threadIdx.x; c < D3; c += 256) {
        float v;
        if (c < Ddim)          v = dro[OUT_AP + (size_t)bl * Ddim + c];
        else if (c < 2 * Ddim) v = dro[OUT_WM + (size_t)bl * Ddim + (c - Ddim)];
        else                   v = dro[OUT_MF + (size_t)bl * Ddim + (c - 2 * Ddim)];
        buf[c] = v;
        s += v;
    }
    s = block_sum(s, red);
    float mu = s * (1.f / D3);
    float sq = 0.f;
    for (int c = threadIdx.x; c < D3; c += 256) {
        float d = buf[c] - mu;
        sq += d * d;
    }
    sq = block_sum(sq, red);
    float rs = rsqrtf(sq * (1.f / D3) + 1e-5f);
    for (int c = threadIdx.x; c < D3; c += 256) {
        float y = (buf[c] - mu) * rs * g[c] + bb[c];
        __half hi, lo;
        split2h(y, hi, lo);
        size_t row = (size_t)bl * 3072;
        g_Gs[row + c] = hi;
        g_Gs[row + 1536 + c] = lo;
    }
}

// ---------------- final fuse + layernorm(512) ----------------
__global__ void __launch_bounds__(256) ln_final_kernel(
    float* __restrict__ dout, const float* __restrict__ ng,
    const float* __restrict__ nb) {
    int bl = blockIdx.x;
    __shared__ float buf[Ddim];
    __shared__ float red[9];
    float s = 0.f;
    for (int d = threadIdx.x; d < Ddim; d += 256) {
        float gate = g_GATE[(size_t)bl * Ddim + d];
        float ap = dout[OUT_AP + (size_t)bl * Ddim + d];
        float wm = dout[OUT_WM + (size_t)bl * Ddim + d];
        float mf = dout[OUT_MF + (size_t)bl * Ddim + d];
        float y = gate * 0.5f * (ap + wm) + (1.f - gate) * mf + wm;
        buf[d] = y;
        s += y;
    }
    s = block_sum(s, red);
    float mu = s * (1.f / Ddim);
    float sq = 0.f;
    for (int d = threadIdx.x; d < Ddim; d += 256) {
        float dd = buf[d] - mu;
        sq += dd * dd;
    }
    sq = block_sum(sq, red);
    float rs = rsqrtf(sq * (1.f / Ddim) + 1e-5f);
    for (int d = threadIdx.x; d < Ddim; d += 256)
        dout[OUT_FUSED + (size_t)bl * Ddim + d] = (buf[d] - mu) * rs * ng[d] + nb[d];
}

// ---------------- launch ----------------
extern "C" void kernel_launch(void* const* d_in, const int* in_sizes, int n_in,
                              void* d_out, int out_size) {
    const float* sr    = (const float*)d_in[0];
    const void*  rmask = d_in[1];
    const float* sw    = (const float*)d_in[2];
    const int*   roles = (const int*)d_in[3];
    const void*  pmask = d_in[4];
    const float* remb  = (const float*)d_in[5];
    const float* Wq    = (const float*)d_in[6];
    const float* Wk    = (const float*)d_in[7];
    const float* Wv    = (const float*)d_in[8];
    const float* Wo    = (const float*)d_in[9];
    const float* ln1g  = (const float*)d_in[10];
    const float* ln1b  = (const float*)d_in[11];
    const float* Wg1   = (const float*)d_in[12];
    const float* bg1   = (const float*)d_in[13];
    const float* Wg2   = (const float*)d_in[14];
    const float* bg2   = (const float*)d_in[15];
    const float* ng    = (const float*)d_in[16];
    const float* nb    = (const float*)d_in[17];
    float* dout = (float*)d_out;

    __half *pXs, *pAOs, *pGs, *pH1s, *pWs1, *pWso, *pWsg1, *pWsg2;
    float *pQKV, *pGATE;
    cudaGetSymbolAddress((void**)&pXs, g_Xs);
    cudaGetSymbolAddress((void**)&pQKV, g_QKV);
    cudaGetSymbolAddress((void**)&pAOs, g_AOs);
    cudaGetSymbolAddress((void**)&pGs, g_Gs);
    cudaGetSymbolAddress((void**)&pH1s, g_H1s);
    cudaGetSymbolAddress((void**)&pGATE, g_GATE);
    cudaGetSymbolAddress((void**)&pWs1, g_Ws1);
    cudaGetSymbolAddress((void**)&pWso, g_Wso);
    cudaGetSymbolAddress((void**)&pWsg1, g_Wsg1);
    cudaGetSymbolAddress((void**)&pWsg2, g_Wsg2);

    cudaFuncSetAttribute(gemm_mma<0, true>,  cudaFuncAttributeMaxDynamicSharedMemorySize, GSM_BYTES);
    cudaFuncSetAttribute(gemm_mma<0, false>, cudaFuncAttributeMaxDynamicSharedMemorySize, GSM_BYTES);
    cudaFuncSetAttribute(gemm_mma<1, false>, cudaFuncAttributeMaxDynamicSharedMemorySize, GSM_BYTES);
    cudaFuncSetAttribute(gemm_mma<2, false>, cudaFuncAttributeMaxDynamicSharedMemorySize, GSM_BYTES);

    detnsw_kernel<<<1, 256>>>(rmask, sw, pmask, dout + OUT_NSW);
    build_split_kernel<<<BLn + WSPLIT_BLOCKS, 128>>>(sr, rmask, pmask, roles, remb, dout,
                                                     Wq, Wk, Wv, Wo, Wg2, Wg1,
                                                     pWs1, pWso, pWsg2, pWsg1);

    // fused QKV on compacted rows: [Mv x 1536] = Xs([hi|lo], K'=1024) @ Ws1(hi, ldb=512)^T
    {
        dim3 grid(1536 / 128, Tn / 128);
        gemm_mma<0, true><<<grid, 256, GSM_BYTES>>>(pXs, pWs1, nullptr, pQKV, nullptr, 1024, 512, 1536);
    }

    attn_kernel<<<BLn, 256>>>(rmask, pmask, dout);

    // attn_pooled = AOs @ Wso^T  [8192 x 512]
    {
        dim3 grid(512 / 128, BLn / 128);
        gemm_mma<0, false><<<grid, 256, GSM_BYTES>>>(pAOs, pWso, nullptr, dout + OUT_AP, nullptr, 1024, 512, 512);
    }

    ln_gatein_kernel<<<BLn, 256>>>(dout, ln1g, ln1b);

    // h = gelu(Gs @ Wsg1^T + bg1) -> split fp16 [hi|lo]
    {
        dim3 grid(512 / 128, BLn / 128);
        gemm_mma<1, false><<<grid, 256, GSM_BYTES>>>(pGs, pWsg1, bg1, nullptr, pH1s, 3072, 1536, 0);
    }
    // gate = sigmoid(H1s @ Wsg2^T + bg2)
    {
        dim3 grid(512 / 128, BLn / 128);
        gemm_mma<2, false><<<grid, 256, GSM_BYTES>>>(pH1s, pWsg2, bg2, pGATE, nullptr, 1024, 512, 0);
    }

    ln_final_kernel<<<BLn, 256>>>(dout, ng, nb);
}

// round 13
// speedup vs baseline: 1.6424x; 1.0664x over previous
#include <cuda_runtime.h>
#include <cuda_fp16.h>
#include <math.h>
#include <stdint.h>

// ---------------- problem constants ----------------
#define Bdim 8
#define Kst 4
#define Lseq 1024
#define Ddim 512
#define Hn 8
#define HDdim 64
#define BLn 8192
#define Tn 32768
#define D3 1536

#define OUT_FUSED 0
#define OUT_AP    4194304
#define OUT_WM    8388608
#define OUT_MF    12582912
#define OUT_AM    16777216
#define OUT_NSW   16809984

// ---------------- device scratch ----------------
// fp16 2-term split: A-side [hi(0:S) | lo(S:2S)], logical K'=2S.
// B-side stores only hi [N x S]; logical second half re-reads hi (index wrap).
__device__ __half g_Xs[(size_t)Tn * 1024];
__device__ float  g_QKV[(size_t)Tn * 1536];
__device__ __half g_AOs[(size_t)BLn * 1024];
__device__ __half g_Gs[(size_t)BLn * 3072];
__device__ __half g_H1s[(size_t)BLn * 1024];
__device__ float  g_GATE[(size_t)BLn * Ddim];
__device__ __half g_Ws1[1536 * 512];
__device__ __half g_Wso[512 * 512];
__device__ __half g_Wsg1[512 * 1536];
__device__ __half g_Wsg2[512 * 512];
__device__ float g_swr[BLn * Kst];
__device__ float g_nsw[Bdim * Kst];
__device__ float g_lognsw[Bdim * Kst];
__device__ int   g_mask_u8;
__device__ int   g_cnt;
__device__ int   g_rowmap[Tn];

// ---------------- helpers ----------------
__device__ __forceinline__ uint32_t smem_u32(const void* p) {
    uint32_t a;
    asm("{ .reg .u64 t; cvta.to.shared.u64 t, %1; cvt.u32.u64 %0, t; }" : "=r"(a) : "l"(p));
    return a;
}
__device__ __forceinline__ void split2h(float v, __half& hi, __half& lo) {
    hi = __float2half_rn(v);
    lo = __float2half_rn(v - __half2float(hi));
}
__device__ __forceinline__ void ldsm_x4(uint32_t& r0, uint32_t& r1, uint32_t& r2,
                                        uint32_t& r3, uint32_t addr) {
    asm volatile("ldmatrix.sync.aligned.m8n8.x4.shared.b16 {%0,%1,%2,%3}, [%4];"
                 : "=r"(r0), "=r"(r1), "=r"(r2), "=r"(r3) : "r"(addr));
}
__device__ __forceinline__ void mma16816(float* c, const uint32_t* a, const uint32_t* b) {
    asm volatile(
        "mma.sync.aligned.m16n8k16.row.col.f32.f16.f16.f32 "
        "{%0,%1,%2,%3}, {%4,%5,%6,%7}, {%8,%9}, {%0,%1,%2,%3};"
        : "+f"(c[0]), "+f"(c[1]), "+f"(c[2]), "+f"(c[3])
        : "r"(a[0]), "r"(a[1]), "r"(a[2]), "r"(a[3]), "r"(b[0]), "r"(b[1]));
}
__device__ __forceinline__ uint32_t swz(uint32_t off) {
    return off ^ ((off >> 3) & 0x70);
}
__device__ __forceinline__ void cp_async16(uint32_t dst, const void* src) {
    asm volatile("cp.async.cg.shared.global [%0], [%1], 16;" :: "r"(dst), "l"(src));
}
__device__ __forceinline__ bool mask_at(const void* p, int idx, int u8) {
    return u8 ? (((const unsigned char*)p)[idx] != 0) : (((const int*)p)[idx] != 0);
}

// ---------------- fused mask-detect + nsw ----------------
__global__ void detnsw_kernel(const void* __restrict__ rm, const float* __restrict__ sw,
                              const void* __restrict__ pm, float* __restrict__ out_nsw) {
    __shared__ int s_u8;
    const int* p = (const int*)rm;
    int bad = 0;
    for (int i = threadIdx.x; i < 8192; i += 256) {
        int v = p[i];
        if (v != 0 && v != 1) bad = 1;
    }
    bad = __syncthreads_or(bad);
    if (threadIdx.x == 0) {
        g_mask_u8 = bad;
        g_cnt = 0;
        s_u8 = bad;
    }
    __syncthreads();
    int b = threadIdx.x;
    if (b >= Bdim) return;
    int u8 = s_u8;
    float w[Kst], pres[Kst];
    float denom = 0.f, psum = 0.f;
#pragma unroll
    for (int k = 0; k < Kst; k++) {
        pres[k] = mask_at(pm, b * Kst + k, u8) ? 1.f : 0.f;
        w[k] = sw[b * Kst + k] * pres[k];
        denom += w[k];
        psum += pres[k];
    }
#pragma unroll
    for (int k = 0; k < Kst; k++) {
        float nswk = (denom > 1e-8f) ? (w[k] / fmaxf(denom, 1e-8f))
                                     : (pres[k] / fmaxf(psum, 1.f));
        g_nsw[b * Kst + k] = nswk;
        g_lognsw[b * Kst + k] = logf(fmaxf(nswk, 1e-8f));
        out_nsw[b * Kst + k] = nswk;
    }
}

// ---------------- fused build-x + weight convert (blockDim 128) ----------------
#define WSPLIT_BLOCKS 16384

__global__ void __launch_bounds__(128) build_split_kernel(
    const float* __restrict__ sr, const void* __restrict__ rm,
    const void* __restrict__ pm, const int* __restrict__ roles,
    const float* __restrict__ remb, float* __restrict__ dout,
    const float* __restrict__ Wq, const float* __restrict__ Wk,
    const float* __restrict__ Wv, const float* __restrict__ Wo,
    const float* __restrict__ Wg2, const float* __restrict__ Wg1,
    __half* __restrict__ oWs1, __half* __restrict__ oWso,
    __half* __restrict__ oWsg2, __half* __restrict__ oWsg1) {
    if (blockIdx.x >= BLn) {
        int idx = (blockIdx.x - BLn) * 128 + threadIdx.x;
        const float* W;
        __half* out;
        int e;
        if (idx < 262144)        { W = Wq;  out = oWs1;                      e = idx; }
        else if (idx < 524288)   { W = Wk;  out = oWs1 + (size_t)512 * 512;  e = idx - 262144; }
        else if (idx < 786432)   { W = Wv;  out = oWs1 + (size_t)1024 * 512; e = idx - 524288; }
        else if (idx < 1048576)  { W = Wo;  out = oWso;                      e = idx - 786432; }
        else if (idx < 1310720)  { W = Wg2; out = oWsg2;                     e = idx - 1048576; }
        else                     { W = Wg1; out = oWsg1;                     e = idx - 1310720; }
        out[e] = __float2half_rn(W[e]);
        return;
    }
    // ---- build-x path: 128 threads x 4 dims ----
    int bl = blockIdx.x;
    int b = bl >> 10;
    int l = bl & 1023;
    int t = threadIdx.x;
    int d0 = t * 4;
    int u8 = g_mask_u8;
    __shared__ int slots[Kst];

    bool vd[Kst];
    float swr[Kst];
    float ssum = 0.f;
#pragma unroll
    for (int k = 0; k < Kst; k++) {
        bool v = mask_at(rm, (b * Kst + k) * Lseq + l, u8) && mask_at(pm, b * Kst + k, u8);
        vd[k] = v;
        swr[k] = v ? g_nsw[b * Kst + k] : 0.f;
        ssum += swr[k];
    }
    if (t == 0) {
        int nv = 0;
#pragma unroll
        for (int k = 0; k < Kst; k++) nv += vd[k] ? 1 : 0;
        int base = nv ? atomicAdd(&g_cnt, nv) : 0;
#pragma unroll
        for (int k = 0; k < Kst; k++) {
            if (vd[k]) {
                slots[k] = base;
                g_rowmap[base] = bl * Kst + k;
                base++;
            } else slots[k] = -1;
        }
    }
    __syncthreads();
    float inv = 1.f / fmaxf(ssum, 1e-8f);

    float4 wm = make_float4(0.f, 0.f, 0.f, 0.f);
    float4 mx = make_float4(-1e9f, -1e9f, -1e9f, -1e9f);
    bool any = false;
#pragma unroll
    for (int k = 0; k < Kst; k++) {
        swr[k] *= inv;
        if (vd[k]) {
            int role = max(roles[b * Kst + k], 0);
            float4 s4 = *(const float4*)(sr + (((size_t)(b * Kst + k)) * Lseq + l) * Ddim + d0);
            float4 r4 = *(const float4*)(remb + (size_t)role * Ddim + d0);
            float4 xv = make_float4(s4.x + r4.x, s4.y + r4.y, s4.z + r4.z, s4.w + r4.w);
            any = true;
            mx.x = fmaxf(mx.x, xv.x); mx.y = fmaxf(mx.y, xv.y);
            mx.z = fmaxf(mx.z, xv.z); mx.w = fmaxf(mx.w, xv.w);
            __half h0, l0, h1, l1, h2, l2, h3, l3;
            split2h(xv.x, h0, l0); split2h(xv.y, h1, l1);
            split2h(xv.z, h2, l2); split2h(xv.w, h3, l3);
            size_t row = (size_t)slots[k] * 1024;
            *(__half2*)(g_Xs + row + d0)           = __halves2half2(h0, h1);
            *(__half2*)(g_Xs + row + d0 + 2)       = __halves2half2(h2, h3);
            *(__half2*)(g_Xs + row + 512 + d0)     = __halves2half2(l0, l1);
            *(__half2*)(g_Xs + row + 512 + d0 + 2) = __halves2half2(l2, l3);
            wm.x += swr[k] * xv.x; wm.y += swr[k] * xv.y;
            wm.z += swr[k] * xv.z; wm.w += swr[k] * xv.w;
        }
    }
    *(float4*)(dout + OUT_WM + (size_t)bl * Ddim + d0) = wm;
    if (!any) mx = make_float4(0.f, 0.f, 0.f, 0.f);
    *(float4*)(dout + OUT_MF + (size_t)bl * Ddim + d0) = mx;
    if (t < Kst) g_swr[bl * Kst + t] = swr[t];
}

// ---------------- HMMA fp16 GEMM, cp.async 3-stage pipeline, 2 CTAs/SM ----------------
#define STAGES 3
#define GSM_BYTES (STAGES * 32768)

template <int EPI, bool COMPACT>
__global__ void __launch_bounds__(256, 2) gemm_mma(
    const __half* __restrict__ A, const __half* __restrict__ B,
    const float* __restrict__ bias, float* __restrict__ Cf,
    __half* __restrict__ Cb, int K, int ldb, int ldc) {
    int Mv = 0;
    if (COMPACT) {
        Mv = g_cnt;
        int padded = (Mv + 127) & ~127;
        if ((int)(blockIdx.y * 128) >= padded) return;
    }
    extern __shared__ __align__(1024) char smem[];
    uint32_t sA0 = smem_u32(smem);
    int tid = threadIdx.x;
    int wid = tid >> 5, lane = tid & 31;
    const int wm = wid >> 2, wn = wid & 3;

    const size_t bm = (size_t)blockIdx.y * 128;
    const int bn = blockIdx.x * 128;
    const int seg = tid & 7;
    const int r0 = tid >> 3;

    const __half* Ab = A + (bm + r0) * (size_t)K + seg * 8;
    const __half* Bb = B + (size_t)(bn + r0) * ldb + seg * 8;
    const uint32_t swbase = swz(r0 * 128 + seg * 16);

    auto copy_stage = [&](int c, int buf) {
        int kc = c << 6;
        int bkc = (kc >= ldb) ? kc - ldb : kc;
        uint32_t pa = sA0 + buf * 32768 + swbase;
#pragma unroll
        for (int i = 0; i < 4; i++) {
            cp_async16(pa + i * 32 * 128, Ab + (size_t)(i * 32) * K + kc);
            cp_async16(pa + 16384 + i * 32 * 128, Bb + (size_t)(i * 32) * ldb + bkc);
        }
        asm volatile("cp.async.commit_group;" ::: "memory");
    };

    float acc[4][4][4];
#pragma unroll
    for (int i = 0; i < 4; i++)
#pragma unroll
        for (int j = 0; j < 4; j++)
#pragma unroll
            for (int q = 0; q < 4; q++) acc[i][j][q] = 0.f;

    const uint32_t aRow = wm * 64 + (lane & 15);
    const uint32_t aColB = (lane >> 4) << 4;
    const uint32_t bRow = wn * 32 + (lane & 7) + ((lane >> 4) << 3);
    const uint32_t bColB = ((lane >> 3) & 1) << 4;

    const int NC = K >> 6;
#pragma unroll
    for (int s = 0; s < STAGES - 1; s++)
        if (s < NC) copy_stage(s, s);

    for (int c = 0; c < NC; c++) {
        asm volatile("cp.async.wait_group %0;" :: "n"(STAGES - 2));
        __syncthreads();
        if (c + STAGES - 1 < NC) copy_stage(c + STAGES - 1, (c + STAGES - 1) % STAGES);

        uint32_t Abuf = sA0 + (c % STAGES) * 32768;
        uint32_t Bbuf = Abuf + 16384;
#pragma unroll
        for (int ks = 0; ks < 4; ks++) {
            uint32_t a[4][4], b[4][2];
#pragma unroll
            for (int mt = 0; mt < 4; mt++) {
                uint32_t off = (aRow + mt * 16) * 128 + ks * 32 + aColB;
                ldsm_x4(a[mt][0], a[mt][1], a[mt][2], a[mt][3], Abuf + swz(off));
            }
#pragma unroll
            for (int p = 0; p < 2; p++) {
                uint32_t off = (bRow + p * 16) * 128 + ks * 32 + bColB;
                ldsm_x4(b[2 * p][0], b[2 * p][1], b[2 * p + 1][0], b[2 * p + 1][1],
                        Bbuf + swz(off));
            }
#pragma unroll
            for (int mt = 0; mt < 4; mt++)
#pragma unroll
                for (int nt = 0; nt < 4; nt++)
                    mma16816(acc[mt][nt], a[mt], b[nt]);
        }
    }

    // epilogue
    const int g = lane >> 2, t = lane & 3;
#pragma unroll
    for (int mt = 0; mt < 4; mt++) {
#pragma unroll
        for (int half = 0; half < 2; half++) {
            size_t grow = bm + wm * 64 + mt * 16 + g + half * 8;
            size_t orow = grow;
            if (COMPACT) {
                if ((int)grow >= Mv) continue;
                orow = (size_t)g_rowmap[grow];
            }
#pragma unroll
            for (int nt = 0; nt < 4; nt++) {
                int col = bn + wn * 32 + nt * 8 + t * 2;
                float v0 = acc[mt][nt][half * 2 + 0];
                float v1 = acc[mt][nt][half * 2 + 1];
                if (EPI == 0) {
                    float2 o = make_float2(v0, v1);
                    *(float2*)(Cf + orow * (size_t)ldc + col) = o;
                } else if (EPI == 1) {
                    v0 += bias[col];
                    v1 += bias[col + 1];
                    v0 = 0.5f * v0 * (1.f + erff(v0 * 0.70710678118654752f));
                    v1 = 0.5f * v1 * (1.f + erff(v1 * 0.70710678118654752f));
                    __half h0, l0, h1, l1;
                    split2h(v0, h0, l0);
                    split2h(v1, h1, l1);
                    size_t o = orow * 1024 + col;
                    *(__half2*)(Cb + o)       = __halves2half2(h0, h1);
                    *(__half2*)(Cb + o + 512) = __halves2half2(l0, l1);
                } else {
                    v0 += bias[col];
                    v1 += bias[col + 1];
                    float2 o;
                    o.x = 1.f / (1.f + __expf(-v0));
                    o.y = 1.f / (1.f + __expf(-v1));
                    *(float2*)(Cf + orow * 512 + col) = o;
                }
            }
        }
    }
}

// ---------------- attention: 4x4 per (b,l,h); pooled split output + attn_mean ----------------
__global__ void __launch_bounds__(256) attn_kernel(
    const void* __restrict__ rm, const void* __restrict__ pm,
    float* __restrict__ dout) {
    int bl = blockIdx.x;
    int b = bl >> 10;
    int l = bl & 1023;
    int warp = threadIdx.x >> 5;
    int lane = threadIdx.x & 31;
    __shared__ float am[Kst];
    if (threadIdx.x < Kst) am[threadIdx.x] = 0.f;
    __syncthreads();
    int u8 = g_mask_u8;

    float2 q[Kst], kk[Kst], vv[Kst];
    float ln_w[Kst], swr[Kst];
    bool vd[Kst];
    int col = warp * HDdim + lane * 2;
#pragma unroll
    for (int s = 0; s < Kst; s++) {
        vd[s] = mask_at(rm, (b * Kst + s) * Lseq + l, u8) && mask_at(pm, b * Kst + s, u8);
        if (vd[s]) {
            size_t rbase = (size_t)(bl * Kst + s) * 1536 + col;
            q[s]  = *(const float2*)(g_QKV + rbase);
            kk[s] = *(const float2*)(g_QKV + rbase + 512);
            vv[s] = *(const float2*)(g_QKV + rbase + 1024);
        } else {
            q[s] = kk[s] = vv[s] = make_float2(0.f, 0.f);
        }
        ln_w[s] = g_lognsw[b * Kst + s];
        swr[s]  = g_swr[bl * Kst + s];
    }

    float dot[Kst][Kst];
#pragma unroll
    for (int i = 0; i < Kst; i++) {
#pragma unroll
        for (int j = 0; j < Kst; j++) {
            float p = q[i].x * kk[j].x + q[i].y * kk[j].y;
#pragma unroll
            for (int o = 16; o; o >>= 1) p += __shfl_xor_sync(0xffffffffu, p, o);
            dot[i][j] = p;
        }
    }

    float a[Kst][Kst];
#pragma unroll
    for (int i = 0; i < Kst; i++) {
        float lm[Kst] = {0.f, 0.f, 0.f, 0.f};
        float m = -3.4e38f;
#pragma unroll
        for (int j = 0; j < Kst; j++) {
            if (vd[j]) {
                lm[j] = dot[i][j] * 0.125f + ln_w[j];
                m = fmaxf(m, lm[j]);
            }
        }
        float ssum = 0.f;
#pragma unroll
        for (int j = 0; j < Kst; j++) {
            float e = vd[j] ? __expf(lm[j] - m) : 0.f;
            a[i][j] = e;
            ssum += e;
        }
        float invs = (ssum > 0.f) ? (1.f / ssum) : 0.f;
#pragma unroll
        for (int j = 0; j < Kst; j++) a[i][j] *= invs;
    }

    float px = 0.f, py = 0.f;
#pragma unroll
    for (int i = 0; i < Kst; i++) {
        float ox = 0.f, oy = 0.f;
#pragma unroll
        for (int j = 0; j < Kst; j++) {
            ox += a[i][j] * vv[j].x;
            oy += a[i][j] * vv[j].y;
        }
        px += swr[i] * ox;
        py += swr[i] * oy;
    }
    __half hx, lx, hy, ly;
    split2h(px, hx, lx);
    split2h(py, hy, ly);
    size_t ob = (size_t)bl * 1024 + col;
    *(__half2*)(g_AOs + ob)       = __halves2half2(hx, hy);
    *(__half2*)(g_AOs + ob + 512) = __halves2half2(lx, ly);

    if (lane == 0) {
#pragma unroll
        for (int j = 0; j < Kst; j++)
            atomicAdd(&am[j], a[0][j] + a[1][j] + a[2][j] + a[3][j]);
    }
    __syncthreads();
    if (threadIdx.x < Kst)
        dout[OUT_AM + (size_t)bl * Kst + threadIdx.x] = am[threadIdx.x] * (1.f / 32.f);
}

// ---------------- block reduction ----------------
__device__ __forceinline__ float block_sum(float v, float* red) {
    int lane = threadIdx.x & 31, w = threadIdx.x >> 5;
#pragma unroll
    for (int o = 16; o; o >>= 1) v += __shfl_xor_sync(0xffffffffu, v, o);
    __syncthreads();
    if (lane == 0) red[w] = v;
    __syncthreads();
    if (threadIdx.x == 0) {
        float t = 0.f;
        int nw = (blockDim.x + 31) >> 5;
        for (int i = 0; i < nw; i++) t += red[i];
        red[8] = t;
    }
    __syncthreads();
    return red[8];
}

// ---------------- layernorm of gate_in (1536) -> split fp16 [hi|lo], float4 ----------------
__global__ void __launch_bounds__(256) ln_gatein_kernel(
    const float* __restrict__ dro, const float* __restrict__ g,
    const float* __restrict__ bb) {
    int bl = blockIdx.x;
    __shared__ float4 sbuf[384];
    __shared__ float red[9];
    float s = 0.f;
    // 384 float4 sections: [0,128)=AP, [128,256)=WM, [256,384)=MF
#pragma unroll 2
    for (int i = threadIdx.x; i < 384; i += 256) {
        float4 v;
        if (i < 128)      v = *(const float4*)(dro + OUT_AP + (size_t)bl * Ddim + i * 4);
        else if (i < 256) v = *(const float4*)(dro + OUT_WM + (size_t)bl * Ddim + (i - 128) * 4);
        else              v = *(const float4*)(dro + OUT_MF + (size_t)bl * Ddim + (i - 256) * 4);
        sbuf[i] = v;
        s += v.x + v.y + v.z + v.w;
    }
    s = block_sum(s, red);
    float mu = s * (1.f / D3);
    float sq = 0.f;
#pragma unroll 2
    for (int i = threadIdx.x; i < 384; i += 256) {
        float4 v = sbuf[i];
        float dx = v.x - mu, dy = v.y - mu, dz = v.z - mu, dw = v.w - mu;
        sq += dx * dx + dy * dy + dz * dz + dw * dw;
    }
    sq = block_sum(sq, red);
    float rs = rsqrtf(sq * (1.f / D3) + 1e-5f);
#pragma unroll 2
    for (int i = threadIdx.x; i < 384; i += 256) {
        int c = i * 4;
        float4 v = sbuf[i];
        float4 g4 = *(const float4*)(g + c);
        float4 b4 = *(const float4*)(bb + c);
        float y0 = (v.x - mu) * rs * g4.x + b4.x;
        float y1 = (v.y - mu) * rs * g4.y + b4.y;
        float y2 = (v.z - mu) * rs * g4.z + b4.z;
        float y3 = (v.w - mu) * rs * g4.w + b4.w;
        __half h0, l0, h1, l1, h2, l2, h3, l3;
        split2h(y0, h0, l0); split2h(y1, h1, l1);
        split2h(y2, h2, l2); split2h(y3, h3, l3);
        size_t row = (size_t)bl * 3072;
        *(__half2*)(g_Gs + row + c)            = __halves2half2(h0, h1);
        *(__half2*)(g_Gs + row + c + 2)        = __halves2half2(h2, h3);
        *(__half2*)(g_Gs + row + 1536 + c)     = __halves2half2(l0, l1);
        *(__half2*)(g_Gs + row + 1536 + c + 2) = __halves2half2(l2, l3);
    }
}

// ---------------- final fuse + layernorm(512), float4, 128 threads ----------------
__global__ void __launch_bounds__(128) ln_final_kernel(
    float* __restrict__ dout, const float* __restrict__ ng,
    const float* __restrict__ nb) {
    int bl = blockIdx.x;
    __shared__ float red[9];
    int d0 = threadIdx.x * 4;
    float4 gate = *(const float4*)(g_GATE + (size_t)bl * Ddim + d0);
    float4 ap = *(const float4*)(dout + OUT_AP + (size_t)bl * Ddim + d0);
    float4 wm = *(const float4*)(dout + OUT_WM + (size_t)bl * Ddim + d0);
    float4 mf = *(const float4*)(dout + OUT_MF + (size_t)bl * Ddim + d0);
    float4 y;
    y.x = gate.x * 0.5f * (ap.x + wm.x) + (1.f - gate.x) * mf.x + wm.x;
    y.y = gate.y * 0.5f * (ap.y + wm.y) + (1.f - gate.y) * mf.y + wm.y;
    y.z = gate.z * 0.5f * (ap.z + wm.z) + (1.f - gate.z) * mf.z + wm.z;
    y.w = gate.w * 0.5f * (ap.w + wm.w) + (1.f - gate.w) * mf.w + wm.w;
    float s = block_sum(y.x + y.y + y.z + y.w, red);
    float mu = s * (1.f / Ddim);
    float dx = y.x - mu, dy = y.y - mu, dz = y.z - mu, dw = y.w - mu;
    float sq = block_sum(dx * dx + dy * dy + dz * dz + dw * dw, red);
    float rs = rsqrtf(sq * (1.f / Ddim) + 1e-5f);
    float4 g4 = *(const float4*)(ng + d0);
    float4 b4 = *(const float4*)(nb + d0);
    float4 o;
    o.x = dx * rs * g4.x + b4.x;
    o.y = dy * rs * g4.y + b4.y;
    o.z = dz * rs * g4.z + b4.z;
    o.w = dw * rs * g4.w + b4.w;
    *(float4*)(dout + OUT_FUSED + (size_t)bl * Ddim + d0) = o;
}

// ---------------- launch ----------------
extern "C" void kernel_launch(void* const* d_in, const int* in_sizes, int n_in,
                              void* d_out, int out_size) {
    const float* sr    = (const float*)d_in[0];
    const void*  rmask = d_in[1];
    const float* sw    = (const float*)d_in[2];
    const int*   roles = (const int*)d_in[3];
    const void*  pmask = d_in[4];
    const float* remb  = (const float*)d_in[5];
    const float* Wq    = (const float*)d_in[6];
    const float* Wk    = (const float*)d_in[7];
    const float* Wv    = (const float*)d_in[8];
    const float* Wo    = (const float*)d_in[9];
    const float* ln1g  = (const float*)d_in[10];
    const float* ln1b  = (const float*)d_in[11];
    const float* Wg1   = (const float*)d_in[12];
    const float* bg1   = (const float*)d_in[13];
    const float* Wg2   = (const float*)d_in[14];
    const float* bg2   = (const float*)d_in[15];
    const float* ng    = (const float*)d_in[16];
    const float* nb    = (const float*)d_in[17];
    float* dout = (float*)d_out;

    __half *pXs, *pAOs, *pGs, *pH1s, *pWs1, *pWso, *pWsg1, *pWsg2;
    float *pQKV, *pGATE;
    cudaGetSymbolAddress((void**)&pXs, g_Xs);
    cudaGetSymbolAddress((void**)&pQKV, g_QKV);
    cudaGetSymbolAddress((void**)&pAOs, g_AOs);
    cudaGetSymbolAddress((void**)&pGs, g_Gs);
    cudaGetSymbolAddress((void**)&pH1s, g_H1s);
    cudaGetSymbolAddress((void**)&pGATE, g_GATE);
    cudaGetSymbolAddress((void**)&pWs1, g_Ws1);
    cudaGetSymbolAddress((void**)&pWso, g_Wso);
    cudaGetSymbolAddress((void**)&pWsg1, g_Wsg1);
    cudaGetSymbolAddress((void**)&pWsg2, g_Wsg2);

    cudaFuncSetAttribute(gemm_mma<0, true>,  cudaFuncAttributeMaxDynamicSharedMemorySize, GSM_BYTES);
    cudaFuncSetAttribute(gemm_mma<0, false>, cudaFuncAttributeMaxDynamicSharedMemorySize, GSM_BYTES);
    cudaFuncSetAttribute(gemm_mma<1, false>, cudaFuncAttributeMaxDynamicSharedMemorySize, GSM_BYTES);
    cudaFuncSetAttribute(gemm_mma<2, false>, cudaFuncAttributeMaxDynamicSharedMemorySize, GSM_BYTES);

    detnsw_kernel<<<1, 256>>>(rmask, sw, pmask, dout + OUT_NSW);
    build_split_kernel<<<BLn + WSPLIT_BLOCKS, 128>>>(sr, rmask, pmask, roles, remb, dout,
                                                     Wq, Wk, Wv, Wo, Wg2, Wg1,
                                                     pWs1, pWso, pWsg2, pWsg1);

    // fused QKV on compacted rows: [Mv x 1536] = Xs([hi|lo], K'=1024) @ Ws1(hi, ldb=512)^T
    {
        dim3 grid(1536 / 128, Tn / 128);
        gemm_mma<0, true><<<grid, 256, GSM_BYTES>>>(pXs, pWs1, nullptr, pQKV, nullptr, 1024, 512, 1536);
    }

    attn_kernel<<<BLn, 256>>>(rmask, pmask, dout);

    // attn_pooled = AOs @ Wso^T  [8192 x 512]
    {
        dim3 grid(512 / 128, BLn / 128);
        gemm_mma<0, false><<<grid, 256, GSM_BYTES>>>(pAOs, pWso, nullptr, dout + OUT_AP, nullptr, 1024, 512, 512);
    }

    ln_gatein_kernel<<<BLn, 256>>>(dout, ln1g, ln1b);

    // h = gelu(Gs @ Wsg1^T + bg1) -> split fp16 [hi|lo]
    {
        dim3 grid(512 / 128, BLn / 128);
        gemm_mma<1, false><<<grid, 256, GSM_BYTES>>>(pGs, pWsg1, bg1, nullptr, pH1s, 3072, 1536, 0);
    }
    // gate = sigmoid(H1s @ Wsg2^T + bg2)
    {
        dim3 grid(512 / 128, BLn / 128);
        gemm_mma<2, false><<<grid, 256, GSM_BYTES>>>(pH1s, pWsg2, bg2, pGATE, nullptr, 1024, 512, 0);
    }

    ln_final_kernel<<<BLn, 128>>>(dout, ng, nb);
}

// round 14
// speedup vs baseline: 1.8954x; 1.1541x over previous
#include <cuda_runtime.h>
#include <cuda_fp16.h>
#include <math.h>
#include <stdint.h>

// ---------------- problem constants ----------------
#define Bdim 8
#define Kst 4
#define Lseq 1024
#define Ddim 512
#define Hn 8
#define HDdim 64
#define BLn 8192
#define Tn 32768
#define D3 1536

#define OUT_FUSED 0
#define OUT_AP    4194304
#define OUT_WM    8388608
#define OUT_MF    12582912
#define OUT_AM    16777216
#define OUT_NSW   16809984

// ---------------- device scratch ----------------
// QKV/Wo GEMMs: fp16 2-term split (A [hi|lo], B hi with index wrap).
// Gate MLP GEMMs (Wg1, Wg2): hi-only fp16 (1-term) — error budget analysis in journal.
__device__ __half g_Xs[(size_t)Tn * 1024];
__device__ float  g_QKV[(size_t)Tn * 1536];
__device__ __half g_AOs[(size_t)BLn * 1024];
__device__ __half g_Gs[(size_t)BLn * 1536];    // hi only
__device__ __half g_H1s[(size_t)BLn * 512];    // hi only
__device__ float  g_GATE[(size_t)BLn * Ddim];
__device__ __half g_Ws1[1536 * 512];
__device__ __half g_Wso[512 * 512];
__device__ __half g_Wsg1[512 * 1536];
__device__ __half g_Wsg2[512 * 512];
__device__ float g_swr[BLn * Kst];
__device__ float g_nsw[Bdim * Kst];
__device__ float g_lognsw[Bdim * Kst];
__device__ int   g_mask_u8;
__device__ int   g_cnt;
__device__ int   g_rowmap[Tn];

// ---------------- helpers ----------------
__device__ __forceinline__ uint32_t smem_u32(const void* p) {
    uint32_t a;
    asm("{ .reg .u64 t; cvta.to.shared.u64 t, %1; cvt.u32.u64 %0, t; }" : "=r"(a) : "l"(p));
    return a;
}
__device__ __forceinline__ void split2h(float v, __half& hi, __half& lo) {
    hi = __float2half_rn(v);
    lo = __float2half_rn(v - __half2float(hi));
}
__device__ __forceinline__ void ldsm_x4(uint32_t& r0, uint32_t& r1, uint32_t& r2,
                                        uint32_t& r3, uint32_t addr) {
    asm volatile("ldmatrix.sync.aligned.m8n8.x4.shared.b16 {%0,%1,%2,%3}, [%4];"
                 : "=r"(r0), "=r"(r1), "=r"(r2), "=r"(r3) : "r"(addr));
}
__device__ __forceinline__ void mma16816(float* c, const uint32_t* a, const uint32_t* b) {
    asm volatile(
        "mma.sync.aligned.m16n8k16.row.col.f32.f16.f16.f32 "
        "{%0,%1,%2,%3}, {%4,%5,%6,%7}, {%8,%9}, {%0,%1,%2,%3};"
        : "+f"(c[0]), "+f"(c[1]), "+f"(c[2]), "+f"(c[3])
        : "r"(a[0]), "r"(a[1]), "r"(a[2]), "r"(a[3]), "r"(b[0]), "r"(b[1]));
}
__device__ __forceinline__ uint32_t swz(uint32_t off) {
    return off ^ ((off >> 3) & 0x70);
}
__device__ __forceinline__ void cp_async16(uint32_t dst, const void* src) {
    asm volatile("cp.async.cg.shared.global [%0], [%1], 16;" :: "r"(dst), "l"(src));
}
__device__ __forceinline__ bool mask_at(const void* p, int idx, int u8) {
    return u8 ? (((const unsigned char*)p)[idx] != 0) : (((const int*)p)[idx] != 0);
}

// ---------------- fused mask-detect + nsw ----------------
__global__ void detnsw_kernel(const void* __restrict__ rm, const float* __restrict__ sw,
                              const void* __restrict__ pm, float* __restrict__ out_nsw) {
    __shared__ int s_u8;
    const int* p = (const int*)rm;
    int bad = 0;
    for (int i = threadIdx.x; i < 8192; i += 256) {
        int v = p[i];
        if (v != 0 && v != 1) bad = 1;
    }
    bad = __syncthreads_or(bad);
    if (threadIdx.x == 0) {
        g_mask_u8 = bad;
        g_cnt = 0;
        s_u8 = bad;
    }
    __syncthreads();
    int b = threadIdx.x;
    if (b >= Bdim) return;
    int u8 = s_u8;
    float w[Kst], pres[Kst];
    float denom = 0.f, psum = 0.f;
#pragma unroll
    for (int k = 0; k < Kst; k++) {
        pres[k] = mask_at(pm, b * Kst + k, u8) ? 1.f : 0.f;
        w[k] = sw[b * Kst + k] * pres[k];
        denom += w[k];
        psum += pres[k];
    }
#pragma unroll
    for (int k = 0; k < Kst; k++) {
        float nswk = (denom > 1e-8f) ? (w[k] / fmaxf(denom, 1e-8f))
                                     : (pres[k] / fmaxf(psum, 1.f));
        g_nsw[b * Kst + k] = nswk;
        g_lognsw[b * Kst + k] = logf(fmaxf(nswk, 1e-8f));
        out_nsw[b * Kst + k] = nswk;
    }
}

// ---------------- fused build-x + weight convert (blockDim 128) ----------------
#define WSPLIT_BLOCKS 16384

__global__ void __launch_bounds__(128) build_split_kernel(
    const float* __restrict__ sr, const void* __restrict__ rm,
    const void* __restrict__ pm, const int* __restrict__ roles,
    const float* __restrict__ remb, float* __restrict__ dout,
    const float* __restrict__ Wq, const float* __restrict__ Wk,
    const float* __restrict__ Wv, const float* __restrict__ Wo,
    const float* __restrict__ Wg2, const float* __restrict__ Wg1,
    __half* __restrict__ oWs1, __half* __restrict__ oWso,
    __half* __restrict__ oWsg2, __half* __restrict__ oWsg1) {
    if (blockIdx.x >= BLn) {
        int idx = (blockIdx.x - BLn) * 128 + threadIdx.x;
        const float* W;
        __half* out;
        int e;
        if (idx < 262144)        { W = Wq;  out = oWs1;                      e = idx; }
        else if (idx < 524288)   { W = Wk;  out = oWs1 + (size_t)512 * 512;  e = idx - 262144; }
        else if (idx < 786432)   { W = Wv;  out = oWs1 + (size_t)1024 * 512; e = idx - 524288; }
        else if (idx < 1048576)  { W = Wo;  out = oWso;                      e = idx - 786432; }
        else if (idx < 1310720)  { W = Wg2; out = oWsg2;                     e = idx - 1048576; }
        else                     { W = Wg1; out = oWsg1;                     e = idx - 1310720; }
        out[e] = __float2half_rn(W[e]);
        return;
    }
    // ---- build-x path: 128 threads x 4 dims ----
    int bl = blockIdx.x;
    int b = bl >> 10;
    int l = bl & 1023;
    int t = threadIdx.x;
    int d0 = t * 4;
    int u8 = g_mask_u8;
    __shared__ int slots[Kst];

    bool vd[Kst];
    float swr[Kst];
    float ssum = 0.f;
#pragma unroll
    for (int k = 0; k < Kst; k++) {
        bool v = mask_at(rm, (b * Kst + k) * Lseq + l, u8) && mask_at(pm, b * Kst + k, u8);
        vd[k] = v;
        swr[k] = v ? g_nsw[b * Kst + k] : 0.f;
        ssum += swr[k];
    }
    if (t == 0) {
        int nv = 0;
#pragma unroll
        for (int k = 0; k < Kst; k++) nv += vd[k] ? 1 : 0;
        int base = nv ? atomicAdd(&g_cnt, nv) : 0;
#pragma unroll
        for (int k = 0; k < Kst; k++) {
            if (vd[k]) {
                slots[k] = base;
                g_rowmap[base] = bl * Kst + k;
                base++;
            } else slots[k] = -1;
        }
    }
    __syncthreads();
    float inv = 1.f / fmaxf(ssum, 1e-8f);

    float4 wm = make_float4(0.f, 0.f, 0.f, 0.f);
    float4 mx = make_float4(-1e9f, -1e9f, -1e9f, -1e9f);
    bool any = false;
#pragma unroll
    for (int k = 0; k < Kst; k++) {
        swr[k] *= inv;
        if (vd[k]) {
            int role = max(roles[b * Kst + k], 0);
            float4 s4 = *(const float4*)(sr + (((size_t)(b * Kst + k)) * Lseq + l) * Ddim + d0);
            float4 r4 = *(const float4*)(remb + (size_t)role * Ddim + d0);
            float4 xv = make_float4(s4.x + r4.x, s4.y + r4.y, s4.z + r4.z, s4.w + r4.w);
            any = true;
            mx.x = fmaxf(mx.x, xv.x); mx.y = fmaxf(mx.y, xv.y);
            mx.z = fmaxf(mx.z, xv.z); mx.w = fmaxf(mx.w, xv.w);
            __half h0, l0, h1, l1, h2, l2, h3, l3;
            split2h(xv.x, h0, l0); split2h(xv.y, h1, l1);
            split2h(xv.z, h2, l2); split2h(xv.w, h3, l3);
            size_t row = (size_t)slots[k] * 1024;
            *(__half2*)(g_Xs + row + d0)           = __halves2half2(h0, h1);
            *(__half2*)(g_Xs + row + d0 + 2)       = __halves2half2(h2, h3);
            *(__half2*)(g_Xs + row + 512 + d0)     = __halves2half2(l0, l1);
            *(__half2*)(g_Xs + row + 512 + d0 + 2) = __halves2half2(l2, l3);
            wm.x += swr[k] * xv.x; wm.y += swr[k] * xv.y;
            wm.z += swr[k] * xv.z; wm.w += swr[k] * xv.w;
        }
    }
    *(float4*)(dout + OUT_WM + (size_t)bl * Ddim + d0) = wm;
    if (!any) mx = make_float4(0.f, 0.f, 0.f, 0.f);
    *(float4*)(dout + OUT_MF + (size_t)bl * Ddim + d0) = mx;
    if (t < Kst) g_swr[bl * Kst + t] = swr[t];
}

// ---------------- HMMA fp16 GEMM, cp.async 3-stage pipeline, 2 CTAs/SM ----------------
// B index wrap only active when K > ldb (2-term GEMMs); hi-only GEMMs pass ldb = K.
#define STAGES 3
#define GSM_BYTES (STAGES * 32768)

template <int EPI, bool COMPACT>
__global__ void __launch_bounds__(256, 2) gemm_mma(
    const __half* __restrict__ A, const __half* __restrict__ B,
    const float* __restrict__ bias, float* __restrict__ Cf,
    __half* __restrict__ Cb, int K, int ldb, int ldc) {
    int Mv = 0;
    if (COMPACT) {
        Mv = g_cnt;
        int padded = (Mv + 127) & ~127;
        if ((int)(blockIdx.y * 128) >= padded) return;
    }
    extern __shared__ __align__(1024) char smem[];
    uint32_t sA0 = smem_u32(smem);
    int tid = threadIdx.x;
    int wid = tid >> 5, lane = tid & 31;
    const int wm = wid >> 2, wn = wid & 3;

    const size_t bm = (size_t)blockIdx.y * 128;
    const int bn = blockIdx.x * 128;
    const int seg = tid & 7;
    const int r0 = tid >> 3;

    const __half* Ab = A + (bm + r0) * (size_t)K + seg * 8;
    const __half* Bb = B + (size_t)(bn + r0) * ldb + seg * 8;
    const uint32_t swbase = swz(r0 * 128 + seg * 16);

    auto copy_stage = [&](int c, int buf) {
        int kc = c << 6;
        int bkc = (kc >= ldb) ? kc - ldb : kc;
        uint32_t pa = sA0 + buf * 32768 + swbase;
#pragma unroll
        for (int i = 0; i < 4; i++) {
            cp_async16(pa + i * 32 * 128, Ab + (size_t)(i * 32) * K + kc);
            cp_async16(pa + 16384 + i * 32 * 128, Bb + (size_t)(i * 32) * ldb + bkc);
        }
        asm volatile("cp.async.commit_group;" ::: "memory");
    };

    float acc[4][4][4];
#pragma unroll
    for (int i = 0; i < 4; i++)
#pragma unroll
        for (int j = 0; j < 4; j++)
#pragma unroll
            for (int q = 0; q < 4; q++) acc[i][j][q] = 0.f;

    const uint32_t aRow = wm * 64 + (lane & 15);
    const uint32_t aColB = (lane >> 4) << 4;
    const uint32_t bRow = wn * 32 + (lane & 7) + ((lane >> 4) << 3);
    const uint32_t bColB = ((lane >> 3) & 1) << 4;

    const int NC = K >> 6;
#pragma unroll
    for (int s = 0; s < STAGES - 1; s++)
        if (s < NC) copy_stage(s, s);

    for (int c = 0; c < NC; c++) {
        asm volatile("cp.async.wait_group %0;" :: "n"(STAGES - 2));
        __syncthreads();
        if (c + STAGES - 1 < NC) copy_stage(c + STAGES - 1, (c + STAGES - 1) % STAGES);

        uint32_t Abuf = sA0 + (c % STAGES) * 32768;
        uint32_t Bbuf = Abuf + 16384;
#pragma unroll
        for (int ks = 0; ks < 4; ks++) {
            uint32_t a[4][4], b[4][2];
#pragma unroll
            for (int mt = 0; mt < 4; mt++) {
                uint32_t off = (aRow + mt * 16) * 128 + ks * 32 + aColB;
                ldsm_x4(a[mt][0], a[mt][1], a[mt][2], a[mt][3], Abuf + swz(off));
            }
#pragma unroll
            for (int p = 0; p < 2; p++) {
                uint32_t off = (bRow + p * 16) * 128 + ks * 32 + bColB;
                ldsm_x4(b[2 * p][0], b[2 * p][1], b[2 * p + 1][0], b[2 * p + 1][1],
                        Bbuf + swz(off));
            }
#pragma unroll
            for (int mt = 0; mt < 4; mt++)
#pragma unroll
                for (int nt = 0; nt < 4; nt++)
                    mma16816(acc[mt][nt], a[mt], b[nt]);
        }
    }

    // epilogue
    const int g = lane >> 2, t = lane & 3;
#pragma unroll
    for (int mt = 0; mt < 4; mt++) {
#pragma unroll
        for (int half = 0; half < 2; half++) {
            size_t grow = bm + wm * 64 + mt * 16 + g + half * 8;
            size_t orow = grow;
            if (COMPACT) {
                if ((int)grow >= Mv) continue;
                orow = (size_t)g_rowmap[grow];
            }
#pragma unroll
            for (int nt = 0; nt < 4; nt++) {
                int col = bn + wn * 32 + nt * 8 + t * 2;
                float v0 = acc[mt][nt][half * 2 + 0];
                float v1 = acc[mt][nt][half * 2 + 1];
                if (EPI == 0) {
                    float2 o = make_float2(v0, v1);
                    *(float2*)(Cf + orow * (size_t)ldc + col) = o;
                } else if (EPI == 1) {
                    v0 += bias[col];
                    v1 += bias[col + 1];
                    v0 = 0.5f * v0 * (1.f + erff(v0 * 0.70710678118654752f));
                    v1 = 0.5f * v1 * (1.f + erff(v1 * 0.70710678118654752f));
                    // hi-only output for gate path
                    *(__half2*)(Cb + orow * 512 + col) =
                        __halves2half2(__float2half_rn(v0), __float2half_rn(v1));
                } else {
                    v0 += bias[col];
                    v1 += bias[col + 1];
                    float2 o;
                    o.x = 1.f / (1.f + __expf(-v0));
                    o.y = 1.f / (1.f + __expf(-v1));
                    *(float2*)(Cf + orow * 512 + col) = o;
                }
            }
        }
    }
}

// ---------------- attention: 4x4 per (b,l,h); pooled split output + attn_mean ----------------
__global__ void __launch_bounds__(256) attn_kernel(
    const void* __restrict__ rm, const void* __restrict__ pm,
    float* __restrict__ dout) {
    int bl = blockIdx.x;
    int b = bl >> 10;
    int l = bl & 1023;
    int warp = threadIdx.x >> 5;
    int lane = threadIdx.x & 31;
    __shared__ float amp[8][Kst];
    int u8 = g_mask_u8;

    float2 q[Kst], kk[Kst], vv[Kst];
    float ln_w[Kst], swr[Kst];
    bool vd[Kst];
    int col = warp * HDdim + lane * 2;
#pragma unroll
    for (int s = 0; s < Kst; s++) {
        vd[s] = mask_at(rm, (b * Kst + s) * Lseq + l, u8) && mask_at(pm, b * Kst + s, u8);
        if (vd[s]) {
            size_t rbase = (size_t)(bl * Kst + s) * 1536 + col;
            q[s]  = *(const float2*)(g_QKV + rbase);
            kk[s] = *(const float2*)(g_QKV + rbase + 512);
            vv[s] = *(const float2*)(g_QKV + rbase + 1024);
        } else {
            q[s] = kk[s] = vv[s] = make_float2(0.f, 0.f);
        }
        ln_w[s] = g_lognsw[b * Kst + s];
        swr[s]  = g_swr[bl * Kst + s];
    }

    float dot[Kst][Kst];
#pragma unroll
    for (int i = 0; i < Kst; i++) {
#pragma unroll
        for (int j = 0; j < Kst; j++) {
            float p = q[i].x * kk[j].x + q[i].y * kk[j].y;
#pragma unroll
            for (int o = 16; o; o >>= 1) p += __shfl_xor_sync(0xffffffffu, p, o);
            dot[i][j] = p;
        }
    }

    float a[Kst][Kst];
#pragma unroll
    for (int i = 0; i < Kst; i++) {
        float lm[Kst] = {0.f, 0.f, 0.f, 0.f};
        float m = -3.4e38f;
#pragma unroll
        for (int j = 0; j < Kst; j++) {
            if (vd[j]) {
                lm[j] = dot[i][j] * 0.125f + ln_w[j];
                m = fmaxf(m, lm[j]);
            }
        }
        float ssum = 0.f;
#pragma unroll
        for (int j = 0; j < Kst; j++) {
            float e = vd[j] ? __expf(lm[j] - m) : 0.f;
            a[i][j] = e;
            ssum += e;
        }
        float invs = (ssum > 0.f) ? (1.f / ssum) : 0.f;
#pragma unroll
        for (int j = 0; j < Kst; j++) a[i][j] *= invs;
    }

    float px = 0.f, py = 0.f;
#pragma unroll
    for (int i = 0; i < Kst; i++) {
        float ox = 0.f, oy = 0.f;
#pragma unroll
        for (int j = 0; j < Kst; j++) {
            ox += a[i][j] * vv[j].x;
            oy += a[i][j] * vv[j].y;
        }
        px += swr[i] * ox;
        py += swr[i] * oy;
    }
    __half hx, lx, hy, ly;
    split2h(px, hx, lx);
    split2h(py, hy, ly);
    size_t ob = (size_t)bl * 1024 + col;
    *(__half2*)(g_AOs + ob)       = __halves2half2(hx, hy);
    *(__half2*)(g_AOs + ob + 512) = __halves2half2(lx, ly);

    if (lane == 0) {
#pragma unroll
        for (int j = 0; j < Kst; j++)
            amp[warp][j] = a[0][j] + a[1][j] + a[2][j] + a[3][j];
    }
    __syncthreads();
    if (threadIdx.x < Kst) {
        float t = 0.f;
#pragma unroll
        for (int w = 0; w < 8; w++) t += amp[w][threadIdx.x];
        dout[OUT_AM + (size_t)bl * Kst + threadIdx.x] = t * (1.f / 32.f);
    }
}

// ---------------- block reduction ----------------
__device__ __forceinline__ float block_sum(float v, float* red) {
    int lane = threadIdx.x & 31, w = threadIdx.x >> 5;
#pragma unroll
    for (int o = 16; o; o >>= 1) v += __shfl_xor_sync(0xffffffffu, v, o);
    __syncthreads();
    if (lane == 0) red[w] = v;
    __syncthreads();
    if (threadIdx.x == 0) {
        float t = 0.f;
        int nw = (blockDim.x + 31) >> 5;
        for (int i = 0; i < nw; i++) t += red[i];
        red[8] = t;
    }
    __syncthreads();
    return red[8];
}

// ---------------- layernorm of gate_in (1536) -> hi-only fp16, float4 ----------------
__global__ void __launch_bounds__(256) ln_gatein_kernel(
    const float* __restrict__ dro, const float* __restrict__ g,
    const float* __restrict__ bb) {
    int bl = blockIdx.x;
    __shared__ float4 sbuf[384];
    __shared__ float red[9];
    float s = 0.f;
#pragma unroll 2
    for (int i = threadIdx.x; i < 384; i += 256) {
        float4 v;
        if (i < 128)      v = *(const float4*)(dro + OUT_AP + (size_t)bl * Ddim + i * 4);
        else if (i < 256) v = *(const float4*)(dro + OUT_WM + (size_t)bl * Ddim + (i - 128) * 4);
        else              v = *(const float4*)(dro + OUT_MF + (size_t)bl * Ddim + (i - 256) * 4);
        sbuf[i] = v;
        s += v.x + v.y + v.z + v.w;
    }
    s = block_sum(s, red);
    float mu = s * (1.f / D3);
    float sq = 0.f;
#pragma unroll 2
    for (int i = threadIdx.x; i < 384; i += 256) {
        float4 v = sbuf[i];
        float dx = v.x - mu, dy = v.y - mu, dz = v.z - mu, dw = v.w - mu;
        sq += dx * dx + dy * dy + dz * dz + dw * dw;
    }
    sq = block_sum(sq, red);
    float rs = rsqrtf(sq * (1.f / D3) + 1e-5f);
#pragma unroll 2
    for (int i = threadIdx.x; i < 384; i += 256) {
        int c = i * 4;
        float4 v = sbuf[i];
        float4 g4 = *(const float4*)(g + c);
        float4 b4 = *(const float4*)(bb + c);
        float y0 = (v.x - mu) * rs * g4.x + b4.x;
        float y1 = (v.y - mu) * rs * g4.y + b4.y;
        float y2 = (v.z - mu) * rs * g4.z + b4.z;
        float y3 = (v.w - mu) * rs * g4.w + b4.w;
        size_t row = (size_t)bl * 1536;
        *(__half2*)(g_Gs + row + c)     = __halves2half2(__float2half_rn(y0), __float2half_rn(y1));
        *(__half2*)(g_Gs + row + c + 2) = __halves2half2(__float2half_rn(y2), __float2half_rn(y3));
    }
}

// ---------------- final fuse + layernorm(512), float4, 128 threads ----------------
__global__ void __launch_bounds__(128) ln_final_kernel(
    float* __restrict__ dout, const float* __restrict__ ng,
    const float* __restrict__ nb) {
    int bl = blockIdx.x;
    __shared__ float red[9];
    int d0 = threadIdx.x * 4;
    float4 gate = *(const float4*)(g_GATE + (size_t)bl * Ddim + d0);
    float4 ap = *(const float4*)(dout + OUT_AP + (size_t)bl * Ddim + d0);
    float4 wm = *(const float4*)(dout + OUT_WM + (size_t)bl * Ddim + d0);
    float4 mf = *(const float4*)(dout + OUT_MF + (size_t)bl * Ddim + d0);
    float4 y;
    y.x = gate.x * 0.5f * (ap.x + wm.x) + (1.f - gate.x) * mf.x + wm.x;
    y.y = gate.y * 0.5f * (ap.y + wm.y) + (1.f - gate.y) * mf.y + wm.y;
    y.z = gate.z * 0.5f * (ap.z + wm.z) + (1.f - gate.z) * mf.z + wm.z;
    y.w = gate.w * 0.5f * (ap.w + wm.w) + (1.f - gate.w) * mf.w + wm.w;
    float s = block_sum(y.x + y.y + y.z + y.w, red);
    float mu = s * (1.f / Ddim);
    float dx = y.x - mu, dy = y.y - mu, dz = y.z - mu, dw = y.w - mu;
    float sq = block_sum(dx * dx + dy * dy + dz * dz + dw * dw, red);
    float rs = rsqrtf(sq * (1.f / Ddim) + 1e-5f);
    float4 g4 = *(const float4*)(ng + d0);
    float4 b4 = *(const float4*)(nb + d0);
    float4 o;
    o.x = dx * rs * g4.x + b4.x;
    o.y = dy * rs * g4.y + b4.y;
    o.z = dz * rs * g4.z + b4.z;
    o.w = dw * rs * g4.w + b4.w;
    *(float4*)(dout + OUT_FUSED + (size_t)bl * Ddim + d0) = o;
}

// ---------------- launch ----------------
extern "C" void kernel_launch(void* const* d_in, const int* in_sizes, int n_in,
                              void* d_out, int out_size) {
    const float* sr    = (const float*)d_in[0];
    const void*  rmask = d_in[1];
    const float* sw    = (const float*)d_in[2];
    const int*   roles = (const int*)d_in[3];
    const void*  pmask = d_in[4];
    const float* remb  = (const float*)d_in[5];
    const float* Wq    = (const float*)d_in[6];
    const float* Wk    = (const float*)d_in[7];
    const float* Wv    = (const float*)d_in[8];
    const float* Wo    = (const float*)d_in[9];
    const float* ln1g  = (const float*)d_in[10];
    const float* ln1b  = (const float*)d_in[11];
    const float* Wg1   = (const float*)d_in[12];
    const float* bg1   = (const float*)d_in[13];
    const float* Wg2   = (const float*)d_in[14];
    const float* bg2   = (const float*)d_in[15];
    const float* ng    = (const float*)d_in[16];
    const float* nb    = (const float*)d_in[17];
    float* dout = (float*)d_out;

    __half *pXs, *pAOs, *pGs, *pH1s, *pWs1, *pWso, *pWsg1, *pWsg2;
    float *pQKV, *pGATE;
    cudaGetSymbolAddress((void**)&pXs, g_Xs);
    cudaGetSymbolAddress((void**)&pQKV, g_QKV);
    cudaGetSymbolAddress((void**)&pAOs, g_AOs);
    cudaGetSymbolAddress((void**)&pGs, g_Gs);
    cudaGetSymbolAddress((void**)&pH1s, g_H1s);
    cudaGetSymbolAddress((void**)&pGATE, g_GATE);
    cudaGetSymbolAddress((void**)&pWs1, g_Ws1);
    cudaGetSymbolAddress((void**)&pWso, g_Wso);
    cudaGetSymbolAddress((void**)&pWsg1, g_Wsg1);
    cudaGetSymbolAddress((void**)&pWsg2, g_Wsg2);

    cudaFuncSetAttribute(gemm_mma<0, true>,  cudaFuncAttributeMaxDynamicSharedMemorySize, GSM_BYTES);
    cudaFuncSetAttribute(gemm_mma<0, false>, cudaFuncAttributeMaxDynamicSharedMemorySize, GSM_BYTES);
    cudaFuncSetAttribute(gemm_mma<1, false>, cudaFuncAttributeMaxDynamicSharedMemorySize, GSM_BYTES);
    cudaFuncSetAttribute(gemm_mma<2, false>, cudaFuncAttributeMaxDynamicSharedMemorySize, GSM_BYTES);

    detnsw_kernel<<<1, 256>>>(rmask, sw, pmask, dout + OUT_NSW);
    build_split_kernel<<<BLn + WSPLIT_BLOCKS, 128>>>(sr, rmask, pmask, roles, remb, dout,
                                                     Wq, Wk, Wv, Wo, Wg2, Wg1,
                                                     pWs1, pWso, pWsg2, pWsg1);

    // fused QKV on compacted rows: [Mv x 1536] = Xs([hi|lo], K'=1024) @ Ws1(hi, ldb=512)^T
    {
        dim3 grid(1536 / 128, Tn / 128);
        gemm_mma<0, true><<<grid, 256, GSM_BYTES>>>(pXs, pWs1, nullptr, pQKV, nullptr, 1024, 512, 1536);
    }

    attn_kernel<<<BLn, 256>>>(rmask, pmask, dout);

    // attn_pooled = AOs @ Wso^T  [8192 x 512] (2-term)
    {
        dim3 grid(512 / 128, BLn / 128);
        gemm_mma<0, false><<<grid, 256, GSM_BYTES>>>(pAOs, pWso, nullptr, dout + OUT_AP, nullptr, 1024, 512, 512);
    }

    ln_gatein_kernel<<<BLn, 256>>>(dout, ln1g, ln1b);

    // h = gelu(Gs @ Wsg1^T + bg1), hi-only (K=1536, no wrap)
    {
        dim3 grid(512 / 128, BLn / 128);
        gemm_mma<1, false><<<grid, 256, GSM_BYTES>>>(pGs, pWsg1, bg1, nullptr, pH1s, 1536, 1536, 0);
    }
    // gate = sigmoid(H1s @ Wsg2^T + bg2), hi-only (K=512, no wrap)
    {
        dim3 grid(512 / 128, BLn / 128);
        gemm_mma<2, false><<<grid, 256, GSM_BYTES>>>(pH1s, pWsg2, bg2, pGATE, nullptr, 512, 512, 0);
    }

    ln_final_kernel<<<BLn, 128>>>(dout, ng, nb);
}

// round 15
// speedup vs baseline: 1.9535x; 1.0306x over previous
#include <cuda_runtime.h>
#include <cuda_fp16.h>
#include <math.h>
#include <stdint.h>

// ---------------- problem constants ----------------
#define Bdim 8
#define Kst 4
#define Lseq 1024
#define Ddim 512
#define Hn 8
#define HDdim 64
#define BLn 8192
#define Tn 32768
#define D3 1536

#define OUT_FUSED 0
#define OUT_AP    4194304
#define OUT_WM    8388608
#define OUT_MF    12582912
#define OUT_AM    16777216
#define OUT_NSW   16809984

// ---------------- device scratch ----------------
// QKV GEMM: fp16 2-term split (A [hi|lo], B hi with index wrap) — dominant error path.
// Wo / Wg1 / Wg2 GEMMs: hi-only fp16 (1-term) — sub-dominant error paths.
__device__ __half g_Xs[(size_t)Tn * 1024];
__device__ float  g_QKV[(size_t)Tn * 1536];
__device__ __half g_AOs[(size_t)BLn * 512];    // hi only
__device__ __half g_Gs[(size_t)BLn * 1536];    // hi only
__device__ __half g_H1s[(size_t)BLn * 512];    // hi only
__device__ float  g_GATE[(size_t)BLn * Ddim];
__device__ __half g_Ws1[1536 * 512];
__device__ __half g_Wso[512 * 512];
__device__ __half g_Wsg1[512 * 1536];
__device__ __half g_Wsg2[512 * 512];
__device__ float g_swr[BLn * Kst];
__device__ float g_nsw[Bdim * Kst];
__device__ float g_lognsw[Bdim * Kst];
__device__ int   g_mask_u8;
__device__ int   g_cnt;
__device__ int   g_rowmap[Tn];

// ---------------- helpers ----------------
__device__ __forceinline__ uint32_t smem_u32(const void* p) {
    uint32_t a;
    asm("{ .reg .u64 t; cvta.to.shared.u64 t, %1; cvt.u32.u64 %0, t; }" : "=r"(a) : "l"(p));
    return a;
}
__device__ __forceinline__ void split2h(float v, __half& hi, __half& lo) {
    hi = __float2half_rn(v);
    lo = __float2half_rn(v - __half2float(hi));
}
__device__ __forceinline__ void ldsm_x4(uint32_t& r0, uint32_t& r1, uint32_t& r2,
                                        uint32_t& r3, uint32_t addr) {
    asm volatile("ldmatrix.sync.aligned.m8n8.x4.shared.b16 {%0,%1,%2,%3}, [%4];"
                 : "=r"(r0), "=r"(r1), "=r"(r2), "=r"(r3) : "r"(addr));
}
__device__ __forceinline__ void mma16816(float* c, const uint32_t* a, const uint32_t* b) {
    asm volatile(
        "mma.sync.aligned.m16n8k16.row.col.f32.f16.f16.f32 "
        "{%0,%1,%2,%3}, {%4,%5,%6,%7}, {%8,%9}, {%0,%1,%2,%3};"
        : "+f"(c[0]), "+f"(c[1]), "+f"(c[2]), "+f"(c[3])
        : "r"(a[0]), "r"(a[1]), "r"(a[2]), "r"(a[3]), "r"(b[0]), "r"(b[1]));
}
__device__ __forceinline__ uint32_t swz(uint32_t off) {
    return off ^ ((off >> 3) & 0x70);
}
__device__ __forceinline__ void cp_async16(uint32_t dst, const void* src) {
    asm volatile("cp.async.cg.shared.global [%0], [%1], 16;" :: "r"(dst), "l"(src));
}
__device__ __forceinline__ bool mask_at(const void* p, int idx, int u8) {
    return u8 ? (((const unsigned char*)p)[idx] != 0) : (((const int*)p)[idx] != 0);
}

// ---------------- fused mask-detect + nsw ----------------
__global__ void detnsw_kernel(const void* __restrict__ rm, const float* __restrict__ sw,
                              const void* __restrict__ pm, float* __restrict__ out_nsw) {
    __shared__ int s_u8;
    const int* p = (const int*)rm;
    int bad = 0;
    for (int i = threadIdx.x; i < 8192; i += 256) {
        int v = p[i];
        if (v != 0 && v != 1) bad = 1;
    }
    bad = __syncthreads_or(bad);
    if (threadIdx.x == 0) {
        g_mask_u8 = bad;
        g_cnt = 0;
        s_u8 = bad;
    }
    __syncthreads();
    int b = threadIdx.x;
    if (b >= Bdim) return;
    int u8 = s_u8;
    float w[Kst], pres[Kst];
    float denom = 0.f, psum = 0.f;
#pragma unroll
    for (int k = 0; k < Kst; k++) {
        pres[k] = mask_at(pm, b * Kst + k, u8) ? 1.f : 0.f;
        w[k] = sw[b * Kst + k] * pres[k];
        denom += w[k];
        psum += pres[k];
    }
#pragma unroll
    for (int k = 0; k < Kst; k++) {
        float nswk = (denom > 1e-8f) ? (w[k] / fmaxf(denom, 1e-8f))
                                     : (pres[k] / fmaxf(psum, 1.f));
        g_nsw[b * Kst + k] = nswk;
        g_lognsw[b * Kst + k] = logf(fmaxf(nswk, 1e-8f));
        out_nsw[b * Kst + k] = nswk;
    }
}

// ---------------- fused build-x + weight convert (blockDim 128) ----------------
#define WSPLIT_BLOCKS 16384

__global__ void __launch_bounds__(128) build_split_kernel(
    const float* __restrict__ sr, const void* __restrict__ rm,
    const void* __restrict__ pm, const int* __restrict__ roles,
    const float* __restrict__ remb, float* __restrict__ dout,
    const float* __restrict__ Wq, const float* __restrict__ Wk,
    const float* __restrict__ Wv, const float* __restrict__ Wo,
    const float* __restrict__ Wg2, const float* __restrict__ Wg1,
    __half* __restrict__ oWs1, __half* __restrict__ oWso,
    __half* __restrict__ oWsg2, __half* __restrict__ oWsg1) {
    if (blockIdx.x >= BLn) {
        int idx = (blockIdx.x - BLn) * 128 + threadIdx.x;
        const float* W;
        __half* out;
        int e;
        if (idx < 262144)        { W = Wq;  out = oWs1;                      e = idx; }
        else if (idx < 524288)   { W = Wk;  out = oWs1 + (size_t)512 * 512;  e = idx - 262144; }
        else if (idx < 786432)   { W = Wv;  out = oWs1 + (size_t)1024 * 512; e = idx - 524288; }
        else if (idx < 1048576)  { W = Wo;  out = oWso;                      e = idx - 786432; }
        else if (idx < 1310720)  { W = Wg2; out = oWsg2;                     e = idx - 1048576; }
        else                     { W = Wg1; out = oWsg1;                     e = idx - 1310720; }
        out[e] = __float2half_rn(W[e]);
        return;
    }
    // ---- build-x path: 128 threads x 4 dims ----
    int bl = blockIdx.x;
    int b = bl >> 10;
    int l = bl & 1023;
    int t = threadIdx.x;
    int d0 = t * 4;
    int u8 = g_mask_u8;
    __shared__ int slots[Kst];

    bool vd[Kst];
    float swr[Kst];
    float ssum = 0.f;
#pragma unroll
    for (int k = 0; k < Kst; k++) {
        bool v = mask_at(rm, (b * Kst + k) * Lseq + l, u8) && mask_at(pm, b * Kst + k, u8);
        vd[k] = v;
        swr[k] = v ? g_nsw[b * Kst + k] : 0.f;
        ssum += swr[k];
    }
    if (t == 0) {
        int nv = 0;
#pragma unroll
        for (int k = 0; k < Kst; k++) nv += vd[k] ? 1 : 0;
        int base = nv ? atomicAdd(&g_cnt, nv) : 0;
#pragma unroll
        for (int k = 0; k < Kst; k++) {
            if (vd[k]) {
                slots[k] = base;
                g_rowmap[base] = bl * Kst + k;
                base++;
            } else slots[k] = -1;
        }
    }
    __syncthreads();
    float inv = 1.f / fmaxf(ssum, 1e-8f);

    float4 wm = make_float4(0.f, 0.f, 0.f, 0.f);
    float4 mx = make_float4(-1e9f, -1e9f, -1e9f, -1e9f);
    bool any = false;
#pragma unroll
    for (int k = 0; k < Kst; k++) {
        swr[k] *= inv;
        if (vd[k]) {
            int role = max(roles[b * Kst + k], 0);
            float4 s4 = *(const float4*)(sr + (((size_t)(b * Kst + k)) * Lseq + l) * Ddim + d0);
            float4 r4 = *(const float4*)(remb + (size_t)role * Ddim + d0);
            float4 xv = make_float4(s4.x + r4.x, s4.y + r4.y, s4.z + r4.z, s4.w + r4.w);
            any = true;
            mx.x = fmaxf(mx.x, xv.x); mx.y = fmaxf(mx.y, xv.y);
            mx.z = fmaxf(mx.z, xv.z); mx.w = fmaxf(mx.w, xv.w);
            __half h0, l0, h1, l1, h2, l2, h3, l3;
            split2h(xv.x, h0, l0); split2h(xv.y, h1, l1);
            split2h(xv.z, h2, l2); split2h(xv.w, h3, l3);
            size_t row = (size_t)slots[k] * 1024;
            *(__half2*)(g_Xs + row + d0)           = __halves2half2(h0, h1);
            *(__half2*)(g_Xs + row + d0 + 2)       = __halves2half2(h2, h3);
            *(__half2*)(g_Xs + row + 512 + d0)     = __halves2half2(l0, l1);
            *(__half2*)(g_Xs + row + 512 + d0 + 2) = __halves2half2(l2, l3);
            wm.x += swr[k] * xv.x; wm.y += swr[k] * xv.y;
            wm.z += swr[k] * xv.z; wm.w += swr[k] * xv.w;
        }
    }
    *(float4*)(dout + OUT_WM + (size_t)bl * Ddim + d0) = wm;
    if (!any) mx = make_float4(0.f, 0.f, 0.f, 0.f);
    *(float4*)(dout + OUT_MF + (size_t)bl * Ddim + d0) = mx;
    if (t < Kst) g_swr[bl * Kst + t] = swr[t];
}

// ---------------- HMMA fp16 GEMM, cp.async 3-stage pipeline, 2 CTAs/SM ----------------
// B index wrap only active when K > ldb (2-term GEMMs); hi-only GEMMs pass ldb = K.
#define STAGES 3
#define GSM_BYTES (STAGES * 32768)

template <int EPI, bool COMPACT>
__global__ void __launch_bounds__(256, 2) gemm_mma(
    const __half* __restrict__ A, const __half* __restrict__ B,
    const float* __restrict__ bias, float* __restrict__ Cf,
    __half* __restrict__ Cb, int K, int ldb, int ldc) {
    int Mv = 0;
    if (COMPACT) {
        Mv = g_cnt;
        int padded = (Mv + 127) & ~127;
        if ((int)(blockIdx.y * 128) >= padded) return;
    }
    extern __shared__ __align__(1024) char smem[];
    uint32_t sA0 = smem_u32(smem);
    int tid = threadIdx.x;
    int wid = tid >> 5, lane = tid & 31;
    const int wm = wid >> 2, wn = wid & 3;

    const size_t bm = (size_t)blockIdx.y * 128;
    const int bn = blockIdx.x * 128;
    const int seg = tid & 7;
    const int r0 = tid >> 3;

    const __half* Ab = A + (bm + r0) * (size_t)K + seg * 8;
    const __half* Bb = B + (size_t)(bn + r0) * ldb + seg * 8;
    const uint32_t swbase = swz(r0 * 128 + seg * 16);

    auto copy_stage = [&](int c, int buf) {
        int kc = c << 6;
        int bkc = (kc >= ldb) ? kc - ldb : kc;
        uint32_t pa = sA0 + buf * 32768 + swbase;
#pragma unroll
        for (int i = 0; i < 4; i++) {
            cp_async16(pa + i * 32 * 128, Ab + (size_t)(i * 32) * K + kc);
            cp_async16(pa + 16384 + i * 32 * 128, Bb + (size_t)(i * 32) * ldb + bkc);
        }
        asm volatile("cp.async.commit_group;" ::: "memory");
    };

    float acc[4][4][4];
#pragma unroll
    for (int i = 0; i < 4; i++)
#pragma unroll
        for (int j = 0; j < 4; j++)
#pragma unroll
            for (int q = 0; q < 4; q++) acc[i][j][q] = 0.f;

    const uint32_t aRow = wm * 64 + (lane & 15);
    const uint32_t aColB = (lane >> 4) << 4;
    const uint32_t bRow = wn * 32 + (lane & 7) + ((lane >> 4) << 3);
    const uint32_t bColB = ((lane >> 3) & 1) << 4;

    const int NC = K >> 6;
#pragma unroll
    for (int s = 0; s < STAGES - 1; s++)
        if (s < NC) copy_stage(s, s);

    for (int c = 0; c < NC; c++) {
        asm volatile("cp.async.wait_group %0;" :: "n"(STAGES - 2));
        __syncthreads();
        if (c + STAGES - 1 < NC) copy_stage(c + STAGES - 1, (c + STAGES - 1) % STAGES);

        uint32_t Abuf = sA0 + (c % STAGES) * 32768;
        uint32_t Bbuf = Abuf + 16384;
#pragma unroll
        for (int ks = 0; ks < 4; ks++) {
            uint32_t a[4][4], b[4][2];
#pragma unroll
            for (int mt = 0; mt < 4; mt++) {
                uint32_t off = (aRow + mt * 16) * 128 + ks * 32 + aColB;
                ldsm_x4(a[mt][0], a[mt][1], a[mt][2], a[mt][3], Abuf + swz(off));
            }
#pragma unroll
            for (int p = 0; p < 2; p++) {
                uint32_t off = (bRow + p * 16) * 128 + ks * 32 + bColB;
                ldsm_x4(b[2 * p][0], b[2 * p][1], b[2 * p + 1][0], b[2 * p + 1][1],
                        Bbuf + swz(off));
            }
#pragma unroll
            for (int mt = 0; mt < 4; mt++)
#pragma unroll
                for (int nt = 0; nt < 4; nt++)
                    mma16816(acc[mt][nt], a[mt], b[nt]);
        }
    }

    // epilogue
    const int g = lane >> 2, t = lane & 3;
#pragma unroll
    for (int mt = 0; mt < 4; mt++) {
#pragma unroll
        for (int half = 0; half < 2; half++) {
            size_t grow = bm + wm * 64 + mt * 16 + g + half * 8;
            size_t orow = grow;
            if (COMPACT) {
                if ((int)grow >= Mv) continue;
                orow = (size_t)g_rowmap[grow];
            }
#pragma unroll
            for (int nt = 0; nt < 4; nt++) {
                int col = bn + wn * 32 + nt * 8 + t * 2;
                float v0 = acc[mt][nt][half * 2 + 0];
                float v1 = acc[mt][nt][half * 2 + 1];
                if (EPI == 0) {
                    float2 o = make_float2(v0, v1);
                    *(float2*)(Cf + orow * (size_t)ldc + col) = o;
                } else if (EPI == 1) {
                    v0 += bias[col];
                    v1 += bias[col + 1];
                    v0 = 0.5f * v0 * (1.f + erff(v0 * 0.70710678118654752f));
                    v1 = 0.5f * v1 * (1.f + erff(v1 * 0.70710678118654752f));
                    *(__half2*)(Cb + orow * 512 + col) =
                        __halves2half2(__float2half_rn(v0), __float2half_rn(v1));
                } else {
                    v0 += bias[col];
                    v1 += bias[col + 1];
                    float2 o;
                    o.x = 1.f / (1.f + __expf(-v0));
                    o.y = 1.f / (1.f + __expf(-v1));
                    *(float2*)(Cf + orow * 512 + col) = o;
                }
            }
        }
    }
}

// ---------------- attention: 4x4 per (b,l,h); pooled hi-only output + attn_mean ----------------
__global__ void __launch_bounds__(256) attn_kernel(
    const void* __restrict__ rm, const void* __restrict__ pm,
    float* __restrict__ dout) {
    int bl = blockIdx.x;
    int b = bl >> 10;
    int l = bl & 1023;
    int warp = threadIdx.x >> 5;
    int lane = threadIdx.x & 31;
    __shared__ float amp[8][Kst];
    int u8 = g_mask_u8;

    float2 q[Kst], kk[Kst], vv[Kst];
    float ln_w[Kst], swr[Kst];
    bool vd[Kst];
    int col = warp * HDdim + lane * 2;
#pragma unroll
    for (int s = 0; s < Kst; s++) {
        vd[s] = mask_at(rm, (b * Kst + s) * Lseq + l, u8) && mask_at(pm, b * Kst + s, u8);
        if (vd[s]) {
            size_t rbase = (size_t)(bl * Kst + s) * 1536 + col;
            q[s]  = *(const float2*)(g_QKV + rbase);
            kk[s] = *(const float2*)(g_QKV + rbase + 512);
            vv[s] = *(const float2*)(g_QKV + rbase + 1024);
        } else {
            q[s] = kk[s] = vv[s] = make_float2(0.f, 0.f);
        }
        ln_w[s] = g_lognsw[b * Kst + s];
        swr[s]  = g_swr[bl * Kst + s];
    }

    float dot[Kst][Kst];
#pragma unroll
    for (int i = 0; i < Kst; i++) {
#pragma unroll
        for (int j = 0; j < Kst; j++) {
            float p = q[i].x * kk[j].x + q[i].y * kk[j].y;
#pragma unroll
            for (int o = 16; o; o >>= 1) p += __shfl_xor_sync(0xffffffffu, p, o);
            dot[i][j] = p;
        }
    }

    float a[Kst][Kst];
#pragma unroll
    for (int i = 0; i < Kst; i++) {
        float lm[Kst] = {0.f, 0.f, 0.f, 0.f};
        float m = -3.4e38f;
#pragma unroll
        for (int j = 0; j < Kst; j++) {
            if (vd[j]) {
                lm[j] = dot[i][j] * 0.125f + ln_w[j];
                m = fmaxf(m, lm[j]);
            }
        }
        float ssum = 0.f;
#pragma unroll
        for (int j = 0; j < Kst; j++) {
            float e = vd[j] ? __expf(lm[j] - m) : 0.f;
            a[i][j] = e;
            ssum += e;
        }
        float invs = (ssum > 0.f) ? (1.f / ssum) : 0.f;
#pragma unroll
        for (int j = 0; j < Kst; j++) a[i][j] *= invs;
    }

    float px = 0.f, py = 0.f;
#pragma unroll
    for (int i = 0; i < Kst; i++) {
        float ox = 0.f, oy = 0.f;
#pragma unroll
        for (int j = 0; j < Kst; j++) {
            ox += a[i][j] * vv[j].x;
            oy += a[i][j] * vv[j].y;
        }
        px += swr[i] * ox;
        py += swr[i] * oy;
    }
    // hi-only pooled output
    *(__half2*)(g_AOs + (size_t)bl * 512 + col) =
        __halves2half2(__float2half_rn(px), __float2half_rn(py));

    if (lane == 0) {
#pragma unroll
        for (int j = 0; j < Kst; j++)
            amp[warp][j] = a[0][j] + a[1][j] + a[2][j] + a[3][j];
    }
    __syncthreads();
    if (threadIdx.x < Kst) {
        float t = 0.f;
#pragma unroll
        for (int w = 0; w < 8; w++) t += amp[w][threadIdx.x];
        dout[OUT_AM + (size_t)bl * Kst + threadIdx.x] = t * (1.f / 32.f);
    }
}

// ---------------- block reduction ----------------
__device__ __forceinline__ float block_sum(float v, float* red) {
    int lane = threadIdx.x & 31, w = threadIdx.x >> 5;
#pragma unroll
    for (int o = 16; o; o >>= 1) v += __shfl_xor_sync(0xffffffffu, v, o);
    __syncthreads();
    if (lane == 0) red[w] = v;
    __syncthreads();
    if (threadIdx.x == 0) {
        float t = 0.f;
        int nw = (blockDim.x + 31) >> 5;
        for (int i = 0; i < nw; i++) t += red[i];
        red[8] = t;
    }
    __syncthreads();
    return red[8];
}

// ---------------- layernorm of gate_in (1536) -> hi-only fp16, float4 ----------------
__global__ void __launch_bounds__(256) ln_gatein_kernel(
    const float* __restrict__ dro, const float* __restrict__ g,
    const float* __restrict__ bb) {
    int bl = blockIdx.x;
    __shared__ float4 sbuf[384];
    __shared__ float red[9];
    float s = 0.f;
#pragma unroll 2
    for (int i = threadIdx.x; i < 384; i += 256) {
        float4 v;
        if (i < 128)      v = *(const float4*)(dro + OUT_AP + (size_t)bl * Ddim + i * 4);
        else if (i < 256) v = *(const float4*)(dro + OUT_WM + (size_t)bl * Ddim + (i - 128) * 4);
        else              v = *(const float4*)(dro + OUT_MF + (size_t)bl * Ddim + (i - 256) * 4);
        sbuf[i] = v;
        s += v.x + v.y + v.z + v.w;
    }
    s = block_sum(s, red);
    float mu = s * (1.f / D3);
    float sq = 0.f;
#pragma unroll 2
    for (int i = threadIdx.x; i < 384; i += 256) {
        float4 v = sbuf[i];
        float dx = v.x - mu, dy = v.y - mu, dz = v.z - mu, dw = v.w - mu;
        sq += dx * dx + dy * dy + dz * dz + dw * dw;
    }
    sq = block_sum(sq, red);
    float rs = rsqrtf(sq * (1.f / D3) + 1e-5f);
#pragma unroll 2
    for (int i = threadIdx.x; i < 384; i += 256) {
        int c = i * 4;
        float4 v = sbuf[i];
        float4 g4 = *(const float4*)(g + c);
        float4 b4 = *(const float4*)(bb + c);
        float y0 = (v.x - mu) * rs * g4.x + b4.x;
        float y1 = (v.y - mu) * rs * g4.y + b4.y;
        float y2 = (v.z - mu) * rs * g4.z + b4.z;
        float y3 = (v.w - mu) * rs * g4.w + b4.w;
        size_t row = (size_t)bl * 1536;
        *(__half2*)(g_Gs + row + c)     = __halves2half2(__float2half_rn(y0), __float2half_rn(y1));
        *(__half2*)(g_Gs + row + c + 2) = __halves2half2(__float2half_rn(y2), __float2half_rn(y3));
    }
}

// ---------------- final fuse + layernorm(512), float4, 128 threads ----------------
__global__ void __launch_bounds__(128) ln_final_kernel(
    float* __restrict__ dout, const float* __restrict__ ng,
    const float* __restrict__ nb) {
    int bl = blockIdx.x;
    __shared__ float red[9];
    int d0 = threadIdx.x * 4;
    float4 gate = *(const float4*)(g_GATE + (size_t)bl * Ddim + d0);
    float4 ap = *(const float4*)(dout + OUT_AP + (size_t)bl * Ddim + d0);
    float4 wm = *(const float4*)(dout + OUT_WM + (size_t)bl * Ddim + d0);
    float4 mf = *(const float4*)(dout + OUT_MF + (size_t)bl * Ddim + d0);
    float4 y;
    y.x = gate.x * 0.5f * (ap.x + wm.x) + (1.f - gate.x) * mf.x + wm.x;
    y.y = gate.y * 0.5f * (ap.y + wm.y) + (1.f - gate.y) * mf.y + wm.y;
    y.z = gate.z * 0.5f * (ap.z + wm.z) + (1.f - gate.z) * mf.z + wm.z;
    y.w = gate.w * 0.5f * (ap.w + wm.w) + (1.f - gate.w) * mf.w + wm.w;
    float s = block_sum(y.x + y.y + y.z + y.w, red);
    float mu = s * (1.f / Ddim);
    float dx = y.x - mu, dy = y.y - mu, dz = y.z - mu, dw = y.w - mu;
    float sq = block_sum(dx * dx + dy * dy + dz * dz + dw * dw, red);
    float rs = rsqrtf(sq * (1.f / Ddim) + 1e-5f);
    float4 g4 = *(const float4*)(ng + d0);
    float4 b4 = *(const float4*)(nb + d0);
    float4 o;
    o.x = dx * rs * g4.x + b4.x;
    o.y = dy * rs * g4.y + b4.y;
    o.z = dz * rs * g4.z + b4.z;
    o.w = dw * rs * g4.w + b4.w;
    *(float4*)(dout + OUT_FUSED + (size_t)bl * Ddim + d0) = o;
}

// ---------------- launch ----------------
extern "C" void kernel_launch(void* const* d_in, const int* in_sizes, int n_in,
                              void* d_out, int out_size) {
    const float* sr    = (const float*)d_in[0];
    const void*  rmask = d_in[1];
    const float* sw    = (const float*)d_in[2];
    const int*   roles = (const int*)d_in[3];
    const void*  pmask = d_in[4];
    const float* remb  = (const float*)d_in[5];
    const float* Wq    = (const float*)d_in[6];
    const float* Wk    = (const float*)d_in[7];
    const float* Wv    = (const float*)d_in[8];
    const float* Wo    = (const float*)d_in[9];
    const float* ln1g  = (const float*)d_in[10];
    const float* ln1b  = (const float*)d_in[11];
    const float* Wg1   = (const float*)d_in[12];
    const float* bg1   = (const float*)d_in[13];
    const float* Wg2   = (const float*)d_in[14];
    const float* bg2   = (const float*)d_in[15];
    const float* ng    = (const float*)d_in[16];
    const float* nb    = (const float*)d_in[17];
    float* dout = (float*)d_out;

    __half *pXs, *pAOs, *pGs, *pH1s, *pWs1, *pWso, *pWsg1, *pWsg2;
    float *pQKV, *pGATE;
    cudaGetSymbolAddress((void**)&pXs, g_Xs);
    cudaGetSymbolAddress((void**)&pQKV, g_QKV);
    cudaGetSymbolAddress((void**)&pAOs, g_AOs);
    cudaGetSymbolAddress((void**)&pGs, g_Gs);
    cudaGetSymbolAddress((void**)&pH1s, g_H1s);
    cudaGetSymbolAddress((void**)&pGATE, g_GATE);
    cudaGetSymbolAddress((void**)&pWs1, g_Ws1);
    cudaGetSymbolAddress((void**)&pWso, g_Wso);
    cudaGetSymbolAddress((void**)&pWsg1, g_Wsg1);
    cudaGetSymbolAddress((void**)&pWsg2, g_Wsg2);

    cudaFuncSetAttribute(gemm_mma<0, true>,  cudaFuncAttributeMaxDynamicSharedMemorySize, GSM_BYTES);
    cudaFuncSetAttribute(gemm_mma<0, false>, cudaFuncAttributeMaxDynamicSharedMemorySize, GSM_BYTES);
    cudaFuncSetAttribute(gemm_mma<1, false>, cudaFuncAttributeMaxDynamicSharedMemorySize, GSM_BYTES);
    cudaFuncSetAttribute(gemm_mma<2, false>, cudaFuncAttributeMaxDynamicSharedMemorySize, GSM_BYTES);

    detnsw_kernel<<<1, 256>>>(rmask, sw, pmask, dout + OUT_NSW);
    build_split_kernel<<<BLn + WSPLIT_BLOCKS, 128>>>(sr, rmask, pmask, roles, remb, dout,
                                                     Wq, Wk, Wv, Wo, Wg2, Wg1,
                                                     pWs1, pWso, pWsg2, pWsg1);

    // fused QKV on compacted rows: [Mv x 1536] = Xs([hi|lo], K'=1024) @ Ws1(hi, ldb=512)^T
    {
        dim3 grid(1536 / 128, Tn / 128);
        gemm_mma<0, true><<<grid, 256, GSM_BYTES>>>(pXs, pWs1, nullptr, pQKV, nullptr, 1024, 512, 1536);
    }

    attn_kernel<<<BLn, 256>>>(rmask, pmask, dout);

    // attn_pooled = AOs @ Wso^T  [8192 x 512], hi-only (K=512, no wrap)
    {
        dim3 grid(512 / 128, BLn / 128);
        gemm_mma<0, false><<<grid, 256, GSM_BYTES>>>(pAOs, pWso, nullptr, dout + OUT_AP, nullptr, 512, 512, 512);
    }

    ln_gatein_kernel<<<BLn, 256>>>(dout, ln1g, ln1b);

    // h = gelu(Gs @ Wsg1^T + bg1), hi-only (K=1536, no wrap)
    {
        dim3 grid(512 / 128, BLn / 128);
        gemm_mma<1, false><<<grid, 256, GSM_BYTES>>>(pGs, pWsg1, bg1, nullptr, pH1s, 1536, 1536, 0);
    }
    // gate = sigmoid(H1s @ Wsg2^T + bg2), hi-only (K=512, no wrap)
    {
        dim3 grid(512 / 128, BLn / 128);
        gemm_mma<2, false><<<grid, 256, GSM_BYTES>>>(pH1s, pWsg2, bg2, pGATE, nullptr, 512, 512, 0);
    }

    ln_final_kernel<<<BLn, 128>>>(dout, ng, nb);
}

// round 16
// speedup vs baseline: 1.9883x; 1.0178x over previous
#include <cuda_runtime.h>
#include <cuda_fp16.h>
#include <math.h>
#include <stdint.h>

// ---------------- problem constants ----------------
#define Bdim 8
#define Kst 4
#define Lseq 1024
#define Ddim 512
#define Hn 8
#define HDdim 64
#define BLn 8192
#define Tn 32768
#define D3 1536

#define OUT_FUSED 0
#define OUT_AP    4194304
#define OUT_WM    8388608
#define OUT_MF    12582912
#define OUT_AM    16777216
#define OUT_NSW   16809984

// ---------------- device scratch ----------------
// QKV GEMM: fp16 2-term split (A [hi|lo], B hi with index wrap) — dominant error path.
// q,k outputs fp32 (feed logits); v output fp16 (feeds already-fp16-rounded pooled path).
// Wo / Wg1 / Wg2 GEMMs: hi-only fp16.
__device__ __half g_Xs[(size_t)Tn * 1024];
__device__ float  g_QKV[(size_t)Tn * 1024];    // q,k fp32
__device__ __half g_Vh[(size_t)Tn * 512];      // v fp16
__device__ __half g_AOs[(size_t)BLn * 512];
__device__ __half g_Gs[(size_t)BLn * 1536];
__device__ __half g_H1s[(size_t)BLn * 512];
__device__ float  g_GATE[(size_t)BLn * Ddim];
__device__ __half g_Ws1[1536 * 512];
__device__ __half g_Wso[512 * 512];
__device__ __half g_Wsg1[512 * 1536];
__device__ __half g_Wsg2[512 * 512];
__device__ float g_swr[BLn * Kst];
__device__ float g_nsw[Bdim * Kst];
__device__ float g_lognsw[Bdim * Kst];
__device__ int   g_vbits[BLn];
__device__ int   g_mask_u8;
__device__ int   g_cnt;
__device__ int   g_rowmap[Tn];

// ---------------- helpers ----------------
__device__ __forceinline__ uint32_t smem_u32(const void* p) {
    uint32_t a;
    asm("{ .reg .u64 t; cvta.to.shared.u64 t, %1; cvt.u32.u64 %0, t; }" : "=r"(a) : "l"(p));
    return a;
}
__device__ __forceinline__ void split2h(float v, __half& hi, __half& lo) {
    hi = __float2half_rn(v);
    lo = __float2half_rn(v - __half2float(hi));
}
__device__ __forceinline__ void ldsm_x4(uint32_t& r0, uint32_t& r1, uint32_t& r2,
                                        uint32_t& r3, uint32_t addr) {
    asm volatile("ldmatrix.sync.aligned.m8n8.x4.shared.b16 {%0,%1,%2,%3}, [%4];"
                 : "=r"(r0), "=r"(r1), "=r"(r2), "=r"(r3) : "r"(addr));
}
__device__ __forceinline__ void mma16816(float* c, const uint32_t* a, const uint32_t* b) {
    asm volatile(
        "mma.sync.aligned.m16n8k16.row.col.f32.f16.f16.f32 "
        "{%0,%1,%2,%3}, {%4,%5,%6,%7}, {%8,%9}, {%0,%1,%2,%3};"
        : "+f"(c[0]), "+f"(c[1]), "+f"(c[2]), "+f"(c[3])
        : "r"(a[0]), "r"(a[1]), "r"(a[2]), "r"(a[3]), "r"(b[0]), "r"(b[1]));
}
__device__ __forceinline__ uint32_t swz(uint32_t off) {
    return off ^ ((off >> 3) & 0x70);
}
__device__ __forceinline__ void cp_async16(uint32_t dst, const void* src) {
    asm volatile("cp.async.cg.shared.global [%0], [%1], 16;" :: "r"(dst), "l"(src));
}
__device__ __forceinline__ bool mask_at(const void* p, int idx, int u8) {
    return u8 ? (((const unsigned char*)p)[idx] != 0) : (((const int*)p)[idx] != 0);
}

// ---------------- fused mask-detect + nsw ----------------
__global__ void detnsw_kernel(const void* __restrict__ rm, const float* __restrict__ sw,
                              const void* __restrict__ pm, float* __restrict__ out_nsw) {
    __shared__ int s_u8;
    const int* p = (const int*)rm;
    int bad = 0;
    for (int i = threadIdx.x; i < 8192; i += 256) {
        int v = p[i];
        if (v != 0 && v != 1) bad = 1;
    }
    bad = __syncthreads_or(bad);
    if (threadIdx.x == 0) {
        g_mask_u8 = bad;
        g_cnt = 0;
        s_u8 = bad;
    }
    __syncthreads();
    int b = threadIdx.x;
    if (b >= Bdim) return;
    int u8 = s_u8;
    float w[Kst], pres[Kst];
    float denom = 0.f, psum = 0.f;
#pragma unroll
    for (int k = 0; k < Kst; k++) {
        pres[k] = mask_at(pm, b * Kst + k, u8) ? 1.f : 0.f;
        w[k] = sw[b * Kst + k] * pres[k];
        denom += w[k];
        psum += pres[k];
    }
#pragma unroll
    for (int k = 0; k < Kst; k++) {
        float nswk = (denom > 1e-8f) ? (w[k] / fmaxf(denom, 1e-8f))
                                     : (pres[k] / fmaxf(psum, 1.f));
        g_nsw[b * Kst + k] = nswk;
        g_lognsw[b * Kst + k] = logf(fmaxf(nswk, 1e-8f));
        out_nsw[b * Kst + k] = nswk;
    }
}

// ---------------- fused build-x + weight convert (blockDim 128) ----------------
#define WSPLIT_BLOCKS 16384

__global__ void __launch_bounds__(128) build_split_kernel(
    const float* __restrict__ sr, const void* __restrict__ rm,
    const void* __restrict__ pm, const int* __restrict__ roles,
    const float* __restrict__ remb, float* __restrict__ dout,
    const float* __restrict__ Wq, const float* __restrict__ Wk,
    const float* __restrict__ Wv, const float* __restrict__ Wo,
    const float* __restrict__ Wg2, const float* __restrict__ Wg1,
    __half* __restrict__ oWs1, __half* __restrict__ oWso,
    __half* __restrict__ oWsg2, __half* __restrict__ oWsg1) {
    if (blockIdx.x >= BLn) {
        int idx = (blockIdx.x - BLn) * 128 + threadIdx.x;
        const float* W;
        __half* out;
        int e;
        if (idx < 262144)        { W = Wq;  out = oWs1;                      e = idx; }
        else if (idx < 524288)   { W = Wk;  out = oWs1 + (size_t)512 * 512;  e = idx - 262144; }
        else if (idx < 786432)   { W = Wv;  out = oWs1 + (size_t)1024 * 512; e = idx - 524288; }
        else if (idx < 1048576)  { W = Wo;  out = oWso;                      e = idx - 786432; }
        else if (idx < 1310720)  { W = Wg2; out = oWsg2;                     e = idx - 1048576; }
        else                     { W = Wg1; out = oWsg1;                     e = idx - 1310720; }
        out[e] = __float2half_rn(W[e]);
        return;
    }
    // ---- build-x path: 128 threads x 4 dims ----
    int bl = blockIdx.x;
    int b = bl >> 10;
    int l = bl & 1023;
    int t = threadIdx.x;
    int d0 = t * 4;
    int u8 = g_mask_u8;
    __shared__ int slots[Kst];

    bool vd[Kst];
    float swr[Kst];
    float ssum = 0.f;
#pragma unroll
    for (int k = 0; k < Kst; k++) {
        bool v = mask_at(rm, (b * Kst + k) * Lseq + l, u8) && mask_at(pm, b * Kst + k, u8);
        vd[k] = v;
        swr[k] = v ? g_nsw[b * Kst + k] : 0.f;
        ssum += swr[k];
    }
    if (t == 0) {
        int nv = 0, mb = 0;
#pragma unroll
        for (int k = 0; k < Kst; k++) {
            nv += vd[k] ? 1 : 0;
            mb |= (vd[k] ? 1 : 0) << k;
        }
        g_vbits[bl] = mb;
        int base = nv ? atomicAdd(&g_cnt, nv) : 0;
#pragma unroll
        for (int k = 0; k < Kst; k++) {
            if (vd[k]) {
                slots[k] = base;
                g_rowmap[base] = bl * Kst + k;
                base++;
            } else slots[k] = -1;
        }
    }
    __syncthreads();
    float inv = 1.f / fmaxf(ssum, 1e-8f);

    float4 wm = make_float4(0.f, 0.f, 0.f, 0.f);
    float4 mx = make_float4(-1e9f, -1e9f, -1e9f, -1e9f);
    bool any = false;
#pragma unroll
    for (int k = 0; k < Kst; k++) {
        swr[k] *= inv;
        if (vd[k]) {
            int role = max(roles[b * Kst + k], 0);
            float4 s4 = *(const float4*)(sr + (((size_t)(b * Kst + k)) * Lseq + l) * Ddim + d0);
            float4 r4 = *(const float4*)(remb + (size_t)role * Ddim + d0);
            float4 xv = make_float4(s4.x + r4.x, s4.y + r4.y, s4.z + r4.z, s4.w + r4.w);
            any = true;
            mx.x = fmaxf(mx.x, xv.x); mx.y = fmaxf(mx.y, xv.y);
            mx.z = fmaxf(mx.z, xv.z); mx.w = fmaxf(mx.w, xv.w);
            __half h0, l0, h1, l1, h2, l2, h3, l3;
            split2h(xv.x, h0, l0); split2h(xv.y, h1, l1);
            split2h(xv.z, h2, l2); split2h(xv.w, h3, l3);
            size_t row = (size_t)slots[k] * 1024;
            *(__half2*)(g_Xs + row + d0)           = __halves2half2(h0, h1);
            *(__half2*)(g_Xs + row + d0 + 2)       = __halves2half2(h2, h3);
            *(__half2*)(g_Xs + row + 512 + d0)     = __halves2half2(l0, l1);
            *(__half2*)(g_Xs + row + 512 + d0 + 2) = __halves2half2(l2, l3);
            wm.x += swr[k] * xv.x; wm.y += swr[k] * xv.y;
            wm.z += swr[k] * xv.z; wm.w += swr[k] * xv.w;
        }
    }
    *(float4*)(dout + OUT_WM + (size_t)bl * Ddim + d0) = wm;
    if (!any) mx = make_float4(0.f, 0.f, 0.f, 0.f);
    *(float4*)(dout + OUT_MF + (size_t)bl * Ddim + d0) = mx;
    if (t < Kst) g_swr[bl * Kst + t] = swr[t];
}

// ---------------- HMMA fp16 GEMM, cp.async 3-stage pipeline, 2 CTAs/SM ----------------
// EPI 0: fp32 (ldc). EPI 1: bias+gelu -> hi fp16. EPI 2: bias+sigmoid -> fp32.
// EPI 3 (QKV): cols [0,1024) -> fp32 q,k (ld 1024); cols [1024,1536) -> fp16 v (ld 512).
#define STAGES 3
#define GSM_BYTES (STAGES * 32768)

template <int EPI, bool COMPACT>
__global__ void __launch_bounds__(256, 2) gemm_mma(
    const __half* __restrict__ A, const __half* __restrict__ B,
    const float* __restrict__ bias, float* __restrict__ Cf,
    __half* __restrict__ Cb, int K, int ldb, int ldc) {
    int Mv = 0;
    if (COMPACT) {
        Mv = g_cnt;
        int padded = (Mv + 127) & ~127;
        if ((int)(blockIdx.y * 128) >= padded) return;
    }
    extern __shared__ __align__(1024) char smem[];
    uint32_t sA0 = smem_u32(smem);
    int tid = threadIdx.x;
    int wid = tid >> 5, lane = tid & 31;
    const int wm = wid >> 2, wn = wid & 3;

    const size_t bm = (size_t)blockIdx.y * 128;
    const int bn = blockIdx.x * 128;
    const int seg = tid & 7;
    const int r0 = tid >> 3;

    const __half* Ab = A + (bm + r0) * (size_t)K + seg * 8;
    const __half* Bb = B + (size_t)(bn + r0) * ldb + seg * 8;
    const uint32_t swbase = swz(r0 * 128 + seg * 16);

    auto copy_stage = [&](int c, int buf) {
        int kc = c << 6;
        int bkc = (kc >= ldb) ? kc - ldb : kc;
        uint32_t pa = sA0 + buf * 32768 + swbase;
#pragma unroll
        for (int i = 0; i < 4; i++) {
            cp_async16(pa + i * 32 * 128, Ab + (size_t)(i * 32) * K + kc);
            cp_async16(pa + 16384 + i * 32 * 128, Bb + (size_t)(i * 32) * ldb + bkc);
        }
        asm volatile("cp.async.commit_group;" ::: "memory");
    };

    float acc[4][4][4];
#pragma unroll
    for (int i = 0; i < 4; i++)
#pragma unroll
        for (int j = 0; j < 4; j++)
#pragma unroll
            for (int q = 0; q < 4; q++) acc[i][j][q] = 0.f;

    const uint32_t aRow = wm * 64 + (lane & 15);
    const uint32_t aColB = (lane >> 4) << 4;
    const uint32_t bRow = wn * 32 + (lane & 7) + ((lane >> 4) << 3);
    const uint32_t bColB = ((lane >> 3) & 1) << 4;

    const int NC = K >> 6;
#pragma unroll
    for (int s = 0; s < STAGES - 1; s++)
        if (s < NC) copy_stage(s, s);

    for (int c = 0; c < NC; c++) {
        asm volatile("cp.async.wait_group %0;" :: "n"(STAGES - 2));
        __syncthreads();
        if (c + STAGES - 1 < NC) copy_stage(c + STAGES - 1, (c + STAGES - 1) % STAGES);

        uint32_t Abuf = sA0 + (c % STAGES) * 32768;
        uint32_t Bbuf = Abuf + 16384;
#pragma unroll
        for (int ks = 0; ks < 4; ks++) {
            uint32_t a[4][4], b[4][2];
#pragma unroll
            for (int mt = 0; mt < 4; mt++) {
                uint32_t off = (aRow + mt * 16) * 128 + ks * 32 + aColB;
                ldsm_x4(a[mt][0], a[mt][1], a[mt][2], a[mt][3], Abuf + swz(off));
            }
#pragma unroll
            for (int p = 0; p < 2; p++) {
                uint32_t off = (bRow + p * 16) * 128 + ks * 32 + bColB;
                ldsm_x4(b[2 * p][0], b[2 * p][1], b[2 * p + 1][0], b[2 * p + 1][1],
                        Bbuf + swz(off));
            }
#pragma unroll
            for (int mt = 0; mt < 4; mt++)
#pragma unroll
                for (int nt = 0; nt < 4; nt++)
                    mma16816(acc[mt][nt], a[mt], b[nt]);
        }
    }

    // epilogue
    const int g = lane >> 2, t = lane & 3;
    const bool vcols = (EPI == 3) && (bn >= 1024);   // uniform per CTA
#pragma unroll
    for (int mt = 0; mt < 4; mt++) {
#pragma unroll
        for (int half = 0; half < 2; half++) {
            size_t grow = bm + wm * 64 + mt * 16 + g + half * 8;
            size_t orow = grow;
            if (COMPACT) {
                if ((int)grow >= Mv) continue;
                orow = (size_t)g_rowmap[grow];
            }
#pragma unroll
            for (int nt = 0; nt < 4; nt++) {
                int col = bn + wn * 32 + nt * 8 + t * 2;
                float v0 = acc[mt][nt][half * 2 + 0];
                float v1 = acc[mt][nt][half * 2 + 1];
                if (EPI == 0) {
                    float2 o = make_float2(v0, v1);
                    *(float2*)(Cf + orow * (size_t)ldc + col) = o;
                } else if (EPI == 3) {
                    if (!vcols) {
                        *(float2*)(Cf + orow * 1024 + col) = make_float2(v0, v1);
                    } else {
                        *(__half2*)(Cb + orow * 512 + (col - 1024)) =
                            __halves2half2(__float2half_rn(v0), __float2half_rn(v1));
                    }
                } else if (EPI == 1) {
                    v0 += bias[col];
                    v1 += bias[col + 1];
                    v0 = 0.5f * v0 * (1.f + erff(v0 * 0.70710678118654752f));
                    v1 = 0.5f * v1 * (1.f + erff(v1 * 0.70710678118654752f));
                    *(__half2*)(Cb + orow * 512 + col) =
                        __halves2half2(__float2half_rn(v0), __float2half_rn(v1));
                } else {
                    v0 += bias[col];
                    v1 += bias[col + 1];
                    float2 o;
                    o.x = 1.f / (1.f + __expf(-v0));
                    o.y = 1.f / (1.f + __expf(-v1));
                    *(float2*)(Cf + orow * 512 + col) = o;
                }
            }
        }
    }
}

// ---------------- attention: 4x4 per (b,l,h); pooled hi-only output + attn_mean ----------------
__global__ void __launch_bounds__(256) attn_kernel(float* __restrict__ dout) {
    int bl = blockIdx.x;
    int b = bl >> 10;
    int warp = threadIdx.x >> 5;
    int lane = threadIdx.x & 31;
    __shared__ float amp[8][Kst];

    int mbits = g_vbits[bl];
    float2 q[Kst], kk[Kst], vv[Kst];
    float ln_w[Kst], swr[Kst];
    int col = warp * HDdim + lane * 2;
#pragma unroll
    for (int s = 0; s < Kst; s++) {
        if ((mbits >> s) & 1) {
            size_t rbase = (size_t)(bl * Kst + s) * 1024 + col;
            q[s]  = *(const float2*)(g_QKV + rbase);
            kk[s] = *(const float2*)(g_QKV + rbase + 512);
            vv[s] = __half22float2(*(const __half2*)(g_Vh + (size_t)(bl * Kst + s) * 512 + col));
        } else {
            q[s] = kk[s] = vv[s] = make_float2(0.f, 0.f);
        }
        ln_w[s] = g_lognsw[b * Kst + s];
        swr[s]  = g_swr[bl * Kst + s];
    }

    float dot[Kst][Kst];
#pragma unroll
    for (int i = 0; i < Kst; i++) {
#pragma unroll
        for (int j = 0; j < Kst; j++) {
            float p = q[i].x * kk[j].x + q[i].y * kk[j].y;
#pragma unroll
            for (int o = 16; o; o >>= 1) p += __shfl_xor_sync(0xffffffffu, p, o);
            dot[i][j] = p;
        }
    }

    float a[Kst][Kst];
#pragma unroll
    for (int i = 0; i < Kst; i++) {
        float lm[Kst] = {0.f, 0.f, 0.f, 0.f};
        float m = -3.4e38f;
#pragma unroll
        for (int j = 0; j < Kst; j++) {
            if ((mbits >> j) & 1) {
                lm[j] = dot[i][j] * 0.125f + ln_w[j];
                m = fmaxf(m, lm[j]);
            }
        }
        float ssum = 0.f;
#pragma unroll
        for (int j = 0; j < Kst; j++) {
            float e = ((mbits >> j) & 1) ? __expf(lm[j] - m) : 0.f;
            a[i][j] = e;
            ssum += e;
        }
        float invs = (ssum > 0.f) ? (1.f / ssum) : 0.f;
#pragma unroll
        for (int j = 0; j < Kst; j++) a[i][j] *= invs;
    }

    float px = 0.f, py = 0.f;
#pragma unroll
    for (int i = 0; i < Kst; i++) {
        float ox = 0.f, oy = 0.f;
#pragma unroll
        for (int j = 0; j < Kst; j++) {
            ox += a[i][j] * vv[j].x;
            oy += a[i][j] * vv[j].y;
        }
        px += swr[i] * ox;
        py += swr[i] * oy;
    }
    *(__half2*)(g_AOs + (size_t)bl * 512 + col) =
        __halves2half2(__float2half_rn(px), __float2half_rn(py));

    if (lane == 0) {
#pragma unroll
        for (int j = 0; j < Kst; j++)
            amp[warp][j] = a[0][j] + a[1][j] + a[2][j] + a[3][j];
    }
    __syncthreads();
    if (threadIdx.x < Kst) {
        float t = 0.f;
#pragma unroll
        for (int w = 0; w < 8; w++) t += amp[w][threadIdx.x];
        dout[OUT_AM + (size_t)bl * Kst + threadIdx.x] = t * (1.f / 32.f);
    }
}

// ---------------- block reduction ----------------
__device__ __forceinline__ float block_sum(float v, float* red) {
    int lane = threadIdx.x & 31, w = threadIdx.x >> 5;
#pragma unroll
    for (int o = 16; o; o >>= 1) v += __shfl_xor_sync(0xffffffffu, v, o);
    __syncthreads();
    if (lane == 0) red[w] = v;
    __syncthreads();
    if (threadIdx.x == 0) {
        float t = 0.f;
        int nw = (blockDim.x + 31) >> 5;
        for (int i = 0; i < nw; i++) t += red[i];
        red[8] = t;
    }
    __syncthreads();
    return red[8];
}

// ---------------- layernorm of gate_in (1536) -> hi-only fp16, float4 ----------------
__global__ void __launch_bounds__(256) ln_gatein_kernel(
    const float* __restrict__ dro, const float* __restrict__ g,
    const float* __restrict__ bb) {
    int bl = blockIdx.x;
    __shared__ float4 sbuf[384];
    __shared__ float red[9];
    float s = 0.f;
#pragma unroll 2
    for (int i = threadIdx.x; i < 384; i += 256) {
        float4 v;
        if (i < 128)      v = *(const float4*)(dro + OUT_AP + (size_t)bl * Ddim + i * 4);
        else if (i < 256) v = *(const float4*)(dro + OUT_WM + (size_t)bl * Ddim + (i - 128) * 4);
        else              v = *(const float4*)(dro + OUT_MF + (size_t)bl * Ddim + (i - 256) * 4);
        sbuf[i] = v;
        s += v.x + v.y + v.z + v.w;
    }
    s = block_sum(s, red);
    float mu = s * (1.f / D3);
    float sq = 0.f;
#pragma unroll 2
    for (int i = threadIdx.x; i < 384; i += 256) {
        float4 v = sbuf[i];
        float dx = v.x - mu, dy = v.y - mu, dz = v.z - mu, dw = v.w - mu;
        sq += dx * dx + dy * dy + dz * dz + dw * dw;
    }
    sq = block_sum(sq, red);
    float rs = rsqrtf(sq * (1.f / D3) + 1e-5f);
#pragma unroll 2
    for (int i = threadIdx.x; i < 384; i += 256) {
        int c = i * 4;
        float4 v = sbuf[i];
        float4 g4 = *(const float4*)(g + c);
        float4 b4 = *(const float4*)(bb + c);
        float y0 = (v.x - mu) * rs * g4.x + b4.x;
        float y1 = (v.y - mu) * rs * g4.y + b4.y;
        float y2 = (v.z - mu) * rs * g4.z + b4.z;
        float y3 = (v.w - mu) * rs * g4.w + b4.w;
        size_t row = (size_t)bl * 1536;
        *(__half2*)(g_Gs + row + c)     = __halves2half2(__float2half_rn(y0), __float2half_rn(y1));
        *(__half2*)(g_Gs + row + c + 2) = __halves2half2(__float2half_rn(y2), __float2half_rn(y3));
    }
}

// ---------------- final fuse + layernorm(512), float4, 128 threads ----------------
__global__ void __launch_bounds__(128) ln_final_kernel(
    float* __restrict__ dout, const float* __restrict__ ng,
    const float* __restrict__ nb) {
    int bl = blockIdx.x;
    __shared__ float red[9];
    int d0 = threadIdx.x * 4;
    float4 gate = *(const float4*)(g_GATE + (size_t)bl * Ddim + d0);
    float4 ap = *(const float4*)(dout + OUT_AP + (size_t)bl * Ddim + d0);
    float4 wm = *(const float4*)(dout + OUT_WM + (size_t)bl * Ddim + d0);
    float4 mf = *(const float4*)(dout + OUT_MF + (size_t)bl * Ddim + d0);
    float4 y;
    y.x = gate.x * 0.5f * (ap.x + wm.x) + (1.f - gate.x) * mf.x + wm.x;
    y.y = gate.y * 0.5f * (ap.y + wm.y) + (1.f - gate.y) * mf.y + wm.y;
    y.z = gate.z * 0.5f * (ap.z + wm.z) + (1.f - gate.z) * mf.z + wm.z;
    y.w = gate.w * 0.5f * (ap.w + wm.w) + (1.f - gate.w) * mf.w + wm.w;
    float s = block_sum(y.x + y.y + y.z + y.w, red);
    float mu = s * (1.f / Ddim);
    float dx = y.x - mu, dy = y.y - mu, dz = y.z - mu, dw = y.w - mu;
    float sq = block_sum(dx * dx + dy * dy + dz * dz + dw * dw, red);
    float rs = rsqrtf(sq * (1.f / Ddim) + 1e-5f);
    float4 g4 = *(const float4*)(ng + d0);
    float4 b4 = *(const float4*)(nb + d0);
    float4 o;
    o.x = dx * rs * g4.x + b4.x;
    o.y = dy * rs * g4.y + b4.y;
    o.z = dz * rs * g4.z + b4.z;
    o.w = dw * rs * g4.w + b4.w;
    *(float4*)(dout + OUT_FUSED + (size_t)bl * Ddim + d0) = o;
}

// ---------------- launch ----------------
extern "C" void kernel_launch(void* const* d_in, const int* in_sizes, int n_in,
                              void* d_out, int out_size) {
    const float* sr    = (const float*)d_in[0];
    const void*  rmask = d_in[1];
    const float* sw    = (const float*)d_in[2];
    const int*   roles = (const int*)d_in[3];
    const void*  pmask = d_in[4];
    const float* remb  = (const float*)d_in[5];
    const float* Wq    = (const float*)d_in[6];
    const float* Wk    = (const float*)d_in[7];
    const float* Wv    = (const float*)d_in[8];
    const float* Wo    = (const float*)d_in[9];
    const float* ln1g  = (const float*)d_in[10];
    const float* ln1b  = (const float*)d_in[11];
    const float* Wg1   = (const float*)d_in[12];
    const float* bg1   = (const float*)d_in[13];
    const float* Wg2   = (const float*)d_in[14];
    const float* bg2   = (const float*)d_in[15];
    const float* ng    = (const float*)d_in[16];
    const float* nb    = (const float*)d_in[17];
    float* dout = (float*)d_out;

    __half *pXs, *pVh, *pAOs, *pGs, *pH1s, *pWs1, *pWso, *pWsg1, *pWsg2;
    float *pQKV, *pGATE;
    cudaGetSymbolAddress((void**)&pXs, g_Xs);
    cudaGetSymbolAddress((void**)&pQKV, g_QKV);
    cudaGetSymbolAddress((void**)&pVh, g_Vh);
    cudaGetSymbolAddress((void**)&pAOs, g_AOs);
    cudaGetSymbolAddress((void**)&pGs, g_Gs);
    cudaGetSymbolAddress((void**)&pH1s, g_H1s);
    cudaGetSymbolAddress((void**)&pGATE, g_GATE);
    cudaGetSymbolAddress((void**)&pWs1, g_Ws1);
    cudaGetSymbolAddress((void**)&pWso, g_Wso);
    cudaGetSymbolAddress((void**)&pWsg1, g_Wsg1);
    cudaGetSymbolAddress((void**)&pWsg2, g_Wsg2);

    cudaFuncSetAttribute(gemm_mma<3, true>,  cudaFuncAttributeMaxDynamicSharedMemorySize, GSM_BYTES);
    cudaFuncSetAttribute(gemm_mma<0, false>, cudaFuncAttributeMaxDynamicSharedMemorySize, GSM_BYTES);
    cudaFuncSetAttribute(gemm_mma<1, false>, cudaFuncAttributeMaxDynamicSharedMemorySize, GSM_BYTES);
    cudaFuncSetAttribute(gemm_mma<2, false>, cudaFuncAttributeMaxDynamicSharedMemorySize, GSM_BYTES);

    detnsw_kernel<<<1, 256>>>(rmask, sw, pmask, dout + OUT_NSW);
    build_split_kernel<<<BLn + WSPLIT_BLOCKS, 128>>>(sr, rmask, pmask, roles, remb, dout,
                                                     Wq, Wk, Wv, Wo, Wg2, Wg1,
                                                     pWs1, pWso, pWsg2, pWsg1);

    // fused QKV on compacted rows: [Mv x 1536] = Xs([hi|lo], K'=1024) @ Ws1(hi, ldb=512)^T
    // q,k -> fp32 (ld 1024); v -> fp16 g_Vh (ld 512)
    {
        dim3 grid(1536 / 128, Tn / 128);
        gemm_mma<3, true><<<grid, 256, GSM_BYTES>>>(pXs, pWs1, nullptr, pQKV, pVh, 1024, 512, 1024);
    }

    attn_kernel<<<BLn, 256>>>(dout);

    // attn_pooled = AOs @ Wso^T  [8192 x 512], hi-only (K=512, no wrap)
    {
        dim3 grid(512 / 128, BLn / 128);
        gemm_mma<0, false><<<grid, 256, GSM_BYTES>>>(pAOs, pWso, nullptr, dout + OUT_AP, nullptr, 512, 512, 512);
    }

    ln_gatein_kernel<<<BLn, 256>>>(dout, ln1g, ln1b);

    // h = gelu(Gs @ Wsg1^T + bg1), hi-only (K=1536, no wrap)
    {
        dim3 grid(512 / 128, BLn / 128);
        gemm_mma<1, false><<<grid, 256, GSM_BYTES>>>(pGs, pWsg1, bg1, nullptr, pH1s, 1536, 1536, 0);
    }
    // gate = sigmoid(H1s @ Wsg2^T + bg2), hi-only (K=512, no wrap)
    {
        dim3 grid(512 / 128, BLn / 128);
        gemm_mma<2, false><<<grid, 256, GSM_BYTES>>>(pH1s, pWsg2, bg2, pGATE, nullptr, 512, 512, 0);
    }

    ln_final_kernel<<<BLn, 128>>>(dout, ng, nb);
}

// round 17
// speedup vs baseline: 2.4713x; 1.2429x over previous
#include <cuda_runtime.h>
#include <cuda_fp16.h>
#include <math.h>
#include <stdint.h>

// ---------------- problem constants ----------------
#define Bdim 8
#define Kst 4
#define Lseq 1024
#define Ddim 512
#define Hn 8
#define HDdim 64
#define BLn 8192
#define Tn 32768
#define D3 1536

#define OUT_FUSED 0
#define OUT_AP    4194304
#define OUT_WM    8388608
#define OUT_MF    12582912
#define OUT_AM    16777216
#define OUT_NSW   16809984

// ---------------- device scratch ----------------
// ALL GEMMs hi-only fp16 (1-term). Error ledger (quadrature, measured increments):
// QKV 1-term ~4.6e-4, gate path ~2.1e-4, v-fp16 ~1.6e-4 -> ~5.3e-4 total (vs 1e-3).
__device__ __half g_Xs[(size_t)Tn * 512];      // hi only
__device__ float  g_QKV[(size_t)Tn * 1024];    // q,k fp32
__device__ __half g_Vh[(size_t)Tn * 512];      // v fp16
__device__ __half g_AOs[(size_t)BLn * 512];
__device__ __half g_Gs[(size_t)BLn * 1536];
__device__ __half g_H1s[(size_t)BLn * 512];
__device__ float  g_GATE[(size_t)BLn * Ddim];
__device__ __half g_Ws1[1536 * 512];
__device__ __half g_Wso[512 * 512];
__device__ __half g_Wsg1[512 * 1536];
__device__ __half g_Wsg2[512 * 512];
__device__ float g_swr[BLn * Kst];
__device__ float g_nsw[Bdim * Kst];
__device__ float g_lognsw[Bdim * Kst];
__device__ int   g_vbits[BLn];
__device__ int   g_mask_u8;
__device__ int   g_cnt;
__device__ int   g_rowmap[Tn];

// ---------------- helpers ----------------
__device__ __forceinline__ uint32_t smem_u32(const void* p) {
    uint32_t a;
    asm("{ .reg .u64 t; cvta.to.shared.u64 t, %1; cvt.u32.u64 %0, t; }" : "=r"(a) : "l"(p));
    return a;
}
__device__ __forceinline__ void ldsm_x4(uint32_t& r0, uint32_t& r1, uint32_t& r2,
                                        uint32_t& r3, uint32_t addr) {
    asm volatile("ldmatrix.sync.aligned.m8n8.x4.shared.b16 {%0,%1,%2,%3}, [%4];"
                 : "=r"(r0), "=r"(r1), "=r"(r2), "=r"(r3) : "r"(addr));
}
__device__ __forceinline__ void mma16816(float* c, const uint32_t* a, const uint32_t* b) {
    asm volatile(
        "mma.sync.aligned.m16n8k16.row.col.f32.f16.f16.f32 "
        "{%0,%1,%2,%3}, {%4,%5,%6,%7}, {%8,%9}, {%0,%1,%2,%3};"
        : "+f"(c[0]), "+f"(c[1]), "+f"(c[2]), "+f"(c[3])
        : "r"(a[0]), "r"(a[1]), "r"(a[2]), "r"(a[3]), "r"(b[0]), "r"(b[1]));
}
__device__ __forceinline__ uint32_t swz(uint32_t off) {
    return off ^ ((off >> 3) & 0x70);
}
__device__ __forceinline__ void cp_async16(uint32_t dst, const void* src) {
    asm volatile("cp.async.cg.shared.global [%0], [%1], 16;" :: "r"(dst), "l"(src));
}
__device__ __forceinline__ bool mask_at(const void* p, int idx, int u8) {
    return u8 ? (((const unsigned char*)p)[idx] != 0) : (((const int*)p)[idx] != 0);
}

// ---------------- fused mask-detect + nsw ----------------
__global__ void detnsw_kernel(const void* __restrict__ rm, const float* __restrict__ sw,
                              const void* __restrict__ pm, float* __restrict__ out_nsw) {
    __shared__ int s_u8;
    const int* p = (const int*)rm;
    int bad = 0;
    for (int i = threadIdx.x; i < 8192; i += 256) {
        int v = p[i];
        if (v != 0 && v != 1) bad = 1;
    }
    bad = __syncthreads_or(bad);
    if (threadIdx.x == 0) {
        g_mask_u8 = bad;
        g_cnt = 0;
        s_u8 = bad;
    }
    __syncthreads();
    int b = threadIdx.x;
    if (b >= Bdim) return;
    int u8 = s_u8;
    float w[Kst], pres[Kst];
    float denom = 0.f, psum = 0.f;
#pragma unroll
    for (int k = 0; k < Kst; k++) {
        pres[k] = mask_at(pm, b * Kst + k, u8) ? 1.f : 0.f;
        w[k] = sw[b * Kst + k] * pres[k];
        denom += w[k];
        psum += pres[k];
    }
#pragma unroll
    for (int k = 0; k < Kst; k++) {
        float nswk = (denom > 1e-8f) ? (w[k] / fmaxf(denom, 1e-8f))
                                     : (pres[k] / fmaxf(psum, 1.f));
        g_nsw[b * Kst + k] = nswk;
        g_lognsw[b * Kst + k] = logf(fmaxf(nswk, 1e-8f));
        out_nsw[b * Kst + k] = nswk;
    }
}

// ---------------- fused build-x + weight convert (blockDim 128) ----------------
#define WSPLIT_BLOCKS 16384

__global__ void __launch_bounds__(128) build_split_kernel(
    const float* __restrict__ sr, const void* __restrict__ rm,
    const void* __restrict__ pm, const int* __restrict__ roles,
    const float* __restrict__ remb, float* __restrict__ dout,
    const float* __restrict__ Wq, const float* __restrict__ Wk,
    const float* __restrict__ Wv, const float* __restrict__ Wo,
    const float* __restrict__ Wg2, const float* __restrict__ Wg1,
    __half* __restrict__ oWs1, __half* __restrict__ oWso,
    __half* __restrict__ oWsg2, __half* __restrict__ oWsg1) {
    if (blockIdx.x >= BLn) {
        int idx = (blockIdx.x - BLn) * 128 + threadIdx.x;
        const float* W;
        __half* out;
        int e;
        if (idx < 262144)        { W = Wq;  out = oWs1;                      e = idx; }
        else if (idx < 524288)   { W = Wk;  out = oWs1 + (size_t)512 * 512;  e = idx - 262144; }
        else if (idx < 786432)   { W = Wv;  out = oWs1 + (size_t)1024 * 512; e = idx - 524288; }
        else if (idx < 1048576)  { W = Wo;  out = oWso;                      e = idx - 786432; }
        else if (idx < 1310720)  { W = Wg2; out = oWsg2;                     e = idx - 1048576; }
        else                     { W = Wg1; out = oWsg1;                     e = idx - 1310720; }
        out[e] = __float2half_rn(W[e]);
        return;
    }
    // ---- build-x path: 128 threads x 4 dims ----
    int bl = blockIdx.x;
    int b = bl >> 10;
    int l = bl & 1023;
    int t = threadIdx.x;
    int d0 = t * 4;
    int u8 = g_mask_u8;
    __shared__ int slots[Kst];

    bool vd[Kst];
    float swr[Kst];
    float ssum = 0.f;
#pragma unroll
    for (int k = 0; k < Kst; k++) {
        bool v = mask_at(rm, (b * Kst + k) * Lseq + l, u8) && mask_at(pm, b * Kst + k, u8);
        vd[k] = v;
        swr[k] = v ? g_nsw[b * Kst + k] : 0.f;
        ssum += swr[k];
    }
    if (t == 0) {
        int nv = 0, mb = 0;
#pragma unroll
        for (int k = 0; k < Kst; k++) {
            nv += vd[k] ? 1 : 0;
            mb |= (vd[k] ? 1 : 0) << k;
        }
        g_vbits[bl] = mb;
        int base = nv ? atomicAdd(&g_cnt, nv) : 0;
#pragma unroll
        for (int k = 0; k < Kst; k++) {
            if (vd[k]) {
                slots[k] = base;
                g_rowmap[base] = bl * Kst + k;
                base++;
            } else slots[k] = -1;
        }
    }
    __syncthreads();
    float inv = 1.f / fmaxf(ssum, 1e-8f);

    float4 wm = make_float4(0.f, 0.f, 0.f, 0.f);
    float4 mx = make_float4(-1e9f, -1e9f, -1e9f, -1e9f);
    bool any = false;
#pragma unroll
    for (int k = 0; k < Kst; k++) {
        swr[k] *= inv;
        if (vd[k]) {
            int role = max(roles[b * Kst + k], 0);
            float4 s4 = *(const float4*)(sr + (((size_t)(b * Kst + k)) * Lseq + l) * Ddim + d0);
            float4 r4 = *(const float4*)(remb + (size_t)role * Ddim + d0);
            float4 xv = make_float4(s4.x + r4.x, s4.y + r4.y, s4.z + r4.z, s4.w + r4.w);
            any = true;
            mx.x = fmaxf(mx.x, xv.x); mx.y = fmaxf(mx.y, xv.y);
            mx.z = fmaxf(mx.z, xv.z); mx.w = fmaxf(mx.w, xv.w);
            size_t row = (size_t)slots[k] * 512;
            *(__half2*)(g_Xs + row + d0) =
                __halves2half2(__float2half_rn(xv.x), __float2half_rn(xv.y));
            *(__half2*)(g_Xs + row + d0 + 2) =
                __halves2half2(__float2half_rn(xv.z), __float2half_rn(xv.w));
            wm.x += swr[k] * xv.x; wm.y += swr[k] * xv.y;
            wm.z += swr[k] * xv.z; wm.w += swr[k] * xv.w;
        }
    }
    *(float4*)(dout + OUT_WM + (size_t)bl * Ddim + d0) = wm;
    if (!any) mx = make_float4(0.f, 0.f, 0.f, 0.f);
    *(float4*)(dout + OUT_MF + (size_t)bl * Ddim + d0) = mx;
    if (t < Kst) g_swr[bl * Kst + t] = swr[t];
}

// ---------------- HMMA fp16 GEMM, cp.async 3-stage pipeline, 2 CTAs/SM ----------------
// EPI 0: fp32 (ldc). EPI 1: bias+gelu -> hi fp16. EPI 2: bias+sigmoid -> fp32.
// EPI 3 (QKV): cols [0,1024) -> fp32 q,k (ld 1024); cols [1024,1536) -> fp16 v (ld 512).
#define STAGES 3
#define GSM_BYTES (STAGES * 32768)

template <int EPI, bool COMPACT>
__global__ void __launch_bounds__(256, 2) gemm_mma(
    const __half* __restrict__ A, const __half* __restrict__ B,
    const float* __restrict__ bias, float* __restrict__ Cf,
    __half* __restrict__ Cb, int K, int ldb, int ldc) {
    int Mv = 0;
    if (COMPACT) {
        Mv = g_cnt;
        int padded = (Mv + 127) & ~127;
        if ((int)(blockIdx.y * 128) >= padded) return;
    }
    extern __shared__ __align__(1024) char smem[];
    uint32_t sA0 = smem_u32(smem);
    int tid = threadIdx.x;
    int wid = tid >> 5, lane = tid & 31;
    const int wm = wid >> 2, wn = wid & 3;

    const size_t bm = (size_t)blockIdx.y * 128;
    const int bn = blockIdx.x * 128;
    const int seg = tid & 7;
    const int r0 = tid >> 3;

    const __half* Ab = A + (bm + r0) * (size_t)K + seg * 8;
    const __half* Bb = B + (size_t)(bn + r0) * ldb + seg * 8;
    const uint32_t swbase = swz(r0 * 128 + seg * 16);

    auto copy_stage = [&](int c, int buf) {
        int kc = c << 6;
        int bkc = (kc >= ldb) ? kc - ldb : kc;
        uint32_t pa = sA0 + buf * 32768 + swbase;
#pragma unroll
        for (int i = 0; i < 4; i++) {
            cp_async16(pa + i * 32 * 128, Ab + (size_t)(i * 32) * K + kc);
            cp_async16(pa + 16384 + i * 32 * 128, Bb + (size_t)(i * 32) * ldb + bkc);
        }
        asm volatile("cp.async.commit_group;" ::: "memory");
    };

    float acc[4][4][4];
#pragma unroll
    for (int i = 0; i < 4; i++)
#pragma unroll
        for (int j = 0; j < 4; j++)
#pragma unroll
            for (int q = 0; q < 4; q++) acc[i][j][q] = 0.f;

    const uint32_t aRow = wm * 64 + (lane & 15);
    const uint32_t aColB = (lane >> 4) << 4;
    const uint32_t bRow = wn * 32 + (lane & 7) + ((lane >> 4) << 3);
    const uint32_t bColB = ((lane >> 3) & 1) << 4;

    const int NC = K >> 6;
#pragma unroll
    for (int s = 0; s < STAGES - 1; s++)
        if (s < NC) copy_stage(s, s);

    for (int c = 0; c < NC; c++) {
        asm volatile("cp.async.wait_group %0;" :: "n"(STAGES - 2));
        __syncthreads();
        if (c + STAGES - 1 < NC) copy_stage(c + STAGES - 1, (c + STAGES - 1) % STAGES);

        uint32_t Abuf = sA0 + (c % STAGES) * 32768;
        uint32_t Bbuf = Abuf + 16384;
#pragma unroll
        for (int ks = 0; ks < 4; ks++) {
            uint32_t a[4][4], b[4][2];
#pragma unroll
            for (int mt = 0; mt < 4; mt++) {
                uint32_t off = (aRow + mt * 16) * 128 + ks * 32 + aColB;
                ldsm_x4(a[mt][0], a[mt][1], a[mt][2], a[mt][3], Abuf + swz(off));
            }
#pragma unroll
            for (int p = 0; p < 2; p++) {
                uint32_t off = (bRow + p * 16) * 128 + ks * 32 + bColB;
                ldsm_x4(b[2 * p][0], b[2 * p][1], b[2 * p + 1][0], b[2 * p + 1][1],
                        Bbuf + swz(off));
            }
#pragma unroll
            for (int mt = 0; mt < 4; mt++)
#pragma unroll
                for (int nt = 0; nt < 4; nt++)
                    mma16816(acc[mt][nt], a[mt], b[nt]);
        }
    }

    // epilogue
    const int g = lane >> 2, t = lane & 3;
    const bool vcols = (EPI == 3) && (bn >= 1024);
#pragma unroll
    for (int mt = 0; mt < 4; mt++) {
#pragma unroll
        for (int half = 0; half < 2; half++) {
            size_t grow = bm + wm * 64 + mt * 16 + g + half * 8;
            size_t orow = grow;
            if (COMPACT) {
                if ((int)grow >= Mv) continue;
                orow = (size_t)g_rowmap[grow];
            }
#pragma unroll
            for (int nt = 0; nt < 4; nt++) {
                int col = bn + wn * 32 + nt * 8 + t * 2;
                float v0 = acc[mt][nt][half * 2 + 0];
                float v1 = acc[mt][nt][half * 2 + 1];
                if (EPI == 0) {
                    float2 o = make_float2(v0, v1);
                    *(float2*)(Cf + orow * (size_t)ldc + col) = o;
                } else if (EPI == 3) {
                    if (!vcols) {
                        *(float2*)(Cf + orow * 1024 + col) = make_float2(v0, v1);
                    } else {
                        *(__half2*)(Cb + orow * 512 + (col - 1024)) =
                            __halves2half2(__float2half_rn(v0), __float2half_rn(v1));
                    }
                } else if (EPI == 1) {
                    v0 += bias[col];
                    v1 += bias[col + 1];
                    v0 = 0.5f * v0 * (1.f + erff(v0 * 0.70710678118654752f));
                    v1 = 0.5f * v1 * (1.f + erff(v1 * 0.70710678118654752f));
                    *(__half2*)(Cb + orow * 512 + col) =
                        __halves2half2(__float2half_rn(v0), __float2half_rn(v1));
                } else {
                    v0 += bias[col];
                    v1 += bias[col + 1];
                    float2 o;
                    o.x = 1.f / (1.f + __expf(-v0));
                    o.y = 1.f / (1.f + __expf(-v1));
                    *(float2*)(Cf + orow * 512 + col) = o;
                }
            }
        }
    }
}

// ---------------- attention: 4x4 per (b,l,h); pooled hi-only output + attn_mean ----------------
__global__ void __launch_bounds__(256) attn_kernel(float* __restrict__ dout) {
    int bl = blockIdx.x;
    int b = bl >> 10;
    int warp = threadIdx.x >> 5;
    int lane = threadIdx.x & 31;
    __shared__ float amp[8][Kst];

    int mbits = g_vbits[bl];
    float2 q[Kst], kk[Kst], vv[Kst];
    float ln_w[Kst], swr[Kst];
    int col = warp * HDdim + lane * 2;
#pragma unroll
    for (int s = 0; s < Kst; s++) {
        if ((mbits >> s) & 1) {
            size_t rbase = (size_t)(bl * Kst + s) * 1024 + col;
            q[s]  = *(const float2*)(g_QKV + rbase);
            kk[s] = *(const float2*)(g_QKV + rbase + 512);
            vv[s] = __half22float2(*(const __half2*)(g_Vh + (size_t)(bl * Kst + s) * 512 + col));
        } else {
            q[s] = kk[s] = vv[s] = make_float2(0.f, 0.f);
        }
        ln_w[s] = g_lognsw[b * Kst + s];
        swr[s]  = g_swr[bl * Kst + s];
    }

    float dot[Kst][Kst];
#pragma unroll
    for (int i = 0; i < Kst; i++) {
#pragma unroll
        for (int j = 0; j < Kst; j++) {
            float p = q[i].x * kk[j].x + q[i].y * kk[j].y;
#pragma unroll
            for (int o = 16; o; o >>= 1) p += __shfl_xor_sync(0xffffffffu, p, o);
            dot[i][j] = p;
        }
    }

    float a[Kst][Kst];
#pragma unroll
    for (int i = 0; i < Kst; i++) {
        float lm[Kst] = {0.f, 0.f, 0.f, 0.f};
        float m = -3.4e38f;
#pragma unroll
        for (int j = 0; j < Kst; j++) {
            if ((mbits >> j) & 1) {
                lm[j] = dot[i][j] * 0.125f + ln_w[j];
                m = fmaxf(m, lm[j]);
            }
        }
        float ssum = 0.f;
#pragma unroll
        for (int j = 0; j < Kst; j++) {
            float e = ((mbits >> j) & 1) ? __expf(lm[j] - m) : 0.f;
            a[i][j] = e;
            ssum += e;
        }
        float invs = (ssum > 0.f) ? (1.f / ssum) : 0.f;
#pragma unroll
        for (int j = 0; j < Kst; j++) a[i][j] *= invs;
    }

    float px = 0.f, py = 0.f;
#pragma unroll
    for (int i = 0; i < Kst; i++) {
        float ox = 0.f, oy = 0.f;
#pragma unroll
        for (int j = 0; j < Kst; j++) {
            ox += a[i][j] * vv[j].x;
            oy += a[i][j] * vv[j].y;
        }
        px += swr[i] * ox;
        py += swr[i] * oy;
    }
    *(__half2*)(g_AOs + (size_t)bl * 512 + col) =
        __halves2half2(__float2half_rn(px), __float2half_rn(py));

    if (lane == 0) {
#pragma unroll
        for (int j = 0; j < Kst; j++)
            amp[warp][j] = a[0][j] + a[1][j] + a[2][j] + a[3][j];
    }
    __syncthreads();
    if (threadIdx.x < Kst) {
        float t = 0.f;
#pragma unroll
        for (int w = 0; w < 8; w++) t += amp[w][threadIdx.x];
        dout[OUT_AM + (size_t)bl * Kst + threadIdx.x] = t * (1.f / 32.f);
    }
}

// ---------------- block reduction ----------------
__device__ __forceinline__ float block_sum(float v, float* red) {
    int lane = threadIdx.x & 31, w = threadIdx.x >> 5;
#pragma unroll
    for (int o = 16; o; o >>= 1) v += __shfl_xor_sync(0xffffffffu, v, o);
    __syncthreads();
    if (lane == 0) red[w] = v;
    __syncthreads();
    if (threadIdx.x == 0) {
        float t = 0.f;
        int nw = (blockDim.x + 31) >> 5;
        for (int i = 0; i < nw; i++) t += red[i];
        red[8] = t;
    }
    __syncthreads();
    return red[8];
}

// ---------------- layernorm of gate_in (1536) -> hi-only fp16, float4 ----------------
__global__ void __launch_bounds__(256) ln_gatein_kernel(
    const float* __restrict__ dro, const float* __restrict__ g,
    const float* __restrict__ bb) {
    int bl = blockIdx.x;
    __shared__ float4 sbuf[384];
    __shared__ float red[9];
    float s = 0.f;
#pragma unroll 2
    for (int i = threadIdx.x; i < 384; i += 256) {
        float4 v;
        if (i < 128)      v = *(const float4*)(dro + OUT_AP + (size_t)bl * Ddim + i * 4);
        else if (i < 256) v = *(const float4*)(dro + OUT_WM + (size_t)bl * Ddim + (i - 128) * 4);
        else              v = *(const float4*)(dro + OUT_MF + (size_t)bl * Ddim + (i - 256) * 4);
        sbuf[i] = v;
        s += v.x + v.y + v.z + v.w;
    }
    s = block_sum(s, red);
    float mu = s * (1.f / D3);
    float sq = 0.f;
#pragma unroll 2
    for (int i = threadIdx.x; i < 384; i += 256) {
        float4 v = sbuf[i];
        float dx = v.x - mu, dy = v.y - mu, dz = v.z - mu, dw = v.w - mu;
        sq += dx * dx + dy * dy + dz * dz + dw * dw;
    }
    sq = block_sum(sq, red);
    float rs = rsqrtf(sq * (1.f / D3) + 1e-5f);
#pragma unroll 2
    for (int i = threadIdx.x; i < 384; i += 256) {
        int c = i * 4;
        float4 v = sbuf[i];
        float4 g4 = *(const float4*)(g + c);
        float4 b4 = *(const float4*)(bb + c);
        float y0 = (v.x - mu) * rs * g4.x + b4.x;
        float y1 = (v.y - mu) * rs * g4.y + b4.y;
        float y2 = (v.z - mu) * rs * g4.z + b4.z;
        float y3 = (v.w - mu) * rs * g4.w + b4.w;
        size_t row = (size_t)bl * 1536;
        *(__half2*)(g_Gs + row + c)     = __halves2half2(__float2half_rn(y0), __float2half_rn(y1));
        *(__half2*)(g_Gs + row + c + 2) = __halves2half2(__float2half_rn(y2), __float2half_rn(y3));
    }
}

// ---------------- final fuse + layernorm(512), float4, 128 threads ----------------
__global__ void __launch_bounds__(128) ln_final_kernel(
    float* __restrict__ dout, const float* __restrict__ ng,
    const float* __restrict__ nb) {
    int bl = blockIdx.x;
    __shared__ float red[9];
    int d0 = threadIdx.x * 4;
    float4 gate = *(const float4*)(g_GATE + (size_t)bl * Ddim + d0);
    float4 ap = *(const float4*)(dout + OUT_AP + (size_t)bl * Ddim + d0);
    float4 wm = *(const float4*)(dout + OUT_WM + (size_t)bl * Ddim + d0);
    float4 mf = *(const float4*)(dout + OUT_MF + (size_t)bl * Ddim + d0);
    float4 y;
    y.x = gate.x * 0.5f * (ap.x + wm.x) + (1.f - gate.x) * mf.x + wm.x;
    y.y = gate.y * 0.5f * (ap.y + wm.y) + (1.f - gate.y) * mf.y + wm.y;
    y.z = gate.z * 0.5f * (ap.z + wm.z) + (1.f - gate.z) * mf.z + wm.z;
    y.w = gate.w * 0.5f * (ap.w + wm.w) + (1.f - gate.w) * mf.w + wm.w;
    float s = block_sum(y.x + y.y + y.z + y.w, red);
    float mu = s * (1.f / Ddim);
    float dx = y.x - mu, dy = y.y - mu, dz = y.z - mu, dw = y.w - mu;
    float sq = block_sum(dx * dx + dy * dy + dz * dz + dw * dw, red);
    float rs = rsqrtf(sq * (1.f / Ddim) + 1e-5f);
    float4 g4 = *(const float4*)(ng + d0);
    float4 b4 = *(const float4*)(nb + d0);
    float4 o;
    o.x = dx * rs * g4.x + b4.x;
    o.y = dy * rs * g4.y + b4.y;
    o.z = dz * rs * g4.z + b4.z;
    o.w = dw * rs * g4.w + b4.w;
    *(float4*)(dout + OUT_FUSED + (size_t)bl * Ddim + d0) = o;
}

// ---------------- launch ----------------
extern "C" void kernel_launch(void* const* d_in, const int* in_sizes, int n_in,
                              void* d_out, int out_size) {
    const float* sr    = (const float*)d_in[0];
    const void*  rmask = d_in[1];
    const float* sw    = (const float*)d_in[2];
    const int*   roles = (const int*)d_in[3];
    const void*  pmask = d_in[4];
    const float* remb  = (const float*)d_in[5];
    const float* Wq    = (const float*)d_in[6];
    const float* Wk    = (const float*)d_in[7];
    const float* Wv    = (const float*)d_in[8];
    const float* Wo    = (const float*)d_in[9];
    const float* ln1g  = (const float*)d_in[10];
    const float* ln1b  = (const float*)d_in[11];
    const float* Wg1   = (const float*)d_in[12];
    const float* bg1   = (const float*)d_in[13];
    const float* Wg2   = (const float*)d_in[14];
    const float* bg2   = (const float*)d_in[15];
    const float* ng    = (const float*)d_in[16];
    const float* nb    = (const float*)d_in[17];
    float* dout = (float*)d_out;

    __half *pXs, *pVh, *pAOs, *pGs, *pH1s, *pWs1, *pWso, *pWsg1, *pWsg2;
    float *pQKV, *pGATE;
    cudaGetSymbolAddress((void**)&pXs, g_Xs);
    cudaGetSymbolAddress((void**)&pQKV, g_QKV);
    cudaGetSymbolAddress((void**)&pVh, g_Vh);
    cudaGetSymbolAddress((void**)&pAOs, g_AOs);
    cudaGetSymbolAddress((void**)&pGs, g_Gs);
    cudaGetSymbolAddress((void**)&pH1s, g_H1s);
    cudaGetSymbolAddress((void**)&pGATE, g_GATE);
    cudaGetSymbolAddress((void**)&pWs1, g_Ws1);
    cudaGetSymbolAddress((void**)&pWso, g_Wso);
    cudaGetSymbolAddress((void**)&pWsg1, g_Wsg1);
    cudaGetSymbolAddress((void**)&pWsg2, g_Wsg2);

    cudaFuncSetAttribute(gemm_mma<3, true>,  cudaFuncAttributeMaxDynamicSharedMemorySize, GSM_BYTES);
    cudaFuncSetAttribute(gemm_mma<0, false>, cudaFuncAttributeMaxDynamicSharedMemorySize, GSM_BYTES);
    cudaFuncSetAttribute(gemm_mma<1, false>, cudaFuncAttributeMaxDynamicSharedMemorySize, GSM_BYTES);
    cudaFuncSetAttribute(gemm_mma<2, false>, cudaFuncAttributeMaxDynamicSharedMemorySize, GSM_BYTES);

    detnsw_kernel<<<1, 256>>>(rmask, sw, pmask, dout + OUT_NSW);
    build_split_kernel<<<BLn + WSPLIT_BLOCKS, 128>>>(sr, rmask, pmask, roles, remb, dout,
                                                     Wq, Wk, Wv, Wo, Wg2, Wg1,
                                                     pWs1, pWso, pWsg2, pWsg1);

    // fused QKV on compacted rows: [Mv x 1536] = Xs(hi, K=512) @ Ws1(hi, ldb=512)^T
    // q,k -> fp32 (ld 1024); v -> fp16 g_Vh (ld 512)
    {
        dim3 grid(1536 / 128, Tn / 128);
        gemm_mma<3, true><<<grid, 256, GSM_BYTES>>>(pXs, pWs1, nullptr, pQKV, pVh, 512, 512, 1024);
    }

    attn_kernel<<<BLn, 256>>>(dout);

    // attn_pooled = AOs @ Wso^T  [8192 x 512], hi-only
    {
        dim3 grid(512 / 128, BLn / 128);
        gemm_mma<0, false><<<grid, 256, GSM_BYTES>>>(pAOs, pWso, nullptr, dout + OUT_AP, nullptr, 512, 512, 512);
    }

    ln_gatein_kernel<<<BLn, 256>>>(dout, ln1g, ln1b);

    // h = gelu(Gs @ Wsg1^T + bg1), hi-only
    {
        dim3 grid(512 / 128, BLn / 128);
        gemm_mma<1, false><<<grid, 256, GSM_BYTES>>>(pGs, pWsg1, bg1, nullptr, pH1s, 1536, 1536, 0);
    }
    // gate = sigmoid(H1s @ Wsg2^T + bg2), hi-only
    {
        dim3 grid(512 / 128, BLn / 128);
        gemm_mma<2, false><<<grid, 256, GSM_BYTES>>>(pH1s, pWsg2, bg2, pGATE, nullptr, 512, 512, 0);
    }

    ln_final_kernel<<<BLn, 128>>>(dout, ng, nb);
}